// round 10
// baseline (speedup 1.0000x reference)
#include <cuda_runtime.h>
#include <cuda_bf16.h>
#include <stdint.h>
#include <math.h>

#define EMB   512
#define VOCAB 32000
#define HID   1024
#define STY   512
#define NB    32
#define SEQ   64
#define TSTEPS 63
#define MROWS (TSTEPS*NB)   /* 2016 */
#define MPAD  2048

// ---------------- device scratch (zero-initialized .bss) ----------------
__device__ float g_Gx[(size_t)MPAD*4*HID];
__device__ float g_hbuf[2*NB*HID];
__device__ float g_c [NB*HID];
__device__ float g_bias3[4*HID];
__device__ __nv_bfloat16 g_Xh[MPAD*EMB],     g_Xl[MPAD*EMB];
__device__ __nv_bfloat16 g_Uh[MPAD*4*STY],   g_Ul[MPAD*4*STY];
__device__ __nv_bfloat16 g_Sh[MPAD*STY],     g_Sl[MPAD*STY];
__device__ __nv_bfloat16 g_Hh[MPAD*HID],     g_Hl[MPAD*HID];   // rows>=2016 stay 0
__device__ __nv_bfloat16 g_Bh[(size_t)VOCAB*1024], g_Bl[(size_t)VOCAB*1024];

// ---------------- helpers ----------------
static __device__ __forceinline__ uint32_t smem_u32(const void* p) {
    uint32_t a;
    asm("{ .reg .u64 t; cvta.to.shared.u64 t, %1; cvt.u32.u64 %0, t; }" : "=r"(a) : "l"(p));
    return a;
}
static __device__ __forceinline__ void cvt2(float f, unsigned& h, unsigned& l) {
    __nv_bfloat16 hb = __float2bfloat16_rn(f);
    float rem = f - __bfloat162float(hb);
    __nv_bfloat16 lb = __float2bfloat16_rn(rem);
    h = (unsigned)__bfloat16_as_ushort(hb);
    l = (unsigned)__bfloat16_as_ushort(lb);
}
static __device__ __forceinline__ void ldm4(uint32_t addr, uint32_t* r) {
    asm volatile("ldmatrix.sync.aligned.m8n8.x4.shared.b16 {%0,%1,%2,%3}, [%4];"
        : "=r"(r[0]), "=r"(r[1]), "=r"(r[2]), "=r"(r[3]) : "r"(addr));
}
static __device__ __forceinline__ void mma16816(float* d, const uint32_t* a,
                                                const uint32_t* b) {
    asm volatile("mma.sync.aligned.m16n8k16.row.col.f32.bf16.bf16.f32 "
        "{%0,%1,%2,%3},{%4,%5,%6,%7},{%8,%9},{%0,%1,%2,%3};"
        : "+f"(d[0]), "+f"(d[1]), "+f"(d[2]), "+f"(d[3])
        : "r"(a[0]), "r"(a[1]), "r"(a[2]), "r"(a[3]), "r"(b[0]), "r"(b[1]));
}
static __device__ __forceinline__ void cpa16(uint32_t s, const void* g) {
    asm volatile("cp.async.cg.shared.global [%0], [%1], 16;" :: "r"(s), "l"(g));
}
static __device__ __forceinline__ void cpcommit() {
    asm volatile("cp.async.commit_group;" ::: "memory");
}
template<int n> static __device__ __forceinline__ void cpwait() {
    asm volatile("cp.async.wait_group %0;" :: "n"(n) : "memory");
}

// ---------------- gather ----------------
__global__ void k_gather(const int* __restrict__ idx, const float* __restrict__ embed,
                         __nv_bfloat16* __restrict__ Xh, __nv_bfloat16* __restrict__ Xl)
{
    int t = blockIdx.x, b = blockIdx.y;
    int tok = idx[b*SEQ + t];
    float4 v = ((const float4*)(embed + (size_t)tok*EMB))[threadIdx.x];
    unsigned h0,l0,h1,l1,h2,l2,h3,l3;
    cvt2(v.x,h0,l0); cvt2(v.y,h1,l1); cvt2(v.z,h2,l2); cvt2(v.w,h3,l3);
    uint2 hv; hv.x = h0|(h1<<16); hv.y = h2|(h3<<16);
    uint2 lv; lv.x = l0|(l1<<16); lv.y = l2|(l3<<16);
    size_t o = (size_t)(t*NB + b)*EMB + threadIdx.x*4;
    *(uint2*)(Xh + o) = hv;
    *(uint2*)(Xl + o) = lv;
}

// ---------------- init ----------------
__global__ void k_init(const float* __restrict__ sv, const float* __restrict__ Vb,
                       const float* __restrict__ Wb, float* __restrict__ h0,
                       float* __restrict__ c, float* __restrict__ b3)
{
    int i = blockIdx.x*blockDim.x + threadIdx.x;
    if (i < NB*HID) { h0[i] = sv[i]; c[i] = sv[i]; }
    if (i < 4*HID)  b3[i] = Vb[i] + Wb[i];
}

// ---------------- convert + transpose: fp32 [K][N] -> bf16 hi/lo [N][K] ----------------
__global__ void k_convT(const float* __restrict__ in, __nv_bfloat16* __restrict__ hiT,
                        __nv_bfloat16* __restrict__ loT, int K, int N)
{
    __shared__ float s[32][33];
    const int k0 = blockIdx.y*32, n0 = blockIdx.x*32;
    const int tid = threadIdx.x;
    {
        int r = tid>>3, c4 = (tid&7)*4;
        float4 v = *(const float4*)(in + (size_t)(k0+r)*N + n0 + c4);
        s[r][c4+0]=v.x; s[r][c4+1]=v.y; s[r][c4+2]=v.z; s[r][c4+3]=v.w;
    }
    __syncthreads();
    {
        int n = tid>>3, kq = (tid&7)*4;
        unsigned hh[4], ll[4];
#pragma unroll
        for (int i = 0; i < 4; ++i) cvt2(s[kq+i][n], hh[i], ll[i]);
        uint2 hv; hv.x = hh[0]|(hh[1]<<16); hv.y = hh[2]|(hh[3]<<16);
        uint2 lv; lv.x = ll[0]|(ll[1]<<16); lv.y = ll[2]|(ll[3]<<16);
        size_t o = ((size_t)(n0+n)*K + k0 + kq);
        *(uint2*)(hiT + o) = hv;
        *(uint2*)(loT + o) = lv;
    }
}

// ======== HMMA GEMM: 128x128 block, 8 warps of 32x64, Kc=32, 2-stage ========
// A: bf16 hi/lo [M][K]; B: bf16 hi/lo [N][K]; C fp32 and/or Chi/Clo bf16 outputs.
// smem per stage: Ah 8K | Al 8K | Bh 8K | Bl 8K = 32KB; 2 stages = 64KB static.
#define STG   32768
#define AL_O  8192
#define BH_O  16384
#define BL_O  24576
static __device__ __forceinline__ uint32_t swz64(int row, int k16) {
    return (uint32_t)(row*64 + ((k16 ^ ((row>>1)&3))<<4));
}

__global__ __launch_bounds__(256, 2)
void k_mgemm(const __nv_bfloat16* __restrict__ Ah, const __nv_bfloat16* __restrict__ Al,
             const __nv_bfloat16* __restrict__ Bh, const __nv_bfloat16* __restrict__ Bl,
             const float* __restrict__ bias, float* __restrict__ C,
             __nv_bfloat16* __restrict__ Chi, __nv_bfloat16* __restrict__ Clo,
             int N, int K, int Mstore)
{
    __shared__ __align__(16) unsigned char sm[2*STG];
    const uint32_t sbase = smem_u32(sm);

    const int tid = threadIdx.x, lane = tid & 31, wid = tid >> 5;
    const int brow = blockIdx.x*128, bcol = blockIdx.y*128;

    // cp.async: 2 threads per row, 2 x 16B segs each, for A and B (128 rows each)
    const int lrow = tid >> 1, ak = (tid & 1)*2;
    const __nv_bfloat16* gAh_t = Ah + (size_t)(brow + lrow)*K + ak*8;
    const __nv_bfloat16* gAl_t = Al + (size_t)(brow + lrow)*K + ak*8;
    const __nv_bfloat16* gBh_t = Bh + (size_t)(bcol + lrow)*K + ak*8;
    const __nv_bfloat16* gBl_t = Bl + (size_t)(bcol + lrow)*K + ak*8;
    const uint32_t cs0 = sbase + swz64(lrow, ak);
    const uint32_t cs1 = sbase + swz64(lrow, ak+1);

    // warp tile 32x64 at (m0w, n0w); 4x2 warp grid
    const int m0w = (wid & 3)*32, n0w = (wid >> 2)*64;
    const int arL = lane & 15;
    const int srA = (arL >> 1) & 3;
    const int brL = (lane & 7) + ((lane >> 4) << 3);
    const int srB = ((lane & 7) >> 1) & 3;
    const uint32_t aRowOff = (uint32_t)(m0w + arL)*64;
    const uint32_t bRowOff = (uint32_t)(n0w + brL)*64 + BH_O;

    float acc[2][8][4];
#pragma unroll
    for (int i = 0; i < 2; ++i)
#pragma unroll
        for (int j = 0; j < 8; ++j)
#pragma unroll
            for (int q = 0; q < 4; ++q) acc[i][j][q] = 0.f;

    const int nch = K >> 5;

    // prologue: stage 0 <- chunk 0
    {
        cpa16(cs0, gAh_t);            cpa16(cs1, gAh_t + 8);
        cpa16(cs0 + AL_O, gAl_t);     cpa16(cs1 + AL_O, gAl_t + 8);
        cpa16(cs0 + BH_O, gBh_t);     cpa16(cs1 + BH_O, gBh_t + 8);
        cpa16(cs0 + BL_O, gBl_t);     cpa16(cs1 + BL_O, gBl_t + 8);
        cpcommit();
    }

    for (int c = 0; c < nch; ++c) {
        if (c + 1 < nch) {
            const uint32_t so = (uint32_t)((c+1) & 1)*STG;
            const int kc = (c+1)*32;
            cpa16(cs0 + so, gAh_t + kc);        cpa16(cs1 + so, gAh_t + kc + 8);
            cpa16(cs0 + AL_O + so, gAl_t + kc); cpa16(cs1 + AL_O + so, gAl_t + kc + 8);
            cpa16(cs0 + BH_O + so, gBh_t + kc); cpa16(cs1 + BH_O + so, gBh_t + kc + 8);
            cpa16(cs0 + BL_O + so, gBl_t + kc); cpa16(cs1 + BL_O + so, gBl_t + kc + 8);
            cpcommit();
            cpwait<1>();
        } else {
            cpwait<0>();
        }
        __syncthreads();

        const uint32_t sb_s = sbase + (uint32_t)(c & 1)*STG;
#pragma unroll
        for (int kk = 0; kk < 32; kk += 16) {
            uint32_t Xa[2][4], Xb[4][4], Xc[4][4];
            const int k16a = (kk >> 3) + (lane >> 4);
            const uint32_t abase = sb_s + aRowOff + ((uint32_t)(k16a ^ srA) << 4);
            const int k16b = (kk >> 3) + ((lane >> 3) & 1);
            const uint32_t bbase = sb_s + bRowOff + ((uint32_t)(k16b ^ srB) << 4);

            // term1: ah x bh
#pragma unroll
            for (int mt = 0; mt < 2; ++mt) ldm4(abase + mt*16*64, Xa[mt]);
#pragma unroll
            for (int ng = 0; ng < 4; ++ng) ldm4(bbase + ng*16*64, Xb[ng]);
#pragma unroll
            for (int mt = 0; mt < 2; ++mt)
#pragma unroll
                for (int nt = 0; nt < 8; ++nt)
                    mma16816(acc[mt][nt], Xa[mt], &Xb[nt >> 1][(nt & 1)*2]);

            // term2: ah x bl (bl -> Xc)
#pragma unroll
            for (int ng = 0; ng < 4; ++ng) ldm4(bbase + (BL_O - BH_O) + ng*16*64, Xc[ng]);
#pragma unroll
            for (int mt = 0; mt < 2; ++mt)
#pragma unroll
                for (int nt = 0; nt < 8; ++nt)
                    mma16816(acc[mt][nt], Xa[mt], &Xc[nt >> 1][(nt & 1)*2]);

            // term3: al x bh (al -> Xc[0..1], bl dead)
#pragma unroll
            for (int mt = 0; mt < 2; ++mt) ldm4(abase + AL_O + mt*16*64, Xc[mt]);
#pragma unroll
            for (int mt = 0; mt < 2; ++mt)
#pragma unroll
                for (int nt = 0; nt < 8; ++nt)
                    mma16816(acc[mt][nt], Xc[mt], &Xb[nt >> 1][(nt & 1)*2]);
        }
        __syncthreads();
    }

    // epilogue
    const int g = lane >> 2, tg = lane & 3;
#pragma unroll
    for (int mt = 0; mt < 2; ++mt)
#pragma unroll
        for (int nt = 0; nt < 8; ++nt) {
            const int col = bcol + n0w + nt*8 + tg*2;
            const float b0 = bias[col], b1 = bias[col+1];
#pragma unroll
            for (int half = 0; half < 2; ++half) {
                const int row = brow + m0w + mt*16 + g + half*8;
                if (row < Mstore) {
                    float o0 = acc[mt][nt][half*2+0] + b0;
                    float o1 = acc[mt][nt][half*2+1] + b1;
                    const size_t o = (size_t)row*N + col;
                    if (C) { float2 v; v.x = o0; v.y = o1; *(float2*)(C + o) = v; }
                    if (Chi) {
                        unsigned h0,l0,h1,l1;
                        cvt2(o0,h0,l0); cvt2(o1,h1,l1);
                        *(uint32_t*)(Chi + o) = h0 | (h1<<16);
                        *(uint32_t*)(Clo + o) = l0 | (l1<<16);
                    }
                }
            }
        }
}

// ---------------- fused LSTM step ----------------
__global__ __launch_bounds__(256)
void k_step(const float* __restrict__ Gx, const float* __restrict__ W,
            const float* __restrict__ h_in, float* __restrict__ h_out,
            float* __restrict__ c,
            __nv_bfloat16* __restrict__ Hh, __nv_bfloat16* __restrict__ Hl, int t)
{
    __shared__ float Hs[32][36];
    __shared__ float Ws[32][32];
    __shared__ float Gs[32][32];

    const int tid = threadIdx.x;
    const int n0 = blockIdx.x * 8;
    const int col_local = tid & 31;
    const int gate = col_local >> 3;
    const int n_local = col_local & 7;
    const int gcol = gate*HID + n0 + n_local;
    const int bgrp = tid >> 5;

    float acc0 = Gx[(size_t)(t*NB + bgrp*4 + 0)*(4*HID) + gcol];
    float acc1 = Gx[(size_t)(t*NB + bgrp*4 + 1)*(4*HID) + gcol];
    float acc2 = Gx[(size_t)(t*NB + bgrp*4 + 2)*(4*HID) + gcol];
    float acc3 = Gx[(size_t)(t*NB + bgrp*4 + 3)*(4*HID) + gcol];

    const int hr = tid >> 3;
    const int hc = (tid & 7) * 4;
    const int k4 = (tid >> 5) * 4;

    for (int kb = 0; kb < HID; kb += 32) {
        float4 hv = *(const float4*)(h_in + (size_t)hr*HID + kb + hc);
        Hs[hr][hc+0] = hv.x; Hs[hr][hc+1] = hv.y;
        Hs[hr][hc+2] = hv.z; Hs[hr][hc+3] = hv.w;
#pragma unroll
        for (int kk = 0; kk < 4; kk++)
            Ws[k4+kk][col_local] = W[(size_t)(kb + k4 + kk)*(4*HID) + gcol];
        __syncthreads();
#pragma unroll
        for (int k = 0; k < 32; k++) {
            float w = Ws[k][col_local];
            acc0 += Hs[bgrp*4+0][k] * w;
            acc1 += Hs[bgrp*4+1][k] * w;
            acc2 += Hs[bgrp*4+2][k] * w;
            acc3 += Hs[bgrp*4+3][k] * w;
        }
        __syncthreads();
    }

    Gs[bgrp*4+0][col_local] = acc0;
    Gs[bgrp*4+1][col_local] = acc1;
    Gs[bgrp*4+2][col_local] = acc2;
    Gs[bgrp*4+3][col_local] = acc3;
    __syncthreads();

    const int b = tid >> 3;
    const int nn = tid & 7;
    float gi = Gs[b][0*8 + nn];
    float gf = Gs[b][1*8 + nn];
    float go = Gs[b][2*8 + nn];
    float gc = Gs[b][3*8 + nn];
    int n_glob = n0 + nn;
    float cv = c[(size_t)b*HID + n_glob];
    float si = 1.f / (1.f + expf(-gi));
    float sf = 1.f / (1.f + expf(-gf));
    float so = 1.f / (1.f + expf(-go));
    float c_new = sf * cv + si * tanhf(gc);
    float h_new = so * c_new;
    c[(size_t)b*HID + n_glob] = c_new;
    h_out[(size_t)b*HID + n_glob] = h_new;
    unsigned hh, ll;
    cvt2(h_new, hh, ll);
    size_t ho = (size_t)(b*TSTEPS + t)*HID + n_glob;
    ((unsigned short*)Hh)[ho] = (unsigned short)hh;
    ((unsigned short*)Hl)[ho] = (unsigned short)ll;
}

// ---------------- launch ----------------
extern "C" void kernel_launch(void* const* d_in, const int* in_sizes, int n_in,
                              void* d_out, int out_size)
{
    const int*   rnn   = (const int*)  d_in[0];
    const float* sv    = (const float*)d_in[1];
    const float* embed = (const float*)d_in[2];
    const float* U_w   = (const float*)d_in[3];
    const float* U_b   = (const float*)d_in[4];
    const float* S1_w  = (const float*)d_in[5];
    const float* S1_b  = (const float*)d_in[6];
    const float* V_w   = (const float*)d_in[7];
    const float* W_w   = (const float*)d_in[9];
    const float* P_w   = (const float*)d_in[11];
    const float* P_b   = (const float*)d_in[12];
    float* out = (float*)d_out;

    float *Gx,*hb,*c,*b3;
    __nv_bfloat16 *Xh,*Xl,*Uh,*Ul,*Sh,*Sl,*Hh,*Hl,*Bh,*Bl;
    cudaGetSymbolAddress((void**)&Gx, g_Gx);
    cudaGetSymbolAddress((void**)&hb, g_hbuf);
    cudaGetSymbolAddress((void**)&c,  g_c);
    cudaGetSymbolAddress((void**)&b3, g_bias3);
    cudaGetSymbolAddress((void**)&Xh, g_Xh); cudaGetSymbolAddress((void**)&Xl, g_Xl);
    cudaGetSymbolAddress((void**)&Uh, g_Uh); cudaGetSymbolAddress((void**)&Ul, g_Ul);
    cudaGetSymbolAddress((void**)&Sh, g_Sh); cudaGetSymbolAddress((void**)&Sl, g_Sl);
    cudaGetSymbolAddress((void**)&Hh, g_Hh); cudaGetSymbolAddress((void**)&Hl, g_Hl);
    cudaGetSymbolAddress((void**)&Bh, g_Bh); cudaGetSymbolAddress((void**)&Bl, g_Bl);
    float* h0 = hb;
    float* h1 = hb + NB*HID;

    k_gather<<<dim3(TSTEPS, NB), 128>>>(rnn, embed, Xh, Xl);
    k_init<<<(NB*HID + 255)/256, 256>>>(sv, (const float*)d_in[8],
                                        (const float*)d_in[10], h0, c, b3);

    // GEMM1: U = X @ U_w + U_b -> bf16 hi/lo only
    k_convT<<<dim3((4*STY)/32, EMB/32), 256>>>(U_w, Bh, Bl, EMB, 4*STY);
    k_mgemm<<<dim3(MPAD/128, (4*STY)/128), 256>>>(Xh, Xl, Bh, Bl, U_b,
                                                  nullptr, Uh, Ul, 4*STY, EMB, MPAD);
    // GEMM2: S = U @ S1_w + S1_b -> bf16 hi/lo only
    k_convT<<<dim3(STY/32, (4*STY)/32), 256>>>(S1_w, Bh, Bl, 4*STY, STY);
    k_mgemm<<<dim3(MPAD/128, STY/128), 256>>>(Uh, Ul, Bh, Bl, S1_b,
                                              nullptr, Sh, Sl, STY, 4*STY, MPAD);
    // GEMM3: Gx = S @ V_w + (V_b+W_b) -> fp32 only
    k_convT<<<dim3((4*HID)/32, STY/32), 256>>>(V_w, Bh, Bl, STY, 4*HID);
    k_mgemm<<<dim3(MPAD/128, (4*HID)/128), 256>>>(Sh, Sl, Bh, Bl, b3,
                                                  Gx, nullptr, nullptr, 4*HID, STY, MPAD);

    // recurrence: 63 sequential fused steps, h logged as bf16 hi/lo
    for (int t = 0; t < TSTEPS; t++) {
        float* hin  = (t & 1) ? h1 : h0;
        float* hout = (t & 1) ? h0 : h1;
        k_step<<<HID/8, 256>>>(Gx, W_w, hin, hout, c, Hh, Hl, t);
    }

    // GEMM4: out = H @ P_w + P_b -> fp32 d_out
    k_convT<<<dim3(VOCAB/32, HID/32), 256>>>(P_w, Bh, Bl, HID, VOCAB);
    k_mgemm<<<dim3(MPAD/128, VOCAB/128), 256>>>(Hh, Hl, Bh, Bl, P_b,
                                                out, nullptr, nullptr, VOCAB, HID, MROWS);
}

// round 11
// speedup vs baseline: 1.6988x; 1.6988x over previous
#include <cuda_runtime.h>
#include <cuda_bf16.h>
#include <stdint.h>
#include <math.h>

#define EMB   512
#define VOCAB 32000
#define HID   1024
#define STY   512
#define NB    32
#define SEQ   64
#define TSTEPS 63
#define MROWS (TSTEPS*NB)   /* 2016 */
#define MPAD  2048

// ---------------- device scratch (zero-initialized .bss) ----------------
__device__ float g_Gx[(size_t)MPAD*4*HID];
__device__ float g_c [NB*HID];
__device__ float g_bias3[4*HID];
__device__ __nv_bfloat16 g_Xh[MPAD*EMB],     g_Xl[MPAD*EMB];
__device__ __nv_bfloat16 g_Uh[MPAD*4*STY],   g_Ul[MPAD*4*STY];
__device__ __nv_bfloat16 g_Sh[MPAD*STY],     g_Sl[MPAD*STY];
__device__ __nv_bfloat16 g_Hh[MPAD*HID],     g_Hl[MPAD*HID];   // rows>=2016 stay 0
__device__ __nv_bfloat16 g_Bh[(size_t)VOCAB*1024], g_Bl[(size_t)VOCAB*1024];
__device__ __nv_bfloat16 g_Wh[(size_t)4*HID*HID], g_Wl[(size_t)4*HID*HID]; // W^T split
__device__ __nv_bfloat16 g_hsh[2*NB*HID], g_hsl[2*NB*HID];                 // h ping-pong

// ---------------- helpers ----------------
static __device__ __forceinline__ uint32_t smem_u32(const void* p) {
    uint32_t a;
    asm("{ .reg .u64 t; cvta.to.shared.u64 t, %1; cvt.u32.u64 %0, t; }" : "=r"(a) : "l"(p));
    return a;
}
static __device__ __forceinline__ void cvt2(float f, unsigned& h, unsigned& l) {
    __nv_bfloat16 hb = __float2bfloat16_rn(f);
    float rem = f - __bfloat162float(hb);
    __nv_bfloat16 lb = __float2bfloat16_rn(rem);
    h = (unsigned)__bfloat16_as_ushort(hb);
    l = (unsigned)__bfloat16_as_ushort(lb);
}
static __device__ __forceinline__ void ldm4(uint32_t addr, uint32_t* r) {
    asm volatile("ldmatrix.sync.aligned.m8n8.x4.shared.b16 {%0,%1,%2,%3}, [%4];"
        : "=r"(r[0]), "=r"(r[1]), "=r"(r[2]), "=r"(r[3]) : "r"(addr));
}
static __device__ __forceinline__ void mma16816(float* d, const uint32_t* a,
                                                const uint32_t* b) {
    asm volatile("mma.sync.aligned.m16n8k16.row.col.f32.bf16.bf16.f32 "
        "{%0,%1,%2,%3},{%4,%5,%6,%7},{%8,%9},{%0,%1,%2,%3};"
        : "+f"(d[0]), "+f"(d[1]), "+f"(d[2]), "+f"(d[3])
        : "r"(a[0]), "r"(a[1]), "r"(a[2]), "r"(a[3]), "r"(b[0]), "r"(b[1]));
}
static __device__ __forceinline__ void cpa16(uint32_t s, const void* g) {
    asm volatile("cp.async.cg.shared.global [%0], [%1], 16;" :: "r"(s), "l"(g));
}
static __device__ __forceinline__ void cpcommit() {
    asm volatile("cp.async.commit_group;" ::: "memory");
}
template<int n> static __device__ __forceinline__ void cpwait() {
    asm volatile("cp.async.wait_group %0;" :: "n"(n) : "memory");
}

// ---------------- gather ----------------
__global__ void k_gather(const int* __restrict__ idx, const float* __restrict__ embed,
                         __nv_bfloat16* __restrict__ Xh, __nv_bfloat16* __restrict__ Xl)
{
    int t = blockIdx.x, b = blockIdx.y;
    int tok = idx[b*SEQ + t];
    float4 v = ((const float4*)(embed + (size_t)tok*EMB))[threadIdx.x];
    unsigned h0,l0,h1,l1,h2,l2,h3,l3;
    cvt2(v.x,h0,l0); cvt2(v.y,h1,l1); cvt2(v.z,h2,l2); cvt2(v.w,h3,l3);
    uint2 hv; hv.x = h0|(h1<<16); hv.y = h2|(h3<<16);
    uint2 lv; lv.x = l0|(l1<<16); lv.y = l2|(l3<<16);
    size_t o = (size_t)(t*NB + b)*EMB + threadIdx.x*4;
    *(uint2*)(Xh + o) = hv;
    *(uint2*)(Xl + o) = lv;
}

// ---------------- init: c, h0 split, combined bias ----------------
__global__ void k_init(const float* __restrict__ sv, const float* __restrict__ Vb,
                       const float* __restrict__ Wb, float* __restrict__ c,
                       __nv_bfloat16* __restrict__ hsh, __nv_bfloat16* __restrict__ hsl,
                       float* __restrict__ b3)
{
    int i = blockIdx.x*blockDim.x + threadIdx.x;
    if (i < NB*HID) {
        float v = sv[i];
        c[i] = v;
        unsigned h, l; cvt2(v, h, l);
        ((unsigned short*)hsh)[i] = (unsigned short)h;
        ((unsigned short*)hsl)[i] = (unsigned short)l;
    }
    if (i < 4*HID)  b3[i] = Vb[i] + Wb[i];
}

// ---------------- convert + transpose: fp32 [K][N] -> bf16 hi/lo [N][K] ----------------
__global__ void k_convT(const float* __restrict__ in, __nv_bfloat16* __restrict__ hiT,
                        __nv_bfloat16* __restrict__ loT, int K, int N)
{
    __shared__ float s[32][33];
    const int k0 = blockIdx.y*32, n0 = blockIdx.x*32;
    const int tid = threadIdx.x;
    {
        int r = tid>>3, c4 = (tid&7)*4;
        float4 v = *(const float4*)(in + (size_t)(k0+r)*N + n0 + c4);
        s[r][c4+0]=v.x; s[r][c4+1]=v.y; s[r][c4+2]=v.z; s[r][c4+3]=v.w;
    }
    __syncthreads();
    {
        int n = tid>>3, kq = (tid&7)*4;
        unsigned hh[4], ll[4];
#pragma unroll
        for (int i = 0; i < 4; ++i) cvt2(s[kq+i][n], hh[i], ll[i]);
        uint2 hv; hv.x = hh[0]|(hh[1]<<16); hv.y = hh[2]|(hh[3]<<16);
        uint2 lv; lv.x = ll[0]|(ll[1]<<16); lv.y = ll[2]|(ll[3]<<16);
        size_t o = ((size_t)(n0+n)*K + k0 + kq);
        *(uint2*)(hiT + o) = hv;
        *(uint2*)(loT + o) = lv;
    }
}

// ======== HMMA GEMM: 128x128 block, 8 warps of 32x64, Kc=32, 2-stage ========
#define STG   32768
#define AL_O  8192
#define BH_O  16384
#define BL_O  24576
static __device__ __forceinline__ uint32_t swz64(int row, int k16) {
    return (uint32_t)(row*64 + ((k16 ^ ((row>>1)&3))<<4));
}

__global__ __launch_bounds__(256, 2)
void k_mgemm(const __nv_bfloat16* __restrict__ Ah, const __nv_bfloat16* __restrict__ Al,
             const __nv_bfloat16* __restrict__ Bh, const __nv_bfloat16* __restrict__ Bl,
             const float* __restrict__ bias, float* __restrict__ C,
             __nv_bfloat16* __restrict__ Chi, __nv_bfloat16* __restrict__ Clo,
             int N, int K, int Mstore)
{
    __shared__ __align__(16) unsigned char sm[2*STG];
    const uint32_t sbase = smem_u32(sm);

    const int tid = threadIdx.x, lane = tid & 31, wid = tid >> 5;
    const int brow = blockIdx.x*128, bcol = blockIdx.y*128;

    const int lrow = tid >> 1, ak = (tid & 1)*2;
    const __nv_bfloat16* gAh_t = Ah + (size_t)(brow + lrow)*K + ak*8;
    const __nv_bfloat16* gAl_t = Al + (size_t)(brow + lrow)*K + ak*8;
    const __nv_bfloat16* gBh_t = Bh + (size_t)(bcol + lrow)*K + ak*8;
    const __nv_bfloat16* gBl_t = Bl + (size_t)(bcol + lrow)*K + ak*8;
    const uint32_t cs0 = sbase + swz64(lrow, ak);
    const uint32_t cs1 = sbase + swz64(lrow, ak+1);

    const int m0w = (wid & 3)*32, n0w = (wid >> 2)*64;
    const int arL = lane & 15;
    const int srA = (arL >> 1) & 3;
    const int brL = (lane & 7) + ((lane >> 4) << 3);
    const int srB = ((lane & 7) >> 1) & 3;
    const uint32_t aRowOff = (uint32_t)(m0w + arL)*64;
    const uint32_t bRowOff = (uint32_t)(n0w + brL)*64 + BH_O;

    float acc[2][8][4];
#pragma unroll
    for (int i = 0; i < 2; ++i)
#pragma unroll
        for (int j = 0; j < 8; ++j)
#pragma unroll
            for (int q = 0; q < 4; ++q) acc[i][j][q] = 0.f;

    const int nch = K >> 5;

    {
        cpa16(cs0, gAh_t);            cpa16(cs1, gAh_t + 8);
        cpa16(cs0 + AL_O, gAl_t);     cpa16(cs1 + AL_O, gAl_t + 8);
        cpa16(cs0 + BH_O, gBh_t);     cpa16(cs1 + BH_O, gBh_t + 8);
        cpa16(cs0 + BL_O, gBl_t);     cpa16(cs1 + BL_O, gBl_t + 8);
        cpcommit();
    }

    for (int c = 0; c < nch; ++c) {
        if (c + 1 < nch) {
            const uint32_t so = (uint32_t)((c+1) & 1)*STG;
            const int kc = (c+1)*32;
            cpa16(cs0 + so, gAh_t + kc);        cpa16(cs1 + so, gAh_t + kc + 8);
            cpa16(cs0 + AL_O + so, gAl_t + kc); cpa16(cs1 + AL_O + so, gAl_t + kc + 8);
            cpa16(cs0 + BH_O + so, gBh_t + kc); cpa16(cs1 + BH_O + so, gBh_t + kc + 8);
            cpa16(cs0 + BL_O + so, gBl_t + kc); cpa16(cs1 + BL_O + so, gBl_t + kc + 8);
            cpcommit();
            cpwait<1>();
        } else {
            cpwait<0>();
        }
        __syncthreads();

        const uint32_t sb_s = sbase + (uint32_t)(c & 1)*STG;
#pragma unroll
        for (int kk = 0; kk < 32; kk += 16) {
            uint32_t Xa[2][4], Xb[4][4], Xc[4][4];
            const int k16a = (kk >> 3) + (lane >> 4);
            const uint32_t abase = sb_s + aRowOff + ((uint32_t)(k16a ^ srA) << 4);
            const int k16b = (kk >> 3) + ((lane >> 3) & 1);
            const uint32_t bbase = sb_s + bRowOff + ((uint32_t)(k16b ^ srB) << 4);

#pragma unroll
            for (int mt = 0; mt < 2; ++mt) ldm4(abase + mt*16*64, Xa[mt]);
#pragma unroll
            for (int ng = 0; ng < 4; ++ng) ldm4(bbase + ng*16*64, Xb[ng]);
#pragma unroll
            for (int mt = 0; mt < 2; ++mt)
#pragma unroll
                for (int nt = 0; nt < 8; ++nt)
                    mma16816(acc[mt][nt], Xa[mt], &Xb[nt >> 1][(nt & 1)*2]);

#pragma unroll
            for (int ng = 0; ng < 4; ++ng) ldm4(bbase + (BL_O - BH_O) + ng*16*64, Xc[ng]);
#pragma unroll
            for (int mt = 0; mt < 2; ++mt)
#pragma unroll
                for (int nt = 0; nt < 8; ++nt)
                    mma16816(acc[mt][nt], Xa[mt], &Xc[nt >> 1][(nt & 1)*2]);

#pragma unroll
            for (int mt = 0; mt < 2; ++mt) ldm4(abase + AL_O + mt*16*64, Xc[mt]);
#pragma unroll
            for (int mt = 0; mt < 2; ++mt)
#pragma unroll
                for (int nt = 0; nt < 8; ++nt)
                    mma16816(acc[mt][nt], Xc[mt], &Xb[nt >> 1][(nt & 1)*2]);
        }
        __syncthreads();
    }

    const int g = lane >> 2, tg = lane & 3;
#pragma unroll
    for (int mt = 0; mt < 2; ++mt)
#pragma unroll
        for (int nt = 0; nt < 8; ++nt) {
            const int col = bcol + n0w + nt*8 + tg*2;
            const float b0 = bias[col], b1 = bias[col+1];
#pragma unroll
            for (int half = 0; half < 2; ++half) {
                const int row = brow + m0w + mt*16 + g + half*8;
                if (row < Mstore) {
                    float o0 = acc[mt][nt][half*2+0] + b0;
                    float o1 = acc[mt][nt][half*2+1] + b1;
                    const size_t o = (size_t)row*N + col;
                    if (C) { float2 v; v.x = o0; v.y = o1; *(float2*)(C + o) = v; }
                    if (Chi) {
                        unsigned h0,l0,h1,l1;
                        cvt2(o0,h0,l0); cvt2(o1,h1,l1);
                        *(uint32_t*)(Chi + o) = h0 | (h1<<16);
                        *(uint32_t*)(Clo + o) = l0 | (l1<<16);
                    }
                }
            }
        }
}

// ======== HMMA LSTM step: g = Gx + h@W, gates, c/h update ========
// Grid 128 CTAs x 128 thr. CTA owns 8 n-values x 4 gates (warp = gate).
// A = h hi/lo [32][1024] (global, bf16); B = W^T hi/lo rows {g*1024+n}.
// smem: 2 stages x (hh 4K | hl 4K | wh 4K | wl 4K) + 4K gate buffer.
static __device__ __forceinline__ uint32_t soff(int row, int seg) {
    return (uint32_t)(row*128 + ((seg ^ (row & 7)) << 4));
}

__global__ __launch_bounds__(128)
void k_stepT(const float* __restrict__ Gx,
             const __nv_bfloat16* __restrict__ Wh, const __nv_bfloat16* __restrict__ Wl,
             const __nv_bfloat16* __restrict__ hih, const __nv_bfloat16* __restrict__ hil,
             __nv_bfloat16* __restrict__ hoh, __nv_bfloat16* __restrict__ hol,
             float* __restrict__ c,
             __nv_bfloat16* __restrict__ Hh, __nv_bfloat16* __restrict__ Hl, int ts)
{
    __shared__ __align__(16) unsigned char sm[2*16384 + 4096];
    float* gsm = (float*)(sm + 2*16384);
    const uint32_t sbase = smem_u32(sm);
    const int tid = threadIdx.x, lane = tid & 31, w = tid >> 5;
    const int n0 = blockIdx.x * 8;

    // cp.async assignment: thread -> row (0..31), seg pair
    const int lrow = tid >> 2, sp = (tid & 3)*2;
    const uint32_t so0 = soff(lrow, sp);
    const uint32_t so1 = soff(lrow, sp+1);
    const int grow = (lrow >> 3)*HID + n0 + (lrow & 7);   // W^T row for this thread
    const __nv_bfloat16* gh_h = hih + lrow*HID + sp*8;
    const __nv_bfloat16* gh_l = hil + lrow*HID + sp*8;
    const __nv_bfloat16* gw_h = Wh + (size_t)grow*HID + sp*8;
    const __nv_bfloat16* gw_l = Wl + (size_t)grow*HID + sp*8;

    float acc[2][4];
#pragma unroll
    for (int i = 0; i < 2; ++i)
#pragma unroll
        for (int q = 0; q < 4; ++q) acc[i][q] = 0.f;

    // prologue: chunk 0
    {
        cpa16(sbase         + so0, gh_h); cpa16(sbase         + so1, gh_h + 8);
        cpa16(sbase + 4096  + so0, gh_l); cpa16(sbase + 4096  + so1, gh_l + 8);
        cpa16(sbase + 8192  + so0, gw_h); cpa16(sbase + 8192  + so1, gw_h + 8);
        cpa16(sbase + 12288 + so0, gw_l); cpa16(sbase + 12288 + so1, gw_l + 8);
        cpcommit();
    }

    // ldsm addressing
    const int arow0 = (lane & 15), arow1 = 16 + (lane & 15);
    const int rw = w*8 + (lane & 7), si = lane >> 3;

    for (int cc = 0; cc < 16; ++cc) {
        if (cc + 1 < 16) {
            const uint32_t so = (uint32_t)((cc+1) & 1)*16384;
            const int kc = (cc+1)*64;
            cpa16(sbase + so         + so0, gh_h + kc); cpa16(sbase + so         + so1, gh_h + kc + 8);
            cpa16(sbase + so + 4096  + so0, gh_l + kc); cpa16(sbase + so + 4096  + so1, gh_l + kc + 8);
            cpa16(sbase + so + 8192  + so0, gw_h + kc); cpa16(sbase + so + 8192  + so1, gw_h + kc + 8);
            cpa16(sbase + so + 12288 + so0, gw_l + kc); cpa16(sbase + so + 12288 + so1, gw_l + kc + 8);
            cpcommit();
            cpwait<1>();
        } else {
            cpwait<0>();
        }
        __syncthreads();

        const uint32_t sb = sbase + (uint32_t)(cc & 1)*16384;
        uint32_t ah[4][2][4], al[4][2][4], bh[2][4], bl[2][4];
#pragma unroll
        for (int kb = 0; kb < 2; ++kb) {
            ldm4(sb + 8192  + soff(rw, kb*4 + si), bh[kb]);
            ldm4(sb + 12288 + soff(rw, kb*4 + si), bl[kb]);
        }
#pragma unroll
        for (int q = 0; q < 4; ++q) {
            const int seg = q*2 + (lane >> 4);
            ldm4(sb        + soff(arow0, seg), ah[q][0]);
            ldm4(sb        + soff(arow1, seg), ah[q][1]);
            ldm4(sb + 4096 + soff(arow0, seg), al[q][0]);
            ldm4(sb + 4096 + soff(arow1, seg), al[q][1]);
        }
        // term1: ah x bh
#pragma unroll
        for (int q = 0; q < 4; ++q)
#pragma unroll
            for (int mt = 0; mt < 2; ++mt)
                mma16816(acc[mt], ah[q][mt], &bh[q >> 1][(q & 1)*2]);
        // term2: ah x bl
#pragma unroll
        for (int q = 0; q < 4; ++q)
#pragma unroll
            for (int mt = 0; mt < 2; ++mt)
                mma16816(acc[mt], ah[q][mt], &bl[q >> 1][(q & 1)*2]);
        // term3: al x bh
#pragma unroll
        for (int q = 0; q < 4; ++q)
#pragma unroll
            for (int mt = 0; mt < 2; ++mt)
                mma16816(acc[mt], al[q][mt], &bh[q >> 1][(q & 1)*2]);
        __syncthreads();
    }

    // store gate results to gsm[gate][b][nl]
    {
        const int r = lane >> 2, nl0 = (lane & 3)*2;
#pragma unroll
        for (int mt = 0; mt < 2; ++mt) {
            const int b0 = mt*16 + r, b1 = b0 + 8;
            gsm[(w*32 + b0)*8 + nl0]     = acc[mt][0];
            gsm[(w*32 + b0)*8 + nl0 + 1] = acc[mt][1];
            gsm[(w*32 + b1)*8 + nl0]     = acc[mt][2];
            gsm[(w*32 + b1)*8 + nl0 + 1] = acc[mt][3];
        }
    }
    __syncthreads();

    // gate nonlinearity + c/h update (2 elements per thread)
#pragma unroll
    for (int rep = 0; rep < 2; ++rep) {
        const int idx = tid + rep*128;
        const int b = idx >> 3, nl = idx & 7;
        const int n = n0 + nl;
        const size_t gxrow = (size_t)(ts*NB + b)*(4*HID);
        float gi = gsm[(0*32 + b)*8 + nl] + Gx[gxrow + 0*HID + n];
        float gf = gsm[(1*32 + b)*8 + nl] + Gx[gxrow + 1*HID + n];
        float go = gsm[(2*32 + b)*8 + nl] + Gx[gxrow + 2*HID + n];
        float gc = gsm[(3*32 + b)*8 + nl] + Gx[gxrow + 3*HID + n];
        float cv = c[b*HID + n];
        float si_ = 1.f / (1.f + expf(-gi));
        float sf  = 1.f / (1.f + expf(-gf));
        float so_ = 1.f / (1.f + expf(-go));
        float c_new = sf * cv + si_ * tanhf(gc);
        float h_new = so_ * c_new;
        c[b*HID + n] = c_new;
        unsigned hh, ll;
        cvt2(h_new, hh, ll);
        ((unsigned short*)hoh)[b*HID + n] = (unsigned short)hh;
        ((unsigned short*)hol)[b*HID + n] = (unsigned short)ll;
        const size_t ho = (size_t)(b*TSTEPS + ts)*HID + n;
        ((unsigned short*)Hh)[ho] = (unsigned short)hh;
        ((unsigned short*)Hl)[ho] = (unsigned short)ll;
    }
}

// ---------------- launch ----------------
extern "C" void kernel_launch(void* const* d_in, const int* in_sizes, int n_in,
                              void* d_out, int out_size)
{
    const int*   rnn   = (const int*)  d_in[0];
    const float* sv    = (const float*)d_in[1];
    const float* embed = (const float*)d_in[2];
    const float* U_w   = (const float*)d_in[3];
    const float* U_b   = (const float*)d_in[4];
    const float* S1_w  = (const float*)d_in[5];
    const float* S1_b  = (const float*)d_in[6];
    const float* V_w   = (const float*)d_in[7];
    const float* W_w   = (const float*)d_in[9];
    const float* P_w   = (const float*)d_in[11];
    const float* P_b   = (const float*)d_in[12];
    float* out = (float*)d_out;

    float *Gx,*c,*b3;
    __nv_bfloat16 *Xh,*Xl,*Uh,*Ul,*Sh,*Sl,*Hh,*Hl,*Bh,*Bl,*Wh,*Wl,*hsh,*hsl;
    cudaGetSymbolAddress((void**)&Gx, g_Gx);
    cudaGetSymbolAddress((void**)&c,  g_c);
    cudaGetSymbolAddress((void**)&b3, g_bias3);
    cudaGetSymbolAddress((void**)&Xh, g_Xh); cudaGetSymbolAddress((void**)&Xl, g_Xl);
    cudaGetSymbolAddress((void**)&Uh, g_Uh); cudaGetSymbolAddress((void**)&Ul, g_Ul);
    cudaGetSymbolAddress((void**)&Sh, g_Sh); cudaGetSymbolAddress((void**)&Sl, g_Sl);
    cudaGetSymbolAddress((void**)&Hh, g_Hh); cudaGetSymbolAddress((void**)&Hl, g_Hl);
    cudaGetSymbolAddress((void**)&Bh, g_Bh); cudaGetSymbolAddress((void**)&Bl, g_Bl);
    cudaGetSymbolAddress((void**)&Wh, g_Wh); cudaGetSymbolAddress((void**)&Wl, g_Wl);
    cudaGetSymbolAddress((void**)&hsh, g_hsh); cudaGetSymbolAddress((void**)&hsl, g_hsl);

    k_gather<<<dim3(TSTEPS, NB), 128>>>(rnn, embed, Xh, Xl);
    k_init<<<(NB*HID + 255)/256, 256>>>(sv, (const float*)d_in[8],
                                        (const float*)d_in[10], c, hsh, hsl, b3);

    // W^T split for the recurrence
    k_convT<<<dim3((4*HID)/32, HID/32), 256>>>(W_w, Wh, Wl, HID, 4*HID);

    // GEMM1: U = X @ U_w + U_b -> bf16 hi/lo only
    k_convT<<<dim3((4*STY)/32, EMB/32), 256>>>(U_w, Bh, Bl, EMB, 4*STY);
    k_mgemm<<<dim3(MPAD/128, (4*STY)/128), 256>>>(Xh, Xl, Bh, Bl, U_b,
                                                  nullptr, Uh, Ul, 4*STY, EMB, MPAD);
    // GEMM2: S = U @ S1_w + S1_b -> bf16 hi/lo only
    k_convT<<<dim3(STY/32, (4*STY)/32), 256>>>(S1_w, Bh, Bl, 4*STY, STY);
    k_mgemm<<<dim3(MPAD/128, STY/128), 256>>>(Uh, Ul, Bh, Bl, S1_b,
                                              nullptr, Sh, Sl, STY, 4*STY, MPAD);
    // GEMM3: Gx = S @ V_w + (V_b+W_b) -> fp32 only
    k_convT<<<dim3((4*HID)/32, STY/32), 256>>>(V_w, Bh, Bl, STY, 4*HID);
    k_mgemm<<<dim3(MPAD/128, (4*HID)/128), 256>>>(Sh, Sl, Bh, Bl, b3,
                                                  Gx, nullptr, nullptr, 4*HID, STY, MPAD);

    // recurrence: 63 HMMA steps, h split ping-pong
    for (int t = 0; t < TSTEPS; t++) {
        const __nv_bfloat16* hih = hsh + (t & 1)*NB*HID;
        const __nv_bfloat16* hil = hsl + (t & 1)*NB*HID;
        __nv_bfloat16* hoh = hsh + (1 - (t & 1))*NB*HID;
        __nv_bfloat16* hol = hsl + (1 - (t & 1))*NB*HID;
        k_stepT<<<(4*HID)/32, 128>>>(Gx, Wh, Wl, hih, hil, hoh, hol, c, Hh, Hl, t);
    }

    // GEMM4: out = H @ P_w + P_b -> fp32 d_out
    k_convT<<<dim3(VOCAB/32, HID/32), 256>>>(P_w, Bh, Bl, HID, VOCAB);
    k_mgemm<<<dim3(MPAD/128, VOCAB/128), 256>>>(Hh, Hl, Bh, Bl, P_b,
                                                out, nullptr, nullptr, VOCAB, HID, MROWS);
}

// round 12
// speedup vs baseline: 2.0281x; 1.1938x over previous
#include <cuda_runtime.h>
#include <cuda_bf16.h>
#include <cuda_fp16.h>
#include <stdint.h>
#include <math.h>

#define EMB   512
#define VOCAB 32000
#define HID   1024
#define STY   512
#define NB    32
#define SEQ   64
#define TSTEPS 63
#define MROWS (TSTEPS*NB)   /* 2016 */
#define MPAD  2048

// ---------------- device scratch (zero-initialized .bss) ----------------
__device__ float g_Gx[(size_t)MPAD*4*HID];
__device__ float g_c [NB*HID];
__device__ float g_bias3[4*HID];
__device__ __nv_bfloat16 g_Xh[MPAD*EMB],     g_Xl[MPAD*EMB];
__device__ __nv_bfloat16 g_Uh[MPAD*4*STY],   g_Ul[MPAD*4*STY];
__device__ __nv_bfloat16 g_Sh[MPAD*STY],     g_Sl[MPAD*STY];
__device__ __half        g_Hh[MPAD*HID],     g_Hl[MPAD*HID];   // fp16 split; rows>=2016 stay 0
__device__ __nv_bfloat16 g_Bh[(size_t)VOCAB*1024], g_Bl[(size_t)VOCAB*1024];
__device__ __nv_bfloat16 g_Wh[(size_t)4*HID*HID], g_Wl[(size_t)4*HID*HID]; // W^T split
__device__ __nv_bfloat16 g_hsh[2*NB*HID], g_hsl[2*NB*HID];                 // h ping-pong

// ---------------- helpers ----------------
static __device__ __forceinline__ uint32_t smem_u32(const void* p) {
    uint32_t a;
    asm("{ .reg .u64 t; cvta.to.shared.u64 t, %1; cvt.u32.u64 %0, t; }" : "=r"(a) : "l"(p));
    return a;
}
static __device__ __forceinline__ void cvt2(float f, unsigned& h, unsigned& l) {
    __nv_bfloat16 hb = __float2bfloat16_rn(f);
    float rem = f - __bfloat162float(hb);
    __nv_bfloat16 lb = __float2bfloat16_rn(rem);
    h = (unsigned)__bfloat16_as_ushort(hb);
    l = (unsigned)__bfloat16_as_ushort(lb);
}
static __device__ __forceinline__ void cvt2h(float f, unsigned& h, unsigned& l) {
    __half hb = __float2half_rn(f);
    float rem = f - __half2float(hb);
    __half lb = __float2half_rn(rem);
    h = (unsigned)__half_as_ushort(hb);
    l = (unsigned)__half_as_ushort(lb);
}
static __device__ __forceinline__ void ldm4(uint32_t addr, uint32_t* r) {
    asm volatile("ldmatrix.sync.aligned.m8n8.x4.shared.b16 {%0,%1,%2,%3}, [%4];"
        : "=r"(r[0]), "=r"(r[1]), "=r"(r[2]), "=r"(r[3]) : "r"(addr));
}
static __device__ __forceinline__ void mma16816(float* d, const uint32_t* a,
                                                const uint32_t* b) {
    asm volatile("mma.sync.aligned.m16n8k16.row.col.f32.bf16.bf16.f32 "
        "{%0,%1,%2,%3},{%4,%5,%6,%7},{%8,%9},{%0,%1,%2,%3};"
        : "+f"(d[0]), "+f"(d[1]), "+f"(d[2]), "+f"(d[3])
        : "r"(a[0]), "r"(a[1]), "r"(a[2]), "r"(a[3]), "r"(b[0]), "r"(b[1]));
}
static __device__ __forceinline__ void mma16816h(float* d, const uint32_t* a,
                                                 const uint32_t* b) {
    asm volatile("mma.sync.aligned.m16n8k16.row.col.f32.f16.f16.f32 "
        "{%0,%1,%2,%3},{%4,%5,%6,%7},{%8,%9},{%0,%1,%2,%3};"
        : "+f"(d[0]), "+f"(d[1]), "+f"(d[2]), "+f"(d[3])
        : "r"(a[0]), "r"(a[1]), "r"(a[2]), "r"(a[3]), "r"(b[0]), "r"(b[1]));
}
static __device__ __forceinline__ void cpa16(uint32_t s, const void* g) {
    asm volatile("cp.async.cg.shared.global [%0], [%1], 16;" :: "r"(s), "l"(g));
}
static __device__ __forceinline__ void cpcommit() {
    asm volatile("cp.async.commit_group;" ::: "memory");
}
template<int n> static __device__ __forceinline__ void cpwait() {
    asm volatile("cp.async.wait_group %0;" :: "n"(n) : "memory");
}

// ---------------- gather ----------------
__global__ void k_gather(const int* __restrict__ idx, const float* __restrict__ embed,
                         __nv_bfloat16* __restrict__ Xh, __nv_bfloat16* __restrict__ Xl)
{
    int t = blockIdx.x, b = blockIdx.y;
    int tok = idx[b*SEQ + t];
    float4 v = ((const float4*)(embed + (size_t)tok*EMB))[threadIdx.x];
    unsigned h0,l0,h1,l1,h2,l2,h3,l3;
    cvt2(v.x,h0,l0); cvt2(v.y,h1,l1); cvt2(v.z,h2,l2); cvt2(v.w,h3,l3);
    uint2 hv; hv.x = h0|(h1<<16); hv.y = h2|(h3<<16);
    uint2 lv; lv.x = l0|(l1<<16); lv.y = l2|(l3<<16);
    size_t o = (size_t)(t*NB + b)*EMB + threadIdx.x*4;
    *(uint2*)(Xh + o) = hv;
    *(uint2*)(Xl + o) = lv;
}

// ---------------- init: c, h0 split, combined bias ----------------
__global__ void k_init(const float* __restrict__ sv, const float* __restrict__ Vb,
                       const float* __restrict__ Wb, float* __restrict__ c,
                       __nv_bfloat16* __restrict__ hsh, __nv_bfloat16* __restrict__ hsl,
                       float* __restrict__ b3)
{
    int i = blockIdx.x*blockDim.x + threadIdx.x;
    if (i < NB*HID) {
        float v = sv[i];
        c[i] = v;
        unsigned h, l; cvt2(v, h, l);
        ((unsigned short*)hsh)[i] = (unsigned short)h;
        ((unsigned short*)hsl)[i] = (unsigned short)l;
    }
    if (i < 4*HID)  b3[i] = Vb[i] + Wb[i];
}

// ---------------- convert + transpose: fp32 [K][N] -> bf16 hi/lo [N][K] ----------------
__global__ void k_convT(const float* __restrict__ in, __nv_bfloat16* __restrict__ hiT,
                        __nv_bfloat16* __restrict__ loT, int K, int N)
{
    __shared__ float s[32][33];
    const int k0 = blockIdx.y*32, n0 = blockIdx.x*32;
    const int tid = threadIdx.x;
    {
        int r = tid>>3, c4 = (tid&7)*4;
        float4 v = *(const float4*)(in + (size_t)(k0+r)*N + n0 + c4);
        s[r][c4+0]=v.x; s[r][c4+1]=v.y; s[r][c4+2]=v.z; s[r][c4+3]=v.w;
    }
    __syncthreads();
    {
        int n = tid>>3, kq = (tid&7)*4;
        unsigned hh[4], ll[4];
#pragma unroll
        for (int i = 0; i < 4; ++i) cvt2(s[kq+i][n], hh[i], ll[i]);
        uint2 hv; hv.x = hh[0]|(hh[1]<<16); hv.y = hh[2]|(hh[3]<<16);
        uint2 lv; lv.x = ll[0]|(ll[1]<<16); lv.y = ll[2]|(ll[3]<<16);
        size_t o = ((size_t)(n0+n)*K + k0 + kq);
        *(uint2*)(hiT + o) = hv;
        *(uint2*)(loT + o) = lv;
    }
}

// ---------------- convert + transpose: fp32 [K][N] -> fp16 [N][K] (single) ----------------
__global__ void k_convT1(const float* __restrict__ in, __half* __restrict__ hiT,
                         int K, int N)
{
    __shared__ float s[32][33];
    const int k0 = blockIdx.y*32, n0 = blockIdx.x*32;
    const int tid = threadIdx.x;
    {
        int r = tid>>3, c4 = (tid&7)*4;
        float4 v = *(const float4*)(in + (size_t)(k0+r)*N + n0 + c4);
        s[r][c4+0]=v.x; s[r][c4+1]=v.y; s[r][c4+2]=v.z; s[r][c4+3]=v.w;
    }
    __syncthreads();
    {
        int n = tid>>3, kq = (tid&7)*4;
        unsigned hh[4];
#pragma unroll
        for (int i = 0; i < 4; ++i)
            hh[i] = (unsigned)__half_as_ushort(__float2half_rn(s[kq+i][n]));
        uint2 hv; hv.x = hh[0]|(hh[1]<<16); hv.y = hh[2]|(hh[3]<<16);
        *(uint2*)(hiT + ((size_t)(n0+n)*K + k0 + kq)) = hv;
    }
}

// ======== bf16 3-term HMMA GEMM: 128x128 block, 8 warps of 32x64, Kc=32 ========
#define STG   32768
#define AL_O  8192
#define BH_O  16384
#define BL_O  24576
static __device__ __forceinline__ uint32_t swz64(int row, int k16) {
    return (uint32_t)(row*64 + ((k16 ^ ((row>>1)&3))<<4));
}

__global__ __launch_bounds__(256, 2)
void k_mgemm(const __nv_bfloat16* __restrict__ Ah, const __nv_bfloat16* __restrict__ Al,
             const __nv_bfloat16* __restrict__ Bh, const __nv_bfloat16* __restrict__ Bl,
             const float* __restrict__ bias, float* __restrict__ C,
             __nv_bfloat16* __restrict__ Chi, __nv_bfloat16* __restrict__ Clo,
             int N, int K, int Mstore)
{
    __shared__ __align__(16) unsigned char sm[2*STG];
    const uint32_t sbase = smem_u32(sm);

    const int tid = threadIdx.x, lane = tid & 31, wid = tid >> 5;
    const int brow = blockIdx.x*128, bcol = blockIdx.y*128;

    const int lrow = tid >> 1, ak = (tid & 1)*2;
    const __nv_bfloat16* gAh_t = Ah + (size_t)(brow + lrow)*K + ak*8;
    const __nv_bfloat16* gAl_t = Al + (size_t)(brow + lrow)*K + ak*8;
    const __nv_bfloat16* gBh_t = Bh + (size_t)(bcol + lrow)*K + ak*8;
    const __nv_bfloat16* gBl_t = Bl + (size_t)(bcol + lrow)*K + ak*8;
    const uint32_t cs0 = sbase + swz64(lrow, ak);
    const uint32_t cs1 = sbase + swz64(lrow, ak+1);

    const int m0w = (wid & 3)*32, n0w = (wid >> 2)*64;
    const int arL = lane & 15;
    const int srA = (arL >> 1) & 3;
    const int brL = (lane & 7) + ((lane >> 4) << 3);
    const int srB = ((lane & 7) >> 1) & 3;
    const uint32_t aRowOff = (uint32_t)(m0w + arL)*64;
    const uint32_t bRowOff = (uint32_t)(n0w + brL)*64 + BH_O;

    float acc[2][8][4];
#pragma unroll
    for (int i = 0; i < 2; ++i)
#pragma unroll
        for (int j = 0; j < 8; ++j)
#pragma unroll
            for (int q = 0; q < 4; ++q) acc[i][j][q] = 0.f;

    const int nch = K >> 5;

    {
        cpa16(cs0, gAh_t);            cpa16(cs1, gAh_t + 8);
        cpa16(cs0 + AL_O, gAl_t);     cpa16(cs1 + AL_O, gAl_t + 8);
        cpa16(cs0 + BH_O, gBh_t);     cpa16(cs1 + BH_O, gBh_t + 8);
        cpa16(cs0 + BL_O, gBl_t);     cpa16(cs1 + BL_O, gBl_t + 8);
        cpcommit();
    }

    for (int c = 0; c < nch; ++c) {
        if (c + 1 < nch) {
            const uint32_t so = (uint32_t)((c+1) & 1)*STG;
            const int kc = (c+1)*32;
            cpa16(cs0 + so, gAh_t + kc);        cpa16(cs1 + so, gAh_t + kc + 8);
            cpa16(cs0 + AL_O + so, gAl_t + kc); cpa16(cs1 + AL_O + so, gAl_t + kc + 8);
            cpa16(cs0 + BH_O + so, gBh_t + kc); cpa16(cs1 + BH_O + so, gBh_t + kc + 8);
            cpa16(cs0 + BL_O + so, gBl_t + kc); cpa16(cs1 + BL_O + so, gBl_t + kc + 8);
            cpcommit();
            cpwait<1>();
        } else {
            cpwait<0>();
        }
        __syncthreads();

        const uint32_t sb_s = sbase + (uint32_t)(c & 1)*STG;
#pragma unroll
        for (int kk = 0; kk < 32; kk += 16) {
            uint32_t Xa[2][4], Xb[4][4], Xc[4][4];
            const int k16a = (kk >> 3) + (lane >> 4);
            const uint32_t abase = sb_s + aRowOff + ((uint32_t)(k16a ^ srA) << 4);
            const int k16b = (kk >> 3) + ((lane >> 3) & 1);
            const uint32_t bbase = sb_s + bRowOff + ((uint32_t)(k16b ^ srB) << 4);

#pragma unroll
            for (int mt = 0; mt < 2; ++mt) ldm4(abase + mt*16*64, Xa[mt]);
#pragma unroll
            for (int ng = 0; ng < 4; ++ng) ldm4(bbase + ng*16*64, Xb[ng]);
#pragma unroll
            for (int mt = 0; mt < 2; ++mt)
#pragma unroll
                for (int nt = 0; nt < 8; ++nt)
                    mma16816(acc[mt][nt], Xa[mt], &Xb[nt >> 1][(nt & 1)*2]);

#pragma unroll
            for (int ng = 0; ng < 4; ++ng) ldm4(bbase + (BL_O - BH_O) + ng*16*64, Xc[ng]);
#pragma unroll
            for (int mt = 0; mt < 2; ++mt)
#pragma unroll
                for (int nt = 0; nt < 8; ++nt)
                    mma16816(acc[mt][nt], Xa[mt], &Xc[nt >> 1][(nt & 1)*2]);

#pragma unroll
            for (int mt = 0; mt < 2; ++mt) ldm4(abase + AL_O + mt*16*64, Xc[mt]);
#pragma unroll
            for (int mt = 0; mt < 2; ++mt)
#pragma unroll
                for (int nt = 0; nt < 8; ++nt)
                    mma16816(acc[mt][nt], Xc[mt], &Xb[nt >> 1][(nt & 1)*2]);
        }
        __syncthreads();
    }

    const int g = lane >> 2, tg = lane & 3;
#pragma unroll
    for (int mt = 0; mt < 2; ++mt)
#pragma unroll
        for (int nt = 0; nt < 8; ++nt) {
            const int col = bcol + n0w + nt*8 + tg*2;
            const float b0 = bias[col], b1 = bias[col+1];
#pragma unroll
            for (int half = 0; half < 2; ++half) {
                const int row = brow + m0w + mt*16 + g + half*8;
                if (row < Mstore) {
                    float o0 = acc[mt][nt][half*2+0] + b0;
                    float o1 = acc[mt][nt][half*2+1] + b1;
                    const size_t o = (size_t)row*N + col;
                    if (C) { float2 v; v.x = o0; v.y = o1; *(float2*)(C + o) = v; }
                    if (Chi) {
                        unsigned h0,l0,h1,l1;
                        cvt2(o0,h0,l0); cvt2(o1,h1,l1);
                        *(uint32_t*)(Chi + o) = h0 | (h1<<16);
                        *(uint32_t*)(Clo + o) = l0 | (l1<<16);
                    }
                }
            }
        }
}

// ======== fp16 A-split 2-term GEMM (vocab projection) ========
// D = (Ah + Al) @ Bh^T + bias, fp16 operands, fp32 accum. A split exact.
#define STG2  24576
#define AL2_O 8192
#define BH2_O 16384
__global__ __launch_bounds__(256, 2)
void k_mgemm2(const __half* __restrict__ Ah, const __half* __restrict__ Al,
              const __half* __restrict__ Bh,
              const float* __restrict__ bias, float* __restrict__ C,
              int N, int K, int Mstore)
{
    __shared__ __align__(16) unsigned char sm[2*STG2];
    const uint32_t sbase = smem_u32(sm);

    const int tid = threadIdx.x, lane = tid & 31, wid = tid >> 5;
    const int brow = blockIdx.x*128, bcol = blockIdx.y*128;

    const int lrow = tid >> 1, ak = (tid & 1)*2;
    const __half* gAh_t = Ah + (size_t)(brow + lrow)*K + ak*8;
    const __half* gAl_t = Al + (size_t)(brow + lrow)*K + ak*8;
    const __half* gBh_t = Bh + (size_t)(bcol + lrow)*K + ak*8;
    const uint32_t cs0 = sbase + swz64(lrow, ak);
    const uint32_t cs1 = sbase + swz64(lrow, ak+1);

    const int m0w = (wid & 3)*32, n0w = (wid >> 2)*64;
    const int arL = lane & 15;
    const int srA = (arL >> 1) & 3;
    const int brL = (lane & 7) + ((lane >> 4) << 3);
    const int srB = ((lane & 7) >> 1) & 3;
    const uint32_t aRowOff = (uint32_t)(m0w + arL)*64;
    const uint32_t bRowOff = (uint32_t)(n0w + brL)*64 + BH2_O;

    float acc[2][8][4];
#pragma unroll
    for (int i = 0; i < 2; ++i)
#pragma unroll
        for (int j = 0; j < 8; ++j)
#pragma unroll
            for (int q = 0; q < 4; ++q) acc[i][j][q] = 0.f;

    const int nch = K >> 5;

    {
        cpa16(cs0, gAh_t);             cpa16(cs1, gAh_t + 8);
        cpa16(cs0 + AL2_O, gAl_t);     cpa16(cs1 + AL2_O, gAl_t + 8);
        cpa16(cs0 + BH2_O, gBh_t);     cpa16(cs1 + BH2_O, gBh_t + 8);
        cpcommit();
    }

    for (int c = 0; c < nch; ++c) {
        if (c + 1 < nch) {
            const uint32_t so = (uint32_t)((c+1) & 1)*STG2;
            const int kc = (c+1)*32;
            cpa16(cs0 + so, gAh_t + kc);         cpa16(cs1 + so, gAh_t + kc + 8);
            cpa16(cs0 + AL2_O + so, gAl_t + kc); cpa16(cs1 + AL2_O + so, gAl_t + kc + 8);
            cpa16(cs0 + BH2_O + so, gBh_t + kc); cpa16(cs1 + BH2_O + so, gBh_t + kc + 8);
            cpcommit();
            cpwait<1>();
        } else {
            cpwait<0>();
        }
        __syncthreads();

        const uint32_t sb_s = sbase + (uint32_t)(c & 1)*STG2;
#pragma unroll
        for (int kk = 0; kk < 32; kk += 16) {
            uint32_t Xa[2][4], Xd[2][4], Xb[4][4];
            const int k16a = (kk >> 3) + (lane >> 4);
            const uint32_t abase = sb_s + aRowOff + ((uint32_t)(k16a ^ srA) << 4);
            const int k16b = (kk >> 3) + ((lane >> 3) & 1);
            const uint32_t bbase = sb_s + bRowOff + ((uint32_t)(k16b ^ srB) << 4);

#pragma unroll
            for (int mt = 0; mt < 2; ++mt) ldm4(abase + mt*16*64, Xa[mt]);
#pragma unroll
            for (int mt = 0; mt < 2; ++mt) ldm4(abase + AL2_O + mt*16*64, Xd[mt]);
#pragma unroll
            for (int ng = 0; ng < 4; ++ng) ldm4(bbase + ng*16*64, Xb[ng]);

            // term1: ah x bh
#pragma unroll
            for (int mt = 0; mt < 2; ++mt)
#pragma unroll
                for (int nt = 0; nt < 8; ++nt)
                    mma16816h(acc[mt][nt], Xa[mt], &Xb[nt >> 1][(nt & 1)*2]);
            // term2: al x bh
#pragma unroll
            for (int mt = 0; mt < 2; ++mt)
#pragma unroll
                for (int nt = 0; nt < 8; ++nt)
                    mma16816h(acc[mt][nt], Xd[mt], &Xb[nt >> 1][(nt & 1)*2]);
        }
        __syncthreads();
    }

    const int g = lane >> 2, tg = lane & 3;
#pragma unroll
    for (int mt = 0; mt < 2; ++mt)
#pragma unroll
        for (int nt = 0; nt < 8; ++nt) {
            const int col = bcol + n0w + nt*8 + tg*2;
            const float b0 = bias[col], b1 = bias[col+1];
#pragma unroll
            for (int half = 0; half < 2; ++half) {
                const int row = brow + m0w + mt*16 + g + half*8;
                if (row < Mstore) {
                    float2 v;
                    v.x = acc[mt][nt][half*2+0] + b0;
                    v.y = acc[mt][nt][half*2+1] + b1;
                    *(float2*)(C + (size_t)row*N + col) = v;
                }
            }
        }
}

// ======== HMMA LSTM step: g = Gx + h@W, gates, c/h update ========
static __device__ __forceinline__ uint32_t soff(int row, int seg) {
    return (uint32_t)(row*128 + ((seg ^ (row & 7)) << 4));
}

__global__ __launch_bounds__(128)
void k_stepT(const float* __restrict__ Gx,
             const __nv_bfloat16* __restrict__ Wh, const __nv_bfloat16* __restrict__ Wl,
             const __nv_bfloat16* __restrict__ hih, const __nv_bfloat16* __restrict__ hil,
             __nv_bfloat16* __restrict__ hoh, __nv_bfloat16* __restrict__ hol,
             float* __restrict__ c,
             __half* __restrict__ Hh, __half* __restrict__ Hl, int ts)
{
    __shared__ __align__(16) unsigned char sm[2*16384 + 4096];
    float* gsm = (float*)(sm + 2*16384);
    const uint32_t sbase = smem_u32(sm);
    const int tid = threadIdx.x, lane = tid & 31, w = tid >> 5;
    const int n0 = blockIdx.x * 8;

    const int lrow = tid >> 2, sp = (tid & 3)*2;
    const uint32_t so0 = soff(lrow, sp);
    const uint32_t so1 = soff(lrow, sp+1);
    const int grow = (lrow >> 3)*HID + n0 + (lrow & 7);
    const __nv_bfloat16* gh_h = hih + lrow*HID + sp*8;
    const __nv_bfloat16* gh_l = hil + lrow*HID + sp*8;
    const __nv_bfloat16* gw_h = Wh + (size_t)grow*HID + sp*8;
    const __nv_bfloat16* gw_l = Wl + (size_t)grow*HID + sp*8;

    float acc[2][4];
#pragma unroll
    for (int i = 0; i < 2; ++i)
#pragma unroll
        for (int q = 0; q < 4; ++q) acc[i][q] = 0.f;

    {
        cpa16(sbase         + so0, gh_h); cpa16(sbase         + so1, gh_h + 8);
        cpa16(sbase + 4096  + so0, gh_l); cpa16(sbase + 4096  + so1, gh_l + 8);
        cpa16(sbase + 8192  + so0, gw_h); cpa16(sbase + 8192  + so1, gw_h + 8);
        cpa16(sbase + 12288 + so0, gw_l); cpa16(sbase + 12288 + so1, gw_l + 8);
        cpcommit();
    }

    const int arow0 = (lane & 15), arow1 = 16 + (lane & 15);
    const int rw = w*8 + (lane & 7), si = lane >> 3;

    for (int cc = 0; cc < 16; ++cc) {
        if (cc + 1 < 16) {
            const uint32_t so = (uint32_t)((cc+1) & 1)*16384;
            const int kc = (cc+1)*64;
            cpa16(sbase + so         + so0, gh_h + kc); cpa16(sbase + so         + so1, gh_h + kc + 8);
            cpa16(sbase + so + 4096  + so0, gh_l + kc); cpa16(sbase + so + 4096  + so1, gh_l + kc + 8);
            cpa16(sbase + so + 8192  + so0, gw_h + kc); cpa16(sbase + so + 8192  + so1, gw_h + kc + 8);
            cpa16(sbase + so + 12288 + so0, gw_l + kc); cpa16(sbase + so + 12288 + so1, gw_l + kc + 8);
            cpcommit();
            cpwait<1>();
        } else {
            cpwait<0>();
        }
        __syncthreads();

        const uint32_t sb = sbase + (uint32_t)(cc & 1)*16384;
        uint32_t ah[4][2][4], al[4][2][4], bh[2][4], bl[2][4];
#pragma unroll
        for (int kb = 0; kb < 2; ++kb) {
            ldm4(sb + 8192  + soff(rw, kb*4 + si), bh[kb]);
            ldm4(sb + 12288 + soff(rw, kb*4 + si), bl[kb]);
        }
#pragma unroll
        for (int q = 0; q < 4; ++q) {
            const int seg = q*2 + (lane >> 4);
            ldm4(sb        + soff(arow0, seg), ah[q][0]);
            ldm4(sb        + soff(arow1, seg), ah[q][1]);
            ldm4(sb + 4096 + soff(arow0, seg), al[q][0]);
            ldm4(sb + 4096 + soff(arow1, seg), al[q][1]);
        }
#pragma unroll
        for (int q = 0; q < 4; ++q)
#pragma unroll
            for (int mt = 0; mt < 2; ++mt)
                mma16816(acc[mt], ah[q][mt], &bh[q >> 1][(q & 1)*2]);
#pragma unroll
        for (int q = 0; q < 4; ++q)
#pragma unroll
            for (int mt = 0; mt < 2; ++mt)
                mma16816(acc[mt], ah[q][mt], &bl[q >> 1][(q & 1)*2]);
#pragma unroll
        for (int q = 0; q < 4; ++q)
#pragma unroll
            for (int mt = 0; mt < 2; ++mt)
                mma16816(acc[mt], al[q][mt], &bh[q >> 1][(q & 1)*2]);
        __syncthreads();
    }

    {
        const int r = lane >> 2, nl0 = (lane & 3)*2;
#pragma unroll
        for (int mt = 0; mt < 2; ++mt) {
            const int b0 = mt*16 + r, b1 = b0 + 8;
            gsm[(w*32 + b0)*8 + nl0]     = acc[mt][0];
            gsm[(w*32 + b0)*8 + nl0 + 1] = acc[mt][1];
            gsm[(w*32 + b1)*8 + nl0]     = acc[mt][2];
            gsm[(w*32 + b1)*8 + nl0 + 1] = acc[mt][3];
        }
    }
    __syncthreads();

#pragma unroll
    for (int rep = 0; rep < 2; ++rep) {
        const int idx = tid + rep*128;
        const int b = idx >> 3, nl = idx & 7;
        const int n = n0 + nl;
        const size_t gxrow = (size_t)(ts*NB + b)*(4*HID);
        float gi = gsm[(0*32 + b)*8 + nl] + Gx[gxrow + 0*HID + n];
        float gf = gsm[(1*32 + b)*8 + nl] + Gx[gxrow + 1*HID + n];
        float go = gsm[(2*32 + b)*8 + nl] + Gx[gxrow + 2*HID + n];
        float gc = gsm[(3*32 + b)*8 + nl] + Gx[gxrow + 3*HID + n];
        float cv = c[b*HID + n];
        float si_ = 1.f / (1.f + expf(-gi));
        float sf  = 1.f / (1.f + expf(-gf));
        float so_ = 1.f / (1.f + expf(-go));
        float c_new = sf * cv + si_ * tanhf(gc);
        float h_new = so_ * c_new;
        c[b*HID + n] = c_new;
        unsigned hh, ll;
        cvt2(h_new, hh, ll);
        ((unsigned short*)hoh)[b*HID + n] = (unsigned short)hh;
        ((unsigned short*)hol)[b*HID + n] = (unsigned short)ll;
        // fp16 exact split for the vocab GEMM input
        unsigned fh, fl;
        cvt2h(h_new, fh, fl);
        const size_t ho = (size_t)(b*TSTEPS + ts)*HID + n;
        ((unsigned short*)Hh)[ho] = (unsigned short)fh;
        ((unsigned short*)Hl)[ho] = (unsigned short)fl;
    }
}

// ---------------- launch ----------------
extern "C" void kernel_launch(void* const* d_in, const int* in_sizes, int n_in,
                              void* d_out, int out_size)
{
    const int*   rnn   = (const int*)  d_in[0];
    const float* sv    = (const float*)d_in[1];
    const float* embed = (const float*)d_in[2];
    const float* U_w   = (const float*)d_in[3];
    const float* U_b   = (const float*)d_in[4];
    const float* S1_w  = (const float*)d_in[5];
    const float* S1_b  = (const float*)d_in[6];
    const float* V_w   = (const float*)d_in[7];
    const float* W_w   = (const float*)d_in[9];
    const float* P_w   = (const float*)d_in[11];
    const float* P_b   = (const float*)d_in[12];
    float* out = (float*)d_out;

    float *Gx,*c,*b3;
    __nv_bfloat16 *Xh,*Xl,*Uh,*Ul,*Sh,*Sl,*Bh,*Bl,*Wh,*Wl,*hsh,*hsl;
    __half *Hh,*Hl;
    cudaGetSymbolAddress((void**)&Gx, g_Gx);
    cudaGetSymbolAddress((void**)&c,  g_c);
    cudaGetSymbolAddress((void**)&b3, g_bias3);
    cudaGetSymbolAddress((void**)&Xh, g_Xh); cudaGetSymbolAddress((void**)&Xl, g_Xl);
    cudaGetSymbolAddress((void**)&Uh, g_Uh); cudaGetSymbolAddress((void**)&Ul, g_Ul);
    cudaGetSymbolAddress((void**)&Sh, g_Sh); cudaGetSymbolAddress((void**)&Sl, g_Sl);
    cudaGetSymbolAddress((void**)&Hh, g_Hh); cudaGetSymbolAddress((void**)&Hl, g_Hl);
    cudaGetSymbolAddress((void**)&Bh, g_Bh); cudaGetSymbolAddress((void**)&Bl, g_Bl);
    cudaGetSymbolAddress((void**)&Wh, g_Wh); cudaGetSymbolAddress((void**)&Wl, g_Wl);
    cudaGetSymbolAddress((void**)&hsh, g_hsh); cudaGetSymbolAddress((void**)&hsl, g_hsl);

    k_gather<<<dim3(TSTEPS, NB), 128>>>(rnn, embed, Xh, Xl);
    k_init<<<(NB*HID + 255)/256, 256>>>(sv, (const float*)d_in[8],
                                        (const float*)d_in[10], c, hsh, hsl, b3);

    // W^T split for the recurrence
    k_convT<<<dim3((4*HID)/32, HID/32), 256>>>(W_w, Wh, Wl, HID, 4*HID);

    // GEMM1: U = X @ U_w + U_b -> bf16 hi/lo only
    k_convT<<<dim3((4*STY)/32, EMB/32), 256>>>(U_w, Bh, Bl, EMB, 4*STY);
    k_mgemm<<<dim3(MPAD/128, (4*STY)/128), 256>>>(Xh, Xl, Bh, Bl, U_b,
                                                  nullptr, Uh, Ul, 4*STY, EMB, MPAD);
    // GEMM2: S = U @ S1_w + S1_b -> bf16 hi/lo only
    k_convT<<<dim3(STY/32, (4*STY)/32), 256>>>(S1_w, Bh, Bl, 4*STY, STY);
    k_mgemm<<<dim3(MPAD/128, STY/128), 256>>>(Uh, Ul, Bh, Bl, S1_b,
                                              nullptr, Sh, Sl, STY, 4*STY, MPAD);
    // GEMM3: Gx = S @ V_w + (V_b+W_b) -> fp32 only
    k_convT<<<dim3((4*HID)/32, STY/32), 256>>>(V_w, Bh, Bl, STY, 4*HID);
    k_mgemm<<<dim3(MPAD/128, (4*HID)/128), 256>>>(Sh, Sl, Bh, Bl, b3,
                                                  Gx, nullptr, nullptr, 4*HID, STY, MPAD);

    // recurrence: 63 HMMA steps, h split ping-pong
    for (int t = 0; t < TSTEPS; t++) {
        const __nv_bfloat16* hih = hsh + (t & 1)*NB*HID;
        const __nv_bfloat16* hil = hsl + (t & 1)*NB*HID;
        __nv_bfloat16* hoh = hsh + (1 - (t & 1))*NB*HID;
        __nv_bfloat16* hol = hsl + (1 - (t & 1))*NB*HID;
        k_stepT<<<(4*HID)/32, 128>>>(Gx, Wh, Wl, hih, hil, hoh, hol, c, Hh, Hl, t);
    }

    // GEMM4 (fp16 2-term): out = H @ P_w + P_b -> fp32 d_out
    __half* B16 = (__half*)Bh;   // reuse staging buffer as fp16
    k_convT1<<<dim3(VOCAB/32, HID/32), 256>>>(P_w, B16, HID, VOCAB);
    k_mgemm2<<<dim3(MPAD/128, VOCAB/128), 256>>>(Hh, Hl, B16, P_b,
                                                 out, VOCAB, HID, MROWS);
}

// round 13
// speedup vs baseline: 2.0364x; 1.0041x over previous
#include <cuda_runtime.h>
#include <cuda_bf16.h>
#include <cuda_fp16.h>
#include <stdint.h>
#include <math.h>

#define EMB   512
#define VOCAB 32000
#define HID   1024
#define STY   512
#define NB    32
#define SEQ   64
#define TSTEPS 63
#define MROWS (TSTEPS*NB)   /* 2016 */
#define MPAD  2048

// ---------------- device scratch (zero-initialized .bss) ----------------
__device__ float g_Gx[(size_t)MPAD*4*HID];
__device__ float g_c [NB*HID];
__device__ float g_bias3[4*HID];
__device__ __nv_bfloat16 g_Xh[MPAD*EMB],     g_Xl[MPAD*EMB];
__device__ __nv_bfloat16 g_Uh[MPAD*4*STY],   g_Ul[MPAD*4*STY];
__device__ __nv_bfloat16 g_Sh[MPAD*STY],     g_Sl[MPAD*STY];
__device__ __half        g_Hh[MPAD*HID],     g_Hl[MPAD*HID];   // fp16 split; rows>=2016 stay 0
__device__ __nv_bfloat16 g_Bh[(size_t)VOCAB*1024], g_Bl[(size_t)VOCAB*1024];
__device__ __half        g_P16[(size_t)VOCAB*1024];            // fp16 P_w^T
__device__ __nv_bfloat16 g_Wh[(size_t)4*HID*HID], g_Wl[(size_t)4*HID*HID]; // W^T split
__device__ __nv_bfloat16 g_hsh[2*NB*HID], g_hsl[2*NB*HID];                 // h ping-pong

// ---------------- helpers ----------------
static __device__ __forceinline__ uint32_t smem_u32(const void* p) {
    uint32_t a;
    asm("{ .reg .u64 t; cvta.to.shared.u64 t, %1; cvt.u32.u64 %0, t; }" : "=r"(a) : "l"(p));
    return a;
}
static __device__ __forceinline__ void cvt2(float f, unsigned& h, unsigned& l) {
    __nv_bfloat16 hb = __float2bfloat16_rn(f);
    float rem = f - __bfloat162float(hb);
    __nv_bfloat16 lb = __float2bfloat16_rn(rem);
    h = (unsigned)__bfloat16_as_ushort(hb);
    l = (unsigned)__bfloat16_as_ushort(lb);
}
static __device__ __forceinline__ void cvt2h(float f, unsigned& h, unsigned& l) {
    __half hb = __float2half_rn(f);
    float rem = f - __half2float(hb);
    __half lb = __float2half_rn(rem);
    h = (unsigned)__half_as_ushort(hb);
    l = (unsigned)__half_as_ushort(lb);
}
static __device__ __forceinline__ void ldm4(uint32_t addr, uint32_t* r) {
    asm volatile("ldmatrix.sync.aligned.m8n8.x4.shared.b16 {%0,%1,%2,%3}, [%4];"
        : "=r"(r[0]), "=r"(r[1]), "=r"(r[2]), "=r"(r[3]) : "r"(addr));
}
static __device__ __forceinline__ void mma16816(float* d, const uint32_t* a,
                                                const uint32_t* b) {
    asm volatile("mma.sync.aligned.m16n8k16.row.col.f32.bf16.bf16.f32 "
        "{%0,%1,%2,%3},{%4,%5,%6,%7},{%8,%9},{%0,%1,%2,%3};"
        : "+f"(d[0]), "+f"(d[1]), "+f"(d[2]), "+f"(d[3])
        : "r"(a[0]), "r"(a[1]), "r"(a[2]), "r"(a[3]), "r"(b[0]), "r"(b[1]));
}
static __device__ __forceinline__ void mma16816h(float* d, const uint32_t* a,
                                                 const uint32_t* b) {
    asm volatile("mma.sync.aligned.m16n8k16.row.col.f32.f16.f16.f32 "
        "{%0,%1,%2,%3},{%4,%5,%6,%7},{%8,%9},{%0,%1,%2,%3};"
        : "+f"(d[0]), "+f"(d[1]), "+f"(d[2]), "+f"(d[3])
        : "r"(a[0]), "r"(a[1]), "r"(a[2]), "r"(a[3]), "r"(b[0]), "r"(b[1]));
}
static __device__ __forceinline__ void cpa16(uint32_t s, const void* g) {
    asm volatile("cp.async.cg.shared.global [%0], [%1], 16;" :: "r"(s), "l"(g));
}
static __device__ __forceinline__ void cpcommit() {
    asm volatile("cp.async.commit_group;" ::: "memory");
}
template<int n> static __device__ __forceinline__ void cpwait() {
    asm volatile("cp.async.wait_group %0;" :: "n"(n) : "memory");
}

// ---------------- gather ----------------
__global__ void k_gather(const int* __restrict__ idx, const float* __restrict__ embed,
                         __nv_bfloat16* __restrict__ Xh, __nv_bfloat16* __restrict__ Xl)
{
    int t = blockIdx.x, b = blockIdx.y;
    int tok = idx[b*SEQ + t];
    float4 v = ((const float4*)(embed + (size_t)tok*EMB))[threadIdx.x];
    unsigned h0,l0,h1,l1,h2,l2,h3,l3;
    cvt2(v.x,h0,l0); cvt2(v.y,h1,l1); cvt2(v.z,h2,l2); cvt2(v.w,h3,l3);
    uint2 hv; hv.x = h0|(h1<<16); hv.y = h2|(h3<<16);
    uint2 lv; lv.x = l0|(l1<<16); lv.y = l2|(l3<<16);
    size_t o = (size_t)(t*NB + b)*EMB + threadIdx.x*4;
    *(uint2*)(Xh + o) = hv;
    *(uint2*)(Xl + o) = lv;
}

// ---------------- init: c, h0 split, combined bias ----------------
__global__ void k_init(const float* __restrict__ sv, const float* __restrict__ Vb,
                       const float* __restrict__ Wb, float* __restrict__ c,
                       __nv_bfloat16* __restrict__ hsh, __nv_bfloat16* __restrict__ hsl,
                       float* __restrict__ b3)
{
    int i = blockIdx.x*blockDim.x + threadIdx.x;
    if (i < NB*HID) {
        float v = sv[i];
        c[i] = v;
        unsigned h, l; cvt2(v, h, l);
        ((unsigned short*)hsh)[i] = (unsigned short)h;
        ((unsigned short*)hsl)[i] = (unsigned short)l;
    }
    if (i < 4*HID)  b3[i] = Vb[i] + Wb[i];
}

// ---------------- convert + transpose: fp32 [K][N] -> bf16 hi/lo [N][K] ----------------
__global__ void k_convT(const float* __restrict__ in, __nv_bfloat16* __restrict__ hiT,
                        __nv_bfloat16* __restrict__ loT, int K, int N)
{
    __shared__ float s[32][33];
    const int k0 = blockIdx.y*32, n0 = blockIdx.x*32;
    const int tid = threadIdx.x;
    {
        int r = tid>>3, c4 = (tid&7)*4;
        float4 v = *(const float4*)(in + (size_t)(k0+r)*N + n0 + c4);
        s[r][c4+0]=v.x; s[r][c4+1]=v.y; s[r][c4+2]=v.z; s[r][c4+3]=v.w;
    }
    __syncthreads();
    {
        int n = tid>>3, kq = (tid&7)*4;
        unsigned hh[4], ll[4];
#pragma unroll
        for (int i = 0; i < 4; ++i) cvt2(s[kq+i][n], hh[i], ll[i]);
        uint2 hv; hv.x = hh[0]|(hh[1]<<16); hv.y = hh[2]|(hh[3]<<16);
        uint2 lv; lv.x = ll[0]|(ll[1]<<16); lv.y = ll[2]|(ll[3]<<16);
        size_t o = ((size_t)(n0+n)*K + k0 + kq);
        *(uint2*)(hiT + o) = hv;
        *(uint2*)(loT + o) = lv;
    }
}

// ---------------- convert + transpose: fp32 [K][N] -> fp16 [N][K] (single) ----------------
__global__ void k_convT1(const float* __restrict__ in, __half* __restrict__ hiT,
                         int K, int N)
{
    __shared__ float s[32][33];
    const int k0 = blockIdx.y*32, n0 = blockIdx.x*32;
    const int tid = threadIdx.x;
    {
        int r = tid>>3, c4 = (tid&7)*4;
        float4 v = *(const float4*)(in + (size_t)(k0+r)*N + n0 + c4);
        s[r][c4+0]=v.x; s[r][c4+1]=v.y; s[r][c4+2]=v.z; s[r][c4+3]=v.w;
    }
    __syncthreads();
    {
        int n = tid>>3, kq = (tid&7)*4;
        unsigned hh[4];
#pragma unroll
        for (int i = 0; i < 4; ++i)
            hh[i] = (unsigned)__half_as_ushort(__float2half_rn(s[kq+i][n]));
        uint2 hv; hv.x = hh[0]|(hh[1]<<16); hv.y = hh[2]|(hh[3]<<16);
        *(uint2*)(hiT + ((size_t)(n0+n)*K + k0 + kq)) = hv;
    }
}

// ======== bf16 3-term HMMA GEMM: 128x128 block, 8 warps of 32x64, Kc=32 ========
#define STG   32768
#define AL_O  8192
#define BH_O  16384
#define BL_O  24576
static __device__ __forceinline__ uint32_t swz64(int row, int k16) {
    return (uint32_t)(row*64 + ((k16 ^ ((row>>1)&3))<<4));
}

__global__ __launch_bounds__(256, 2)
void k_mgemm(const __nv_bfloat16* __restrict__ Ah, const __nv_bfloat16* __restrict__ Al,
             const __nv_bfloat16* __restrict__ Bh, const __nv_bfloat16* __restrict__ Bl,
             const float* __restrict__ bias, float* __restrict__ C,
             __nv_bfloat16* __restrict__ Chi, __nv_bfloat16* __restrict__ Clo,
             int N, int K, int Mstore)
{
    __shared__ __align__(16) unsigned char sm[2*STG];
    const uint32_t sbase = smem_u32(sm);

    const int tid = threadIdx.x, lane = tid & 31, wid = tid >> 5;
    const int brow = blockIdx.x*128, bcol = blockIdx.y*128;

    const int lrow = tid >> 1, ak = (tid & 1)*2;
    const __nv_bfloat16* gAh_t = Ah + (size_t)(brow + lrow)*K + ak*8;
    const __nv_bfloat16* gAl_t = Al + (size_t)(brow + lrow)*K + ak*8;
    const __nv_bfloat16* gBh_t = Bh + (size_t)(bcol + lrow)*K + ak*8;
    const __nv_bfloat16* gBl_t = Bl + (size_t)(bcol + lrow)*K + ak*8;
    const uint32_t cs0 = sbase + swz64(lrow, ak);
    const uint32_t cs1 = sbase + swz64(lrow, ak+1);

    const int m0w = (wid & 3)*32, n0w = (wid >> 2)*64;
    const int arL = lane & 15;
    const int srA = (arL >> 1) & 3;
    const int brL = (lane & 7) + ((lane >> 4) << 3);
    const int srB = ((lane & 7) >> 1) & 3;
    const uint32_t aRowOff = (uint32_t)(m0w + arL)*64;
    const uint32_t bRowOff = (uint32_t)(n0w + brL)*64 + BH_O;

    float acc[2][8][4];
#pragma unroll
    for (int i = 0; i < 2; ++i)
#pragma unroll
        for (int j = 0; j < 8; ++j)
#pragma unroll
            for (int q = 0; q < 4; ++q) acc[i][j][q] = 0.f;

    const int nch = K >> 5;

    {
        cpa16(cs0, gAh_t);            cpa16(cs1, gAh_t + 8);
        cpa16(cs0 + AL_O, gAl_t);     cpa16(cs1 + AL_O, gAl_t + 8);
        cpa16(cs0 + BH_O, gBh_t);     cpa16(cs1 + BH_O, gBh_t + 8);
        cpa16(cs0 + BL_O, gBl_t);     cpa16(cs1 + BL_O, gBl_t + 8);
        cpcommit();
    }

    for (int c = 0; c < nch; ++c) {
        if (c + 1 < nch) {
            const uint32_t so = (uint32_t)((c+1) & 1)*STG;
            const int kc = (c+1)*32;
            cpa16(cs0 + so, gAh_t + kc);        cpa16(cs1 + so, gAh_t + kc + 8);
            cpa16(cs0 + AL_O + so, gAl_t + kc); cpa16(cs1 + AL_O + so, gAl_t + kc + 8);
            cpa16(cs0 + BH_O + so, gBh_t + kc); cpa16(cs1 + BH_O + so, gBh_t + kc + 8);
            cpa16(cs0 + BL_O + so, gBl_t + kc); cpa16(cs1 + BL_O + so, gBl_t + kc + 8);
            cpcommit();
            cpwait<1>();
        } else {
            cpwait<0>();
        }
        __syncthreads();

        const uint32_t sb_s = sbase + (uint32_t)(c & 1)*STG;
#pragma unroll
        for (int kk = 0; kk < 32; kk += 16) {
            uint32_t Xa[2][4], Xb[4][4], Xc[4][4];
            const int k16a = (kk >> 3) + (lane >> 4);
            const uint32_t abase = sb_s + aRowOff + ((uint32_t)(k16a ^ srA) << 4);
            const int k16b = (kk >> 3) + ((lane >> 3) & 1);
            const uint32_t bbase = sb_s + bRowOff + ((uint32_t)(k16b ^ srB) << 4);

#pragma unroll
            for (int mt = 0; mt < 2; ++mt) ldm4(abase + mt*16*64, Xa[mt]);
#pragma unroll
            for (int ng = 0; ng < 4; ++ng) ldm4(bbase + ng*16*64, Xb[ng]);
#pragma unroll
            for (int mt = 0; mt < 2; ++mt)
#pragma unroll
                for (int nt = 0; nt < 8; ++nt)
                    mma16816(acc[mt][nt], Xa[mt], &Xb[nt >> 1][(nt & 1)*2]);

#pragma unroll
            for (int ng = 0; ng < 4; ++ng) ldm4(bbase + (BL_O - BH_O) + ng*16*64, Xc[ng]);
#pragma unroll
            for (int mt = 0; mt < 2; ++mt)
#pragma unroll
                for (int nt = 0; nt < 8; ++nt)
                    mma16816(acc[mt][nt], Xa[mt], &Xc[nt >> 1][(nt & 1)*2]);

#pragma unroll
            for (int mt = 0; mt < 2; ++mt) ldm4(abase + AL_O + mt*16*64, Xc[mt]);
#pragma unroll
            for (int mt = 0; mt < 2; ++mt)
#pragma unroll
                for (int nt = 0; nt < 8; ++nt)
                    mma16816(acc[mt][nt], Xc[mt], &Xb[nt >> 1][(nt & 1)*2]);
        }
        __syncthreads();
    }

    const int g = lane >> 2, tg = lane & 3;
#pragma unroll
    for (int mt = 0; mt < 2; ++mt)
#pragma unroll
        for (int nt = 0; nt < 8; ++nt) {
            const int col = bcol + n0w + nt*8 + tg*2;
            const float b0 = bias[col], b1 = bias[col+1];
#pragma unroll
            for (int half = 0; half < 2; ++half) {
                const int row = brow + m0w + mt*16 + g + half*8;
                if (row < Mstore) {
                    float o0 = acc[mt][nt][half*2+0] + b0;
                    float o1 = acc[mt][nt][half*2+1] + b1;
                    const size_t o = (size_t)row*N + col;
                    if (C) { float2 v; v.x = o0; v.y = o1; *(float2*)(C + o) = v; }
                    if (Chi) {
                        unsigned h0,l0,h1,l1;
                        cvt2(o0,h0,l0); cvt2(o1,h1,l1);
                        *(uint32_t*)(Chi + o) = h0 | (h1<<16);
                        *(uint32_t*)(Clo + o) = l0 | (l1<<16);
                    }
                }
            }
        }
}

// ======== fp16 A-split 2-term GEMM (vocab projection) ========
#define STG2  24576
#define AL2_O 8192
#define BH2_O 16384
__global__ __launch_bounds__(256, 2)
void k_mgemm2(const __half* __restrict__ Ah, const __half* __restrict__ Al,
              const __half* __restrict__ Bh,
              const float* __restrict__ bias, float* __restrict__ C,
              int N, int K, int Mstore)
{
    __shared__ __align__(16) unsigned char sm[2*STG2];
    const uint32_t sbase = smem_u32(sm);

    const int tid = threadIdx.x, lane = tid & 31, wid = tid >> 5;
    const int brow = blockIdx.x*128, bcol = blockIdx.y*128;

    const int lrow = tid >> 1, ak = (tid & 1)*2;
    const __half* gAh_t = Ah + (size_t)(brow + lrow)*K + ak*8;
    const __half* gAl_t = Al + (size_t)(brow + lrow)*K + ak*8;
    const __half* gBh_t = Bh + (size_t)(bcol + lrow)*K + ak*8;
    const uint32_t cs0 = sbase + swz64(lrow, ak);
    const uint32_t cs1 = sbase + swz64(lrow, ak+1);

    const int m0w = (wid & 3)*32, n0w = (wid >> 2)*64;
    const int arL = lane & 15;
    const int srA = (arL >> 1) & 3;
    const int brL = (lane & 7) + ((lane >> 4) << 3);
    const int srB = ((lane & 7) >> 1) & 3;
    const uint32_t aRowOff = (uint32_t)(m0w + arL)*64;
    const uint32_t bRowOff = (uint32_t)(n0w + brL)*64 + BH2_O;

    float acc[2][8][4];
#pragma unroll
    for (int i = 0; i < 2; ++i)
#pragma unroll
        for (int j = 0; j < 8; ++j)
#pragma unroll
            for (int q = 0; q < 4; ++q) acc[i][j][q] = 0.f;

    const int nch = K >> 5;

    {
        cpa16(cs0, gAh_t);             cpa16(cs1, gAh_t + 8);
        cpa16(cs0 + AL2_O, gAl_t);     cpa16(cs1 + AL2_O, gAl_t + 8);
        cpa16(cs0 + BH2_O, gBh_t);     cpa16(cs1 + BH2_O, gBh_t + 8);
        cpcommit();
    }

    for (int c = 0; c < nch; ++c) {
        if (c + 1 < nch) {
            const uint32_t so = (uint32_t)((c+1) & 1)*STG2;
            const int kc = (c+1)*32;
            cpa16(cs0 + so, gAh_t + kc);         cpa16(cs1 + so, gAh_t + kc + 8);
            cpa16(cs0 + AL2_O + so, gAl_t + kc); cpa16(cs1 + AL2_O + so, gAl_t + kc + 8);
            cpa16(cs0 + BH2_O + so, gBh_t + kc); cpa16(cs1 + BH2_O + so, gBh_t + kc + 8);
            cpcommit();
            cpwait<1>();
        } else {
            cpwait<0>();
        }
        __syncthreads();

        const uint32_t sb_s = sbase + (uint32_t)(c & 1)*STG2;
#pragma unroll
        for (int kk = 0; kk < 32; kk += 16) {
            uint32_t Xa[2][4], Xd[2][4], Xb[4][4];
            const int k16a = (kk >> 3) + (lane >> 4);
            const uint32_t abase = sb_s + aRowOff + ((uint32_t)(k16a ^ srA) << 4);
            const int k16b = (kk >> 3) + ((lane >> 3) & 1);
            const uint32_t bbase = sb_s + bRowOff + ((uint32_t)(k16b ^ srB) << 4);

#pragma unroll
            for (int mt = 0; mt < 2; ++mt) ldm4(abase + mt*16*64, Xa[mt]);
#pragma unroll
            for (int mt = 0; mt < 2; ++mt) ldm4(abase + AL2_O + mt*16*64, Xd[mt]);
#pragma unroll
            for (int ng = 0; ng < 4; ++ng) ldm4(bbase + ng*16*64, Xb[ng]);

#pragma unroll
            for (int mt = 0; mt < 2; ++mt)
#pragma unroll
                for (int nt = 0; nt < 8; ++nt)
                    mma16816h(acc[mt][nt], Xa[mt], &Xb[nt >> 1][(nt & 1)*2]);
#pragma unroll
            for (int mt = 0; mt < 2; ++mt)
#pragma unroll
                for (int nt = 0; nt < 8; ++nt)
                    mma16816h(acc[mt][nt], Xd[mt], &Xb[nt >> 1][(nt & 1)*2]);
        }
        __syncthreads();
    }

    const int g = lane >> 2, tg = lane & 3;
#pragma unroll
    for (int mt = 0; mt < 2; ++mt)
#pragma unroll
        for (int nt = 0; nt < 8; ++nt) {
            const int col = bcol + n0w + nt*8 + tg*2;
            const float b0 = bias[col], b1 = bias[col+1];
#pragma unroll
            for (int half = 0; half < 2; ++half) {
                const int row = brow + m0w + mt*16 + g + half*8;
                if (row < Mstore) {
                    float2 v;
                    v.x = acc[mt][nt][half*2+0] + b0;
                    v.y = acc[mt][nt][half*2+1] + b1;
                    *(float2*)(C + (size_t)row*N + col) = v;
                }
            }
        }
}

// ======== HMMA LSTM step: g = Gx + h@W, gates, c/h update ========
static __device__ __forceinline__ uint32_t soff(int row, int seg) {
    return (uint32_t)(row*128 + ((seg ^ (row & 7)) << 4));
}

__global__ __launch_bounds__(128)
void k_stepT(const float* __restrict__ Gx,
             const __nv_bfloat16* __restrict__ Wh, const __nv_bfloat16* __restrict__ Wl,
             const __nv_bfloat16* __restrict__ hih, const __nv_bfloat16* __restrict__ hil,
             __nv_bfloat16* __restrict__ hoh, __nv_bfloat16* __restrict__ hol,
             float* __restrict__ c,
             __half* __restrict__ Hh, __half* __restrict__ Hl, int ts)
{
    __shared__ __align__(16) unsigned char sm[2*16384 + 4096];
    float* gsm = (float*)(sm + 2*16384);
    const uint32_t sbase = smem_u32(sm);
    const int tid = threadIdx.x, lane = tid & 31, w = tid >> 5;
    const int n0 = blockIdx.x * 8;

    const int lrow = tid >> 2, sp = (tid & 3)*2;
    const uint32_t so0 = soff(lrow, sp);
    const uint32_t so1 = soff(lrow, sp+1);
    const int grow = (lrow >> 3)*HID + n0 + (lrow & 7);
    const __nv_bfloat16* gh_h = hih + lrow*HID + sp*8;
    const __nv_bfloat16* gh_l = hil + lrow*HID + sp*8;
    const __nv_bfloat16* gw_h = Wh + (size_t)grow*HID + sp*8;
    const __nv_bfloat16* gw_l = Wl + (size_t)grow*HID + sp*8;

    float acc[2][4];
#pragma unroll
    for (int i = 0; i < 2; ++i)
#pragma unroll
        for (int q = 0; q < 4; ++q) acc[i][q] = 0.f;

    {
        cpa16(sbase         + so0, gh_h); cpa16(sbase         + so1, gh_h + 8);
        cpa16(sbase + 4096  + so0, gh_l); cpa16(sbase + 4096  + so1, gh_l + 8);
        cpa16(sbase + 8192  + so0, gw_h); cpa16(sbase + 8192  + so1, gw_h + 8);
        cpa16(sbase + 12288 + so0, gw_l); cpa16(sbase + 12288 + so1, gw_l + 8);
        cpcommit();
    }

    const int arow0 = (lane & 15), arow1 = 16 + (lane & 15);
    const int rw = w*8 + (lane & 7), si = lane >> 3;

    for (int cc = 0; cc < 16; ++cc) {
        if (cc + 1 < 16) {
            const uint32_t so = (uint32_t)((cc+1) & 1)*16384;
            const int kc = (cc+1)*64;
            cpa16(sbase + so         + so0, gh_h + kc); cpa16(sbase + so         + so1, gh_h + kc + 8);
            cpa16(sbase + so + 4096  + so0, gh_l + kc); cpa16(sbase + so + 4096  + so1, gh_l + kc + 8);
            cpa16(sbase + so + 8192  + so0, gw_h + kc); cpa16(sbase + so + 8192  + so1, gw_h + kc + 8);
            cpa16(sbase + so + 12288 + so0, gw_l + kc); cpa16(sbase + so + 12288 + so1, gw_l + kc + 8);
            cpcommit();
            cpwait<1>();
        } else {
            cpwait<0>();
        }
        __syncthreads();

        const uint32_t sb = sbase + (uint32_t)(cc & 1)*16384;
        uint32_t ah[4][2][4], al[4][2][4], bh[2][4], bl[2][4];
#pragma unroll
        for (int kb = 0; kb < 2; ++kb) {
            ldm4(sb + 8192  + soff(rw, kb*4 + si), bh[kb]);
            ldm4(sb + 12288 + soff(rw, kb*4 + si), bl[kb]);
        }
#pragma unroll
        for (int q = 0; q < 4; ++q) {
            const int seg = q*2 + (lane >> 4);
            ldm4(sb        + soff(arow0, seg), ah[q][0]);
            ldm4(sb        + soff(arow1, seg), ah[q][1]);
            ldm4(sb + 4096 + soff(arow0, seg), al[q][0]);
            ldm4(sb + 4096 + soff(arow1, seg), al[q][1]);
        }
#pragma unroll
        for (int q = 0; q < 4; ++q)
#pragma unroll
            for (int mt = 0; mt < 2; ++mt)
                mma16816(acc[mt], ah[q][mt], &bh[q >> 1][(q & 1)*2]);
#pragma unroll
        for (int q = 0; q < 4; ++q)
#pragma unroll
            for (int mt = 0; mt < 2; ++mt)
                mma16816(acc[mt], ah[q][mt], &bl[q >> 1][(q & 1)*2]);
#pragma unroll
        for (int q = 0; q < 4; ++q)
#pragma unroll
            for (int mt = 0; mt < 2; ++mt)
                mma16816(acc[mt], al[q][mt], &bh[q >> 1][(q & 1)*2]);
        __syncthreads();
    }

    {
        const int r = lane >> 2, nl0 = (lane & 3)*2;
#pragma unroll
        for (int mt = 0; mt < 2; ++mt) {
            const int b0 = mt*16 + r, b1 = b0 + 8;
            gsm[(w*32 + b0)*8 + nl0]     = acc[mt][0];
            gsm[(w*32 + b0)*8 + nl0 + 1] = acc[mt][1];
            gsm[(w*32 + b1)*8 + nl0]     = acc[mt][2];
            gsm[(w*32 + b1)*8 + nl0 + 1] = acc[mt][3];
        }
    }
    __syncthreads();

#pragma unroll
    for (int rep = 0; rep < 2; ++rep) {
        const int idx = tid + rep*128;
        const int b = idx >> 3, nl = idx & 7;
        const int n = n0 + nl;
        const size_t gxrow = (size_t)(ts*NB + b)*(4*HID);
        float gi = gsm[(0*32 + b)*8 + nl] + Gx[gxrow + 0*HID + n];
        float gf = gsm[(1*32 + b)*8 + nl] + Gx[gxrow + 1*HID + n];
        float go = gsm[(2*32 + b)*8 + nl] + Gx[gxrow + 2*HID + n];
        float gc = gsm[(3*32 + b)*8 + nl] + Gx[gxrow + 3*HID + n];
        float cv = c[b*HID + n];
        float si_ = 1.f / (1.f + expf(-gi));
        float sf  = 1.f / (1.f + expf(-gf));
        float so_ = 1.f / (1.f + expf(-go));
        float c_new = sf * cv + si_ * tanhf(gc);
        float h_new = so_ * c_new;
        c[b*HID + n] = c_new;
        unsigned hh, ll;
        cvt2(h_new, hh, ll);
        ((unsigned short*)hoh)[b*HID + n] = (unsigned short)hh;
        ((unsigned short*)hol)[b*HID + n] = (unsigned short)ll;
        unsigned fh, fl;
        cvt2h(h_new, fh, fl);
        const size_t ho = (size_t)(b*TSTEPS + ts)*HID + n;
        ((unsigned short*)Hh)[ho] = (unsigned short)fh;
        ((unsigned short*)Hl)[ho] = (unsigned short)fl;
    }
}

// ---------------- launch ----------------
extern "C" void kernel_launch(void* const* d_in, const int* in_sizes, int n_in,
                              void* d_out, int out_size)
{
    const int*   rnn   = (const int*)  d_in[0];
    const float* sv    = (const float*)d_in[1];
    const float* embed = (const float*)d_in[2];
    const float* U_w   = (const float*)d_in[3];
    const float* U_b   = (const float*)d_in[4];
    const float* S1_w  = (const float*)d_in[5];
    const float* S1_b  = (const float*)d_in[6];
    const float* V_w   = (const float*)d_in[7];
    const float* W_w   = (const float*)d_in[9];
    const float* P_w   = (const float*)d_in[11];
    const float* P_b   = (const float*)d_in[12];
    float* out = (float*)d_out;

    float *Gx,*c,*b3;
    __nv_bfloat16 *Xh,*Xl,*Uh,*Ul,*Sh,*Sl,*Bh,*Bl,*Wh,*Wl,*hsh,*hsl;
    __half *Hh,*Hl,*P16;
    cudaGetSymbolAddress((void**)&Gx, g_Gx);
    cudaGetSymbolAddress((void**)&c,  g_c);
    cudaGetSymbolAddress((void**)&b3, g_bias3);
    cudaGetSymbolAddress((void**)&Xh, g_Xh); cudaGetSymbolAddress((void**)&Xl, g_Xl);
    cudaGetSymbolAddress((void**)&Uh, g_Uh); cudaGetSymbolAddress((void**)&Ul, g_Ul);
    cudaGetSymbolAddress((void**)&Sh, g_Sh); cudaGetSymbolAddress((void**)&Sl, g_Sl);
    cudaGetSymbolAddress((void**)&Hh, g_Hh); cudaGetSymbolAddress((void**)&Hl, g_Hl);
    cudaGetSymbolAddress((void**)&Bh, g_Bh); cudaGetSymbolAddress((void**)&Bl, g_Bl);
    cudaGetSymbolAddress((void**)&P16, g_P16);
    cudaGetSymbolAddress((void**)&Wh, g_Wh); cudaGetSymbolAddress((void**)&Wl, g_Wl);
    cudaGetSymbolAddress((void**)&hsh, g_hsh); cudaGetSymbolAddress((void**)&hsl, g_hsl);

    // side stream + fork/join events (host objects only; capture-legal)
    cudaStream_t s2;
    cudaStreamCreateWithFlags(&s2, cudaStreamNonBlocking);
    cudaEvent_t evFork, evJoin;
    cudaEventCreateWithFlags(&evFork, cudaEventDisableTiming);
    cudaEventCreateWithFlags(&evJoin, cudaEventDisableTiming);

    k_gather<<<dim3(TSTEPS, NB), 128>>>(rnn, embed, Xh, Xl);
    k_init<<<(NB*HID + 255)/256, 256>>>(sv, (const float*)d_in[8],
                                        (const float*)d_in[10], c, hsh, hsl, b3);

    // fork: P_w fp16 transpose runs concurrently (joined before GEMM4)
    cudaEventRecord(evFork, 0);
    cudaStreamWaitEvent(s2, evFork, 0);
    k_convT1<<<dim3(VOCAB/32, HID/32), 256, 0, s2>>>(P_w, P16, HID, VOCAB);
    cudaEventRecord(evJoin, s2);

    // W^T split for the recurrence
    k_convT<<<dim3((4*HID)/32, HID/32), 256>>>(W_w, Wh, Wl, HID, 4*HID);

    // GEMM1: U = X @ U_w + U_b -> bf16 hi/lo only
    k_convT<<<dim3((4*STY)/32, EMB/32), 256>>>(U_w, Bh, Bl, EMB, 4*STY);
    k_mgemm<<<dim3(MPAD/128, (4*STY)/128), 256>>>(Xh, Xl, Bh, Bl, U_b,
                                                  nullptr, Uh, Ul, 4*STY, EMB, MPAD);
    // GEMM2: S = U @ S1_w + S1_b -> bf16 hi/lo only
    k_convT<<<dim3(STY/32, (4*STY)/32), 256>>>(S1_w, Bh, Bl, 4*STY, STY);
    k_mgemm<<<dim3(MPAD/128, STY/128), 256>>>(Uh, Ul, Bh, Bl, S1_b,
                                              nullptr, Sh, Sl, STY, 4*STY, MPAD);
    // GEMM3: Gx = S @ V_w + (V_b+W_b) -> fp32 only
    k_convT<<<dim3((4*HID)/32, STY/32), 256>>>(V_w, Bh, Bl, STY, 4*HID);
    k_mgemm<<<dim3(MPAD/128, (4*HID)/128), 256>>>(Sh, Sl, Bh, Bl, b3,
                                                  Gx, nullptr, nullptr, 4*HID, STY, MPAD);

    // recurrence: 63 HMMA steps, h split ping-pong (convT1 overlaps here)
    for (int t = 0; t < TSTEPS; t++) {
        const __nv_bfloat16* hih = hsh + (t & 1)*NB*HID;
        const __nv_bfloat16* hil = hsl + (t & 1)*NB*HID;
        __nv_bfloat16* hoh = hsh + (1 - (t & 1))*NB*HID;
        __nv_bfloat16* hol = hsl + (1 - (t & 1))*NB*HID;
        k_stepT<<<(4*HID)/32, 128>>>(Gx, Wh, Wl, hih, hil, hoh, hol, c, Hh, Hl, t);
    }

    // join, then GEMM4 (fp16 2-term): out = H @ P_w + P_b -> fp32 d_out
    cudaStreamWaitEvent(0, evJoin, 0);
    k_mgemm2<<<dim3(MPAD/128, VOCAB/128), 256>>>(Hh, Hl, P16, P_b,
                                                 out, VOCAB, HID, MROWS);
}

// round 14
// speedup vs baseline: 2.0585x; 1.0109x over previous
#include <cuda_runtime.h>
#include <cuda_bf16.h>
#include <cuda_fp16.h>
#include <stdint.h>
#include <math.h>

#define EMB   512
#define VOCAB 32000
#define HID   1024
#define STY   512
#define NB    32
#define SEQ   64
#define TSTEPS 63
#define MROWS (TSTEPS*NB)   /* 2016 */
#define MPAD  2048

// ---------------- device scratch (zero-initialized .bss) ----------------
__device__ float g_Gx[(size_t)MPAD*4*HID];
__device__ float g_bias3[4*HID];
__device__ unsigned g_barc[64];
__device__ __nv_bfloat16 g_Xh[MPAD*EMB],     g_Xl[MPAD*EMB];
__device__ __nv_bfloat16 g_Uh[MPAD*4*STY],   g_Ul[MPAD*4*STY];
__device__ __nv_bfloat16 g_Sh[MPAD*STY],     g_Sl[MPAD*STY];
__device__ __half        g_Hh[MPAD*HID],     g_Hl[MPAD*HID];   // fp16 split; rows>=2016 stay 0
__device__ __nv_bfloat16 g_Bh[(size_t)VOCAB*1024], g_Bl[(size_t)VOCAB*1024];
__device__ __half        g_P16[(size_t)VOCAB*1024];            // fp16 P_w^T
__device__ __nv_bfloat16 g_Wh[(size_t)4*HID*HID], g_Wl[(size_t)4*HID*HID]; // W^T split
__device__ __nv_bfloat16 g_hsh[2*NB*HID], g_hsl[2*NB*HID];                 // h ping-pong

// ---------------- helpers ----------------
static __device__ __forceinline__ uint32_t smem_u32(const void* p) {
    uint32_t a;
    asm("{ .reg .u64 t; cvta.to.shared.u64 t, %1; cvt.u32.u64 %0, t; }" : "=r"(a) : "l"(p));
    return a;
}
static __device__ __forceinline__ void cvt2(float f, unsigned& h, unsigned& l) {
    __nv_bfloat16 hb = __float2bfloat16_rn(f);
    float rem = f - __bfloat162float(hb);
    __nv_bfloat16 lb = __float2bfloat16_rn(rem);
    h = (unsigned)__bfloat16_as_ushort(hb);
    l = (unsigned)__bfloat16_as_ushort(lb);
}
static __device__ __forceinline__ void cvt2h(float f, unsigned& h, unsigned& l) {
    __half hb = __float2half_rn(f);
    float rem = f - __half2float(hb);
    __half lb = __float2half_rn(rem);
    h = (unsigned)__half_as_ushort(hb);
    l = (unsigned)__half_as_ushort(lb);
}
static __device__ __forceinline__ void ldm4(uint32_t addr, uint32_t* r) {
    asm volatile("ldmatrix.sync.aligned.m8n8.x4.shared.b16 {%0,%1,%2,%3}, [%4];"
        : "=r"(r[0]), "=r"(r[1]), "=r"(r[2]), "=r"(r[3]) : "r"(addr));
}
static __device__ __forceinline__ void mma16816(float* d, const uint32_t* a,
                                                const uint32_t* b) {
    asm volatile("mma.sync.aligned.m16n8k16.row.col.f32.bf16.bf16.f32 "
        "{%0,%1,%2,%3},{%4,%5,%6,%7},{%8,%9},{%0,%1,%2,%3};"
        : "+f"(d[0]), "+f"(d[1]), "+f"(d[2]), "+f"(d[3])
        : "r"(a[0]), "r"(a[1]), "r"(a[2]), "r"(a[3]), "r"(b[0]), "r"(b[1]));
}
static __device__ __forceinline__ void mma16816h(float* d, const uint32_t* a,
                                                 const uint32_t* b) {
    asm volatile("mma.sync.aligned.m16n8k16.row.col.f32.f16.f16.f32 "
        "{%0,%1,%2,%3},{%4,%5,%6,%7},{%8,%9},{%0,%1,%2,%3};"
        : "+f"(d[0]), "+f"(d[1]), "+f"(d[2]), "+f"(d[3])
        : "r"(a[0]), "r"(a[1]), "r"(a[2]), "r"(a[3]), "r"(b[0]), "r"(b[1]));
}
static __device__ __forceinline__ void cpa16(uint32_t s, const void* g) {
    asm volatile("cp.async.cg.shared.global [%0], [%1], 16;" :: "r"(s), "l"(g));
}
static __device__ __forceinline__ void cpcommit() {
    asm volatile("cp.async.commit_group;" ::: "memory");
}
template<int n> static __device__ __forceinline__ void cpwait() {
    asm volatile("cp.async.wait_group %0;" :: "n"(n) : "memory");
}

// ---------------- gather ----------------
__global__ void k_gather(const int* __restrict__ idx, const float* __restrict__ embed,
                         __nv_bfloat16* __restrict__ Xh, __nv_bfloat16* __restrict__ Xl)
{
    int t = blockIdx.x, b = blockIdx.y;
    int tok = idx[b*SEQ + t];
    float4 v = ((const float4*)(embed + (size_t)tok*EMB))[threadIdx.x];
    unsigned h0,l0,h1,l1,h2,l2,h3,l3;
    cvt2(v.x,h0,l0); cvt2(v.y,h1,l1); cvt2(v.z,h2,l2); cvt2(v.w,h3,l3);
    uint2 hv; hv.x = h0|(h1<<16); hv.y = h2|(h3<<16);
    uint2 lv; lv.x = l0|(l1<<16); lv.y = l2|(l3<<16);
    size_t o = (size_t)(t*NB + b)*EMB + threadIdx.x*4;
    *(uint2*)(Xh + o) = hv;
    *(uint2*)(Xl + o) = lv;
}

// ---------------- init: h0 split, combined bias, barrier slots ----------------
__global__ void k_init(const float* __restrict__ sv, const float* __restrict__ Vb,
                       const float* __restrict__ Wb,
                       __nv_bfloat16* __restrict__ hsh, __nv_bfloat16* __restrict__ hsl,
                       float* __restrict__ b3, unsigned* __restrict__ barc)
{
    int i = blockIdx.x*blockDim.x + threadIdx.x;
    if (i < NB*HID) {
        float v = sv[i];
        unsigned h, l; cvt2(v, h, l);
        ((unsigned short*)hsh)[i] = (unsigned short)h;
        ((unsigned short*)hsl)[i] = (unsigned short)l;
    }
    if (i < 4*HID)  b3[i] = Vb[i] + Wb[i];
    if (i < 64)     barc[i] = 0u;
}

// ---------------- convert + transpose: fp32 [K][N] -> bf16 hi/lo [N][K] ----------------
__global__ void k_convT(const float* __restrict__ in, __nv_bfloat16* __restrict__ hiT,
                        __nv_bfloat16* __restrict__ loT, int K, int N)
{
    __shared__ float s[32][33];
    const int k0 = blockIdx.y*32, n0 = blockIdx.x*32;
    const int tid = threadIdx.x;
    {
        int r = tid>>3, c4 = (tid&7)*4;
        float4 v = *(const float4*)(in + (size_t)(k0+r)*N + n0 + c4);
        s[r][c4+0]=v.x; s[r][c4+1]=v.y; s[r][c4+2]=v.z; s[r][c4+3]=v.w;
    }
    __syncthreads();
    {
        int n = tid>>3, kq = (tid&7)*4;
        unsigned hh[4], ll[4];
#pragma unroll
        for (int i = 0; i < 4; ++i) cvt2(s[kq+i][n], hh[i], ll[i]);
        uint2 hv; hv.x = hh[0]|(hh[1]<<16); hv.y = hh[2]|(hh[3]<<16);
        uint2 lv; lv.x = ll[0]|(ll[1]<<16); lv.y = ll[2]|(ll[3]<<16);
        size_t o = ((size_t)(n0+n)*K + k0 + kq);
        *(uint2*)(hiT + o) = hv;
        *(uint2*)(loT + o) = lv;
    }
}

// ---------------- convert + transpose: fp32 [K][N] -> fp16 [N][K] (single) ----------------
__global__ void k_convT1(const float* __restrict__ in, __half* __restrict__ hiT,
                         int K, int N)
{
    __shared__ float s[32][33];
    const int k0 = blockIdx.y*32, n0 = blockIdx.x*32;
    const int tid = threadIdx.x;
    {
        int r = tid>>3, c4 = (tid&7)*4;
        float4 v = *(const float4*)(in + (size_t)(k0+r)*N + n0 + c4);
        s[r][c4+0]=v.x; s[r][c4+1]=v.y; s[r][c4+2]=v.z; s[r][c4+3]=v.w;
    }
    __syncthreads();
    {
        int n = tid>>3, kq = (tid&7)*4;
        unsigned hh[4];
#pragma unroll
        for (int i = 0; i < 4; ++i)
            hh[i] = (unsigned)__half_as_ushort(__float2half_rn(s[kq+i][n]));
        uint2 hv; hv.x = hh[0]|(hh[1]<<16); hv.y = hh[2]|(hh[3]<<16);
        *(uint2*)(hiT + ((size_t)(n0+n)*K + k0 + kq)) = hv;
    }
}

// ======== bf16 3-term HMMA GEMM: 128x128 block, 8 warps of 32x64, Kc=32 ========
#define STG   32768
#define AL_O  8192
#define BH_O  16384
#define BL_O  24576
static __device__ __forceinline__ uint32_t swz64(int row, int k16) {
    return (uint32_t)(row*64 + ((k16 ^ ((row>>1)&3))<<4));
}

__global__ __launch_bounds__(256, 2)
void k_mgemm(const __nv_bfloat16* __restrict__ Ah, const __nv_bfloat16* __restrict__ Al,
             const __nv_bfloat16* __restrict__ Bh, const __nv_bfloat16* __restrict__ Bl,
             const float* __restrict__ bias, float* __restrict__ C,
             __nv_bfloat16* __restrict__ Chi, __nv_bfloat16* __restrict__ Clo,
             int N, int K, int Mstore)
{
    __shared__ __align__(16) unsigned char sm[2*STG];
    const uint32_t sbase = smem_u32(sm);

    const int tid = threadIdx.x, lane = tid & 31, wid = tid >> 5;
    const int brow = blockIdx.x*128, bcol = blockIdx.y*128;

    const int lrow = tid >> 1, ak = (tid & 1)*2;
    const __nv_bfloat16* gAh_t = Ah + (size_t)(brow + lrow)*K + ak*8;
    const __nv_bfloat16* gAl_t = Al + (size_t)(brow + lrow)*K + ak*8;
    const __nv_bfloat16* gBh_t = Bh + (size_t)(bcol + lrow)*K + ak*8;
    const __nv_bfloat16* gBl_t = Bl + (size_t)(bcol + lrow)*K + ak*8;
    const uint32_t cs0 = sbase + swz64(lrow, ak);
    const uint32_t cs1 = sbase + swz64(lrow, ak+1);

    const int m0w = (wid & 3)*32, n0w = (wid >> 2)*64;
    const int arL = lane & 15;
    const int srA = (arL >> 1) & 3;
    const int brL = (lane & 7) + ((lane >> 4) << 3);
    const int srB = ((lane & 7) >> 1) & 3;
    const uint32_t aRowOff = (uint32_t)(m0w + arL)*64;
    const uint32_t bRowOff = (uint32_t)(n0w + brL)*64 + BH_O;

    float acc[2][8][4];
#pragma unroll
    for (int i = 0; i < 2; ++i)
#pragma unroll
        for (int j = 0; j < 8; ++j)
#pragma unroll
            for (int q = 0; q < 4; ++q) acc[i][j][q] = 0.f;

    const int nch = K >> 5;

    {
        cpa16(cs0, gAh_t);            cpa16(cs1, gAh_t + 8);
        cpa16(cs0 + AL_O, gAl_t);     cpa16(cs1 + AL_O, gAl_t + 8);
        cpa16(cs0 + BH_O, gBh_t);     cpa16(cs1 + BH_O, gBh_t + 8);
        cpa16(cs0 + BL_O, gBl_t);     cpa16(cs1 + BL_O, gBl_t + 8);
        cpcommit();
    }

    for (int c = 0; c < nch; ++c) {
        if (c + 1 < nch) {
            const uint32_t so = (uint32_t)((c+1) & 1)*STG;
            const int kc = (c+1)*32;
            cpa16(cs0 + so, gAh_t + kc);        cpa16(cs1 + so, gAh_t + kc + 8);
            cpa16(cs0 + AL_O + so, gAl_t + kc); cpa16(cs1 + AL_O + so, gAl_t + kc + 8);
            cpa16(cs0 + BH_O + so, gBh_t + kc); cpa16(cs1 + BH_O + so, gBh_t + kc + 8);
            cpa16(cs0 + BL_O + so, gBl_t + kc); cpa16(cs1 + BL_O + so, gBl_t + kc + 8);
            cpcommit();
            cpwait<1>();
        } else {
            cpwait<0>();
        }
        __syncthreads();

        const uint32_t sb_s = sbase + (uint32_t)(c & 1)*STG;
#pragma unroll
        for (int kk = 0; kk < 32; kk += 16) {
            uint32_t Xa[2][4], Xb[4][4], Xc[4][4];
            const int k16a = (kk >> 3) + (lane >> 4);
            const uint32_t abase = sb_s + aRowOff + ((uint32_t)(k16a ^ srA) << 4);
            const int k16b = (kk >> 3) + ((lane >> 3) & 1);
            const uint32_t bbase = sb_s + bRowOff + ((uint32_t)(k16b ^ srB) << 4);

#pragma unroll
            for (int mt = 0; mt < 2; ++mt) ldm4(abase + mt*16*64, Xa[mt]);
#pragma unroll
            for (int ng = 0; ng < 4; ++ng) ldm4(bbase + ng*16*64, Xb[ng]);
#pragma unroll
            for (int mt = 0; mt < 2; ++mt)
#pragma unroll
                for (int nt = 0; nt < 8; ++nt)
                    mma16816(acc[mt][nt], Xa[mt], &Xb[nt >> 1][(nt & 1)*2]);

#pragma unroll
            for (int ng = 0; ng < 4; ++ng) ldm4(bbase + (BL_O - BH_O) + ng*16*64, Xc[ng]);
#pragma unroll
            for (int mt = 0; mt < 2; ++mt)
#pragma unroll
                for (int nt = 0; nt < 8; ++nt)
                    mma16816(acc[mt][nt], Xa[mt], &Xc[nt >> 1][(nt & 1)*2]);

#pragma unroll
            for (int mt = 0; mt < 2; ++mt) ldm4(abase + AL_O + mt*16*64, Xc[mt]);
#pragma unroll
            for (int mt = 0; mt < 2; ++mt)
#pragma unroll
                for (int nt = 0; nt < 8; ++nt)
                    mma16816(acc[mt][nt], Xc[mt], &Xb[nt >> 1][(nt & 1)*2]);
        }
        __syncthreads();
    }

    const int g = lane >> 2, tg = lane & 3;
#pragma unroll
    for (int mt = 0; mt < 2; ++mt)
#pragma unroll
        for (int nt = 0; nt < 8; ++nt) {
            const int col = bcol + n0w + nt*8 + tg*2;
            const float b0 = bias[col], b1 = bias[col+1];
#pragma unroll
            for (int half = 0; half < 2; ++half) {
                const int row = brow + m0w + mt*16 + g + half*8;
                if (row < Mstore) {
                    float o0 = acc[mt][nt][half*2+0] + b0;
                    float o1 = acc[mt][nt][half*2+1] + b1;
                    const size_t o = (size_t)row*N + col;
                    if (C) { float2 v; v.x = o0; v.y = o1; *(float2*)(C + o) = v; }
                    if (Chi) {
                        unsigned h0,l0,h1,l1;
                        cvt2(o0,h0,l0); cvt2(o1,h1,l1);
                        *(uint32_t*)(Chi + o) = h0 | (h1<<16);
                        *(uint32_t*)(Clo + o) = l0 | (l1<<16);
                    }
                }
            }
        }
}

// ======== fp16 A-split 2-term GEMM (vocab projection) ========
#define STG2  24576
#define AL2_O 8192
#define BH2_O 16384
__global__ __launch_bounds__(256, 2)
void k_mgemm2(const __half* __restrict__ Ah, const __half* __restrict__ Al,
              const __half* __restrict__ Bh,
              const float* __restrict__ bias, float* __restrict__ C,
              int N, int K, int Mstore)
{
    __shared__ __align__(16) unsigned char sm[2*STG2];
    const uint32_t sbase = smem_u32(sm);

    const int tid = threadIdx.x, lane = tid & 31, wid = tid >> 5;
    const int brow = blockIdx.x*128, bcol = blockIdx.y*128;

    const int lrow = tid >> 1, ak = (tid & 1)*2;
    const __half* gAh_t = Ah + (size_t)(brow + lrow)*K + ak*8;
    const __half* gAl_t = Al + (size_t)(brow + lrow)*K + ak*8;
    const __half* gBh_t = Bh + (size_t)(bcol + lrow)*K + ak*8;
    const uint32_t cs0 = sbase + swz64(lrow, ak);
    const uint32_t cs1 = sbase + swz64(lrow, ak+1);

    const int m0w = (wid & 3)*32, n0w = (wid >> 2)*64;
    const int arL = lane & 15;
    const int srA = (arL >> 1) & 3;
    const int brL = (lane & 7) + ((lane >> 4) << 3);
    const int srB = ((lane & 7) >> 1) & 3;
    const uint32_t aRowOff = (uint32_t)(m0w + arL)*64;
    const uint32_t bRowOff = (uint32_t)(n0w + brL)*64 + BH2_O;

    float acc[2][8][4];
#pragma unroll
    for (int i = 0; i < 2; ++i)
#pragma unroll
        for (int j = 0; j < 8; ++j)
#pragma unroll
            for (int q = 0; q < 4; ++q) acc[i][j][q] = 0.f;

    const int nch = K >> 5;

    {
        cpa16(cs0, gAh_t);             cpa16(cs1, gAh_t + 8);
        cpa16(cs0 + AL2_O, gAl_t);     cpa16(cs1 + AL2_O, gAl_t + 8);
        cpa16(cs0 + BH2_O, gBh_t);     cpa16(cs1 + BH2_O, gBh_t + 8);
        cpcommit();
    }

    for (int c = 0; c < nch; ++c) {
        if (c + 1 < nch) {
            const uint32_t so = (uint32_t)((c+1) & 1)*STG2;
            const int kc = (c+1)*32;
            cpa16(cs0 + so, gAh_t + kc);         cpa16(cs1 + so, gAh_t + kc + 8);
            cpa16(cs0 + AL2_O + so, gAl_t + kc); cpa16(cs1 + AL2_O + so, gAl_t + kc + 8);
            cpa16(cs0 + BH2_O + so, gBh_t + kc); cpa16(cs1 + BH2_O + so, gBh_t + kc + 8);
            cpcommit();
            cpwait<1>();
        } else {
            cpwait<0>();
        }
        __syncthreads();

        const uint32_t sb_s = sbase + (uint32_t)(c & 1)*STG2;
#pragma unroll
        for (int kk = 0; kk < 32; kk += 16) {
            uint32_t Xa[2][4], Xd[2][4], Xb[4][4];
            const int k16a = (kk >> 3) + (lane >> 4);
            const uint32_t abase = sb_s + aRowOff + ((uint32_t)(k16a ^ srA) << 4);
            const int k16b = (kk >> 3) + ((lane >> 3) & 1);
            const uint32_t bbase = sb_s + bRowOff + ((uint32_t)(k16b ^ srB) << 4);

#pragma unroll
            for (int mt = 0; mt < 2; ++mt) ldm4(abase + mt*16*64, Xa[mt]);
#pragma unroll
            for (int mt = 0; mt < 2; ++mt) ldm4(abase + AL2_O + mt*16*64, Xd[mt]);
#pragma unroll
            for (int ng = 0; ng < 4; ++ng) ldm4(bbase + ng*16*64, Xb[ng]);

#pragma unroll
            for (int mt = 0; mt < 2; ++mt)
#pragma unroll
                for (int nt = 0; nt < 8; ++nt)
                    mma16816h(acc[mt][nt], Xa[mt], &Xb[nt >> 1][(nt & 1)*2]);
#pragma unroll
            for (int mt = 0; mt < 2; ++mt)
#pragma unroll
                for (int nt = 0; nt < 8; ++nt)
                    mma16816h(acc[mt][nt], Xd[mt], &Xb[nt >> 1][(nt & 1)*2]);
        }
        __syncthreads();
    }

    const int g = lane >> 2, tg = lane & 3;
#pragma unroll
    for (int mt = 0; mt < 2; ++mt)
#pragma unroll
        for (int nt = 0; nt < 8; ++nt) {
            const int col = bcol + n0w + nt*8 + tg*2;
            const float b0 = bias[col], b1 = bias[col+1];
#pragma unroll
            for (int half = 0; half < 2; ++half) {
                const int row = brow + m0w + mt*16 + g + half*8;
                if (row < Mstore) {
                    float2 v;
                    v.x = acc[mt][nt][half*2+0] + b0;
                    v.y = acc[mt][nt][half*2+1] + b1;
                    *(float2*)(C + (size_t)row*N + col) = v;
                }
            }
        }
}

// ======== persistent HMMA recurrence: all 63 steps in one kernel ========
// 128 CTAs x 128 thr, one CTA per 8 n-values (x4 gates). W resident in smem.
// smem: Wh 64K | Wl 64K | h stages 2x8K | gate buf 4K = 148K dynamic.
#define WH_O  0
#define WL_O  65536
#define HS_O  131072
#define GS_O  147456
#define REC_SMEM 151552
static __device__ __forceinline__ uint32_t soff(int row, int seg) {
    return (uint32_t)(row*128 + ((seg ^ (row & 7)) << 4));
}

__global__ __launch_bounds__(128)
void k_srec(const float* __restrict__ Gx,
            const __nv_bfloat16* __restrict__ Wh, const __nv_bfloat16* __restrict__ Wl,
            __nv_bfloat16* __restrict__ hsh, __nv_bfloat16* __restrict__ hsl,
            const float* __restrict__ sv,
            __half* __restrict__ Hh, __half* __restrict__ Hl,
            unsigned* __restrict__ barc)
{
    extern __shared__ __align__(16) unsigned char sm[];
    float* gsm = (float*)(sm + GS_O);
    const uint32_t sbase = smem_u32(sm);
    const int tid = threadIdx.x, lane = tid & 31, w = tid >> 5;
    const int n0 = blockIdx.x * 8;

    // loader assignment: thread -> row 0..31, seg pair
    const int lrow = tid >> 2, sp = (tid & 3)*2;
    const uint32_t lo0 = soff(lrow, sp);
    const uint32_t lo1 = soff(lrow, sp+1);
    const int grow = (lrow >> 3)*HID + n0 + (lrow & 7);
    const __nv_bfloat16* gw_h = Wh + (size_t)grow*HID + sp*8;
    const __nv_bfloat16* gw_l = Wl + (size_t)grow*HID + sp*8;

    // ---- preload W (all 16 chunks) into smem ----
#pragma unroll
    for (int cc = 0; cc < 16; ++cc) {
        const uint32_t wb = (uint32_t)cc*4096;
        cpa16(sbase + WH_O + wb + lo0, gw_h + cc*64);
        cpa16(sbase + WH_O + wb + lo1, gw_h + cc*64 + 8);
        cpa16(sbase + WL_O + wb + lo0, gw_l + cc*64);
        cpa16(sbase + WL_O + wb + lo1, gw_l + cc*64 + 8);
    }
    cpcommit();

    // c in registers: thread owns (b0 = tid>>3, n0+(tid&7)) and (b0+16, same n)
    const int cb = tid >> 3, cn = n0 + (tid & 7);
    float creg0 = sv[cb*HID + cn];
    float creg1 = sv[(cb+16)*HID + cn];

    cpwait<0>();
    __syncthreads();

    // ldsm addressing
    const int arow0 = (lane & 15), arow1 = 16 + (lane & 15);
    const int rw = w*8 + (lane & 7), si = lane >> 3;

    for (int ts = 0; ts < TSTEPS; ++ts) {
        const __nv_bfloat16* hih = hsh + (ts & 1)*NB*HID;
        const __nv_bfloat16* hil = hsl + (ts & 1)*NB*HID;
        __nv_bfloat16* hoh = hsh + (1 - (ts & 1))*NB*HID;
        __nv_bfloat16* hol = hsl + (1 - (ts & 1))*NB*HID;
        const __nv_bfloat16* gh_h = hih + lrow*HID + sp*8;
        const __nv_bfloat16* gh_l = hil + lrow*HID + sp*8;

        float acc[2][4];
#pragma unroll
        for (int i = 0; i < 2; ++i)
#pragma unroll
            for (int q = 0; q < 4; ++q) acc[i][q] = 0.f;

        // prologue: h chunk 0 -> stage 0
        cpa16(sbase + HS_O + lo0, gh_h);            cpa16(sbase + HS_O + lo1, gh_h + 8);
        cpa16(sbase + HS_O + 4096 + lo0, gh_l);     cpa16(sbase + HS_O + 4096 + lo1, gh_l + 8);
        cpcommit();

        for (int cc = 0; cc < 16; ++cc) {
            if (cc + 1 < 16) {
                const uint32_t so = HS_O + (uint32_t)((cc+1) & 1)*8192;
                const int kc = (cc+1)*64;
                cpa16(sbase + so + lo0, gh_h + kc);        cpa16(sbase + so + lo1, gh_h + kc + 8);
                cpa16(sbase + so + 4096 + lo0, gh_l + kc); cpa16(sbase + so + 4096 + lo1, gh_l + kc + 8);
                cpcommit();
                cpwait<1>();
            } else {
                cpwait<0>();
            }
            __syncthreads();

            const uint32_t hb = sbase + HS_O + (uint32_t)(cc & 1)*8192;
            const uint32_t wb = (uint32_t)cc*4096;
            uint32_t ah[4][2][4], al[4][2][4], bh[2][4], bl[2][4];
#pragma unroll
            for (int kb = 0; kb < 2; ++kb) {
                ldm4(sbase + WH_O + wb + soff(rw, kb*4 + si), bh[kb]);
                ldm4(sbase + WL_O + wb + soff(rw, kb*4 + si), bl[kb]);
            }
#pragma unroll
            for (int q = 0; q < 4; ++q) {
                const int seg = q*2 + (lane >> 4);
                ldm4(hb        + soff(arow0, seg), ah[q][0]);
                ldm4(hb        + soff(arow1, seg), ah[q][1]);
                ldm4(hb + 4096 + soff(arow0, seg), al[q][0]);
                ldm4(hb + 4096 + soff(arow1, seg), al[q][1]);
            }
#pragma unroll
            for (int q = 0; q < 4; ++q)
#pragma unroll
                for (int mt = 0; mt < 2; ++mt)
                    mma16816(acc[mt], ah[q][mt], &bh[q >> 1][(q & 1)*2]);
#pragma unroll
            for (int q = 0; q < 4; ++q)
#pragma unroll
                for (int mt = 0; mt < 2; ++mt)
                    mma16816(acc[mt], ah[q][mt], &bl[q >> 1][(q & 1)*2]);
#pragma unroll
            for (int q = 0; q < 4; ++q)
#pragma unroll
                for (int mt = 0; mt < 2; ++mt)
                    mma16816(acc[mt], al[q][mt], &bh[q >> 1][(q & 1)*2]);
            __syncthreads();
        }

        // store gate results to gsm[gate][b][nl]
        {
            const int r = lane >> 2, nl0 = (lane & 3)*2;
#pragma unroll
            for (int mt = 0; mt < 2; ++mt) {
                const int b0 = mt*16 + r, b1 = b0 + 8;
                gsm[(w*32 + b0)*8 + nl0]     = acc[mt][0];
                gsm[(w*32 + b0)*8 + nl0 + 1] = acc[mt][1];
                gsm[(w*32 + b1)*8 + nl0]     = acc[mt][2];
                gsm[(w*32 + b1)*8 + nl0 + 1] = acc[mt][3];
            }
        }
        __syncthreads();

        // gate nonlinearity + c/h update (c in registers)
#pragma unroll
        for (int rep = 0; rep < 2; ++rep) {
            const int b = cb + rep*16;
            const int nl = tid & 7;
            const int n = cn;
            const size_t gxrow = (size_t)(ts*NB + b)*(4*HID);
            float gi = gsm[(0*32 + b)*8 + nl] + Gx[gxrow + 0*HID + n];
            float gf = gsm[(1*32 + b)*8 + nl] + Gx[gxrow + 1*HID + n];
            float go = gsm[(2*32 + b)*8 + nl] + Gx[gxrow + 2*HID + n];
            float gc = gsm[(3*32 + b)*8 + nl] + Gx[gxrow + 3*HID + n];
            float cv = rep ? creg1 : creg0;
            float si_ = 1.f / (1.f + expf(-gi));
            float sf  = 1.f / (1.f + expf(-gf));
            float so_ = 1.f / (1.f + expf(-go));
            float c_new = sf * cv + si_ * tanhf(gc);
            float h_new = so_ * c_new;
            if (rep) creg1 = c_new; else creg0 = c_new;
            unsigned hh, ll;
            cvt2(h_new, hh, ll);
            ((unsigned short*)hoh)[b*HID + n] = (unsigned short)hh;
            ((unsigned short*)hol)[b*HID + n] = (unsigned short)ll;
            unsigned fh, fl;
            cvt2h(h_new, fh, fl);
            const size_t ho = (size_t)(b*TSTEPS + ts)*HID + n;
            ((unsigned short*)Hh)[ho] = (unsigned short)fh;
            ((unsigned short*)Hl)[ho] = (unsigned short)fl;
        }

        // grid-wide barrier between steps
        if (ts < TSTEPS - 1) {
            __threadfence();
            __syncthreads();
            if (tid == 0) {
                atomicAdd(&barc[ts], 1u);
                while (*(volatile unsigned*)&barc[ts] < 128u) { }
                __threadfence();
            }
            __syncthreads();
        }
    }
}

// ---------------- launch ----------------
extern "C" void kernel_launch(void* const* d_in, const int* in_sizes, int n_in,
                              void* d_out, int out_size)
{
    const int*   rnn   = (const int*)  d_in[0];
    const float* sv    = (const float*)d_in[1];
    const float* embed = (const float*)d_in[2];
    const float* U_w   = (const float*)d_in[3];
    const float* U_b   = (const float*)d_in[4];
    const float* S1_w  = (const float*)d_in[5];
    const float* S1_b  = (const float*)d_in[6];
    const float* V_w   = (const float*)d_in[7];
    const float* W_w   = (const float*)d_in[9];
    const float* P_w   = (const float*)d_in[11];
    const float* P_b   = (const float*)d_in[12];
    float* out = (float*)d_out;

    float *Gx,*b3;
    unsigned* barc;
    __nv_bfloat16 *Xh,*Xl,*Uh,*Ul,*Sh,*Sl,*Bh,*Bl,*Wh,*Wl,*hsh,*hsl;
    __half *Hh,*Hl,*P16;
    cudaGetSymbolAddress((void**)&Gx, g_Gx);
    cudaGetSymbolAddress((void**)&b3, g_bias3);
    cudaGetSymbolAddress((void**)&barc, g_barc);
    cudaGetSymbolAddress((void**)&Xh, g_Xh); cudaGetSymbolAddress((void**)&Xl, g_Xl);
    cudaGetSymbolAddress((void**)&Uh, g_Uh); cudaGetSymbolAddress((void**)&Ul, g_Ul);
    cudaGetSymbolAddress((void**)&Sh, g_Sh); cudaGetSymbolAddress((void**)&Sl, g_Sl);
    cudaGetSymbolAddress((void**)&Hh, g_Hh); cudaGetSymbolAddress((void**)&Hl, g_Hl);
    cudaGetSymbolAddress((void**)&Bh, g_Bh); cudaGetSymbolAddress((void**)&Bl, g_Bl);
    cudaGetSymbolAddress((void**)&P16, g_P16);
    cudaGetSymbolAddress((void**)&Wh, g_Wh); cudaGetSymbolAddress((void**)&Wl, g_Wl);
    cudaGetSymbolAddress((void**)&hsh, g_hsh); cudaGetSymbolAddress((void**)&hsl, g_hsl);

    cudaFuncSetAttribute(k_srec, cudaFuncAttributeMaxDynamicSharedMemorySize, REC_SMEM);

    // side stream + fork/join events
    cudaStream_t s2;
    cudaStreamCreateWithFlags(&s2, cudaStreamNonBlocking);
    cudaEvent_t evFork, evJoin;
    cudaEventCreateWithFlags(&evFork, cudaEventDisableTiming);
    cudaEventCreateWithFlags(&evJoin, cudaEventDisableTiming);

    k_gather<<<dim3(TSTEPS, NB), 128>>>(rnn, embed, Xh, Xl);
    k_init<<<(NB*HID + 255)/256, 256>>>(sv, (const float*)d_in[8],
                                        (const float*)d_in[10], hsh, hsl, b3, barc);

    // fork: P_w fp16 transpose runs concurrently (joined before GEMM4)
    cudaEventRecord(evFork, 0);
    cudaStreamWaitEvent(s2, evFork, 0);
    k_convT1<<<dim3(VOCAB/32, HID/32), 256, 0, s2>>>(P_w, P16, HID, VOCAB);
    cudaEventRecord(evJoin, s2);

    // W^T split for the recurrence
    k_convT<<<dim3((4*HID)/32, HID/32), 256>>>(W_w, Wh, Wl, HID, 4*HID);

    // GEMM1: U = X @ U_w + U_b -> bf16 hi/lo only
    k_convT<<<dim3((4*STY)/32, EMB/32), 256>>>(U_w, Bh, Bl, EMB, 4*STY);
    k_mgemm<<<dim3(MPAD/128, (4*STY)/128), 256>>>(Xh, Xl, Bh, Bl, U_b,
                                                  nullptr, Uh, Ul, 4*STY, EMB, MPAD);
    // GEMM2: S = U @ S1_w + S1_b -> bf16 hi/lo only
    k_convT<<<dim3(STY/32, (4*STY)/32), 256>>>(S1_w, Bh, Bl, 4*STY, STY);
    k_mgemm<<<dim3(MPAD/128, STY/128), 256>>>(Uh, Ul, Bh, Bl, S1_b,
                                              nullptr, Sh, Sl, STY, 4*STY, MPAD);
    // GEMM3: Gx = S @ V_w + (V_b+W_b) -> fp32 only
    k_convT<<<dim3((4*HID)/32, STY/32), 256>>>(V_w, Bh, Bl, STY, 4*HID);
    k_mgemm<<<dim3(MPAD/128, (4*HID)/128), 256>>>(Sh, Sl, Bh, Bl, b3,
                                                  Gx, nullptr, nullptr, 4*HID, STY, MPAD);

    // recurrence: single persistent kernel, all 63 steps
    k_srec<<<(4*HID)/32, 128, REC_SMEM>>>(Gx, Wh, Wl, hsh, hsl, sv, Hh, Hl, barc);

    // join, then GEMM4 (fp16 2-term): out = H @ P_w + P_b -> fp32 d_out
    cudaStreamWaitEvent(0, evJoin, 0);
    k_mgemm2<<<dim3(MPAD/128, VOCAB/128), 256>>>(Hh, Hl, P16, P_b,
                                                 out, VOCAB, HID, MROWS);
}

// round 15
// speedup vs baseline: 2.4991x; 1.2140x over previous
#include <cuda_runtime.h>
#include <cuda_bf16.h>
#include <cuda_fp16.h>
#include <stdint.h>
#include <math.h>

#define EMB   512
#define VOCAB 32000
#define HID   1024
#define STY   512
#define NB    32
#define SEQ   64
#define TSTEPS 63
#define MROWS (TSTEPS*NB)   /* 2016 */
#define MPAD  2048

// ---------------- device scratch (zero-initialized .bss) ----------------
__device__ float g_Gx[(size_t)MPAD*4*HID];
__device__ float g_bias3[4*HID];
__device__ unsigned g_barc[64];
__device__ __nv_bfloat16 g_Xh[MPAD*EMB],     g_Xl[MPAD*EMB];
__device__ __nv_bfloat16 g_Uh[MPAD*4*STY],   g_Ul[MPAD*4*STY];
__device__ __nv_bfloat16 g_Sh[MPAD*STY],     g_Sl[MPAD*STY];
__device__ __half        g_Hh[MPAD*HID];                        // fp16 H; rows>=2016 stay 0
__device__ __nv_bfloat16 g_Bh[(size_t)VOCAB*1024], g_Bl[(size_t)VOCAB*1024];
__device__ __half        g_P16[(size_t)VOCAB*1024];             // fp16 P_w^T
__device__ __nv_bfloat16 g_Wh[(size_t)4*HID*HID], g_Wl[(size_t)4*HID*HID]; // W^T split
__device__ __nv_bfloat16 g_hsh[2*NB*HID], g_hsl[2*NB*HID];                 // h ping-pong

// ---------------- helpers ----------------
static __device__ __forceinline__ uint32_t smem_u32(const void* p) {
    uint32_t a;
    asm("{ .reg .u64 t; cvta.to.shared.u64 t, %1; cvt.u32.u64 %0, t; }" : "=r"(a) : "l"(p));
    return a;
}
static __device__ __forceinline__ void cvt2(float f, unsigned& h, unsigned& l) {
    __nv_bfloat16 hb = __float2bfloat16_rn(f);
    float rem = f - __bfloat162float(hb);
    __nv_bfloat16 lb = __float2bfloat16_rn(rem);
    h = (unsigned)__bfloat16_as_ushort(hb);
    l = (unsigned)__bfloat16_as_ushort(lb);
}
static __device__ __forceinline__ void ldm4(uint32_t addr, uint32_t* r) {
    asm volatile("ldmatrix.sync.aligned.m8n8.x4.shared.b16 {%0,%1,%2,%3}, [%4];"
        : "=r"(r[0]), "=r"(r[1]), "=r"(r[2]), "=r"(r[3]) : "r"(addr));
}
static __device__ __forceinline__ void mma16816(float* d, const uint32_t* a,
                                                const uint32_t* b) {
    asm volatile("mma.sync.aligned.m16n8k16.row.col.f32.bf16.bf16.f32 "
        "{%0,%1,%2,%3},{%4,%5,%6,%7},{%8,%9},{%0,%1,%2,%3};"
        : "+f"(d[0]), "+f"(d[1]), "+f"(d[2]), "+f"(d[3])
        : "r"(a[0]), "r"(a[1]), "r"(a[2]), "r"(a[3]), "r"(b[0]), "r"(b[1]));
}
static __device__ __forceinline__ void mma16816h(float* d, const uint32_t* a,
                                                 const uint32_t* b) {
    asm volatile("mma.sync.aligned.m16n8k16.row.col.f32.f16.f16.f32 "
        "{%0,%1,%2,%3},{%4,%5,%6,%7},{%8,%9},{%0,%1,%2,%3};"
        : "+f"(d[0]), "+f"(d[1]), "+f"(d[2]), "+f"(d[3])
        : "r"(a[0]), "r"(a[1]), "r"(a[2]), "r"(a[3]), "r"(b[0]), "r"(b[1]));
}
static __device__ __forceinline__ void cpa16(uint32_t s, const void* g) {
    asm volatile("cp.async.cg.shared.global [%0], [%1], 16;" :: "r"(s), "l"(g));
}
static __device__ __forceinline__ void cpcommit() {
    asm volatile("cp.async.commit_group;" ::: "memory");
}
template<int n> static __device__ __forceinline__ void cpwait() {
    asm volatile("cp.async.wait_group %0;" :: "n"(n) : "memory");
}

// ---------------- gather ----------------
__global__ void k_gather(const int* __restrict__ idx, const float* __restrict__ embed,
                         __nv_bfloat16* __restrict__ Xh, __nv_bfloat16* __restrict__ Xl)
{
    int t = blockIdx.x, b = blockIdx.y;
    int tok = idx[b*SEQ + t];
    float4 v = ((const float4*)(embed + (size_t)tok*EMB))[threadIdx.x];
    unsigned h0,l0,h1,l1,h2,l2,h3,l3;
    cvt2(v.x,h0,l0); cvt2(v.y,h1,l1); cvt2(v.z,h2,l2); cvt2(v.w,h3,l3);
    uint2 hv; hv.x = h0|(h1<<16); hv.y = h2|(h3<<16);
    uint2 lv; lv.x = l0|(l1<<16); lv.y = l2|(l3<<16);
    size_t o = (size_t)(t*NB + b)*EMB + threadIdx.x*4;
    *(uint2*)(Xh + o) = hv;
    *(uint2*)(Xl + o) = lv;
}

// ---------------- init: h0 split, combined bias, barrier slots ----------------
__global__ void k_init(const float* __restrict__ sv, const float* __restrict__ Vb,
                       const float* __restrict__ Wb,
                       __nv_bfloat16* __restrict__ hsh, __nv_bfloat16* __restrict__ hsl,
                       float* __restrict__ b3, unsigned* __restrict__ barc)
{
    int i = blockIdx.x*blockDim.x + threadIdx.x;
    if (i < NB*HID) {
        float v = sv[i];
        unsigned h, l; cvt2(v, h, l);
        ((unsigned short*)hsh)[i] = (unsigned short)h;
        ((unsigned short*)hsl)[i] = (unsigned short)l;
    }
    if (i < 4*HID)  b3[i] = Vb[i] + Wb[i];
    if (i < 64)     barc[i] = 0u;
}

// ---------------- convert + transpose: fp32 [K][N] -> bf16 hi/lo [N][K] ----------------
__global__ void k_convT(const float* __restrict__ in, __nv_bfloat16* __restrict__ hiT,
                        __nv_bfloat16* __restrict__ loT, int K, int N)
{
    __shared__ float s[32][33];
    const int k0 = blockIdx.y*32, n0 = blockIdx.x*32;
    const int tid = threadIdx.x;
    {
        int r = tid>>3, c4 = (tid&7)*4;
        float4 v = *(const float4*)(in + (size_t)(k0+r)*N + n0 + c4);
        s[r][c4+0]=v.x; s[r][c4+1]=v.y; s[r][c4+2]=v.z; s[r][c4+3]=v.w;
    }
    __syncthreads();
    {
        int n = tid>>3, kq = (tid&7)*4;
        unsigned hh[4], ll[4];
#pragma unroll
        for (int i = 0; i < 4; ++i) cvt2(s[kq+i][n], hh[i], ll[i]);
        uint2 hv; hv.x = hh[0]|(hh[1]<<16); hv.y = hh[2]|(hh[3]<<16);
        uint2 lv; lv.x = ll[0]|(ll[1]<<16); lv.y = ll[2]|(ll[3]<<16);
        size_t o = ((size_t)(n0+n)*K + k0 + kq);
        *(uint2*)(hiT + o) = hv;
        *(uint2*)(loT + o) = lv;
    }
}

// ---------------- convert + transpose: fp32 [K][N] -> fp16 [N][K] (single) ----------------
__global__ void k_convT1(const float* __restrict__ in, __half* __restrict__ hiT,
                         int K, int N)
{
    __shared__ float s[32][33];
    const int k0 = blockIdx.y*32, n0 = blockIdx.x*32;
    const int tid = threadIdx.x;
    {
        int r = tid>>3, c4 = (tid&7)*4;
        float4 v = *(const float4*)(in + (size_t)(k0+r)*N + n0 + c4);
        s[r][c4+0]=v.x; s[r][c4+1]=v.y; s[r][c4+2]=v.z; s[r][c4+3]=v.w;
    }
    __syncthreads();
    {
        int n = tid>>3, kq = (tid&7)*4;
        unsigned hh[4];
#pragma unroll
        for (int i = 0; i < 4; ++i)
            hh[i] = (unsigned)__half_as_ushort(__float2half_rn(s[kq+i][n]));
        uint2 hv; hv.x = hh[0]|(hh[1]<<16); hv.y = hh[2]|(hh[3]<<16);
        *(uint2*)(hiT + ((size_t)(n0+n)*K + k0 + kq)) = hv;
    }
}

// ======== bf16 3-term HMMA GEMM: 128x128 block, 8 warps of 32x64, Kc=32 ========
#define STG   32768
#define AL_O  8192
#define BH_O  16384
#define BL_O  24576
static __device__ __forceinline__ uint32_t swz64(int row, int k16) {
    return (uint32_t)(row*64 + ((k16 ^ ((row>>1)&3))<<4));
}

__global__ __launch_bounds__(256, 2)
void k_mgemm(const __nv_bfloat16* __restrict__ Ah, const __nv_bfloat16* __restrict__ Al,
             const __nv_bfloat16* __restrict__ Bh, const __nv_bfloat16* __restrict__ Bl,
             const float* __restrict__ bias, float* __restrict__ C,
             __nv_bfloat16* __restrict__ Chi, __nv_bfloat16* __restrict__ Clo,
             int N, int K, int Mstore)
{
    __shared__ __align__(16) unsigned char sm[2*STG];
    const uint32_t sbase = smem_u32(sm);

    const int tid = threadIdx.x, lane = tid & 31, wid = tid >> 5;
    const int brow = blockIdx.x*128, bcol = blockIdx.y*128;

    const int lrow = tid >> 1, ak = (tid & 1)*2;
    const __nv_bfloat16* gAh_t = Ah + (size_t)(brow + lrow)*K + ak*8;
    const __nv_bfloat16* gAl_t = Al + (size_t)(brow + lrow)*K + ak*8;
    const __nv_bfloat16* gBh_t = Bh + (size_t)(bcol + lrow)*K + ak*8;
    const __nv_bfloat16* gBl_t = Bl + (size_t)(bcol + lrow)*K + ak*8;
    const uint32_t cs0 = sbase + swz64(lrow, ak);
    const uint32_t cs1 = sbase + swz64(lrow, ak+1);

    const int m0w = (wid & 3)*32, n0w = (wid >> 2)*64;
    const int arL = lane & 15;
    const int srA = (arL >> 1) & 3;
    const int brL = (lane & 7) + ((lane >> 4) << 3);
    const int srB = ((lane & 7) >> 1) & 3;
    const uint32_t aRowOff = (uint32_t)(m0w + arL)*64;
    const uint32_t bRowOff = (uint32_t)(n0w + brL)*64 + BH_O;

    float acc[2][8][4];
#pragma unroll
    for (int i = 0; i < 2; ++i)
#pragma unroll
        for (int j = 0; j < 8; ++j)
#pragma unroll
            for (int q = 0; q < 4; ++q) acc[i][j][q] = 0.f;

    const int nch = K >> 5;

    {
        cpa16(cs0, gAh_t);            cpa16(cs1, gAh_t + 8);
        cpa16(cs0 + AL_O, gAl_t);     cpa16(cs1 + AL_O, gAl_t + 8);
        cpa16(cs0 + BH_O, gBh_t);     cpa16(cs1 + BH_O, gBh_t + 8);
        cpa16(cs0 + BL_O, gBl_t);     cpa16(cs1 + BL_O, gBl_t + 8);
        cpcommit();
    }

    for (int c = 0; c < nch; ++c) {
        if (c + 1 < nch) {
            const uint32_t so = (uint32_t)((c+1) & 1)*STG;
            const int kc = (c+1)*32;
            cpa16(cs0 + so, gAh_t + kc);        cpa16(cs1 + so, gAh_t + kc + 8);
            cpa16(cs0 + AL_O + so, gAl_t + kc); cpa16(cs1 + AL_O + so, gAl_t + kc + 8);
            cpa16(cs0 + BH_O + so, gBh_t + kc); cpa16(cs1 + BH_O + so, gBh_t + kc + 8);
            cpa16(cs0 + BL_O + so, gBl_t + kc); cpa16(cs1 + BL_O + so, gBl_t + kc + 8);
            cpcommit();
            cpwait<1>();
        } else {
            cpwait<0>();
        }
        __syncthreads();

        const uint32_t sb_s = sbase + (uint32_t)(c & 1)*STG;
#pragma unroll
        for (int kk = 0; kk < 32; kk += 16) {
            uint32_t Xa[2][4], Xb[4][4], Xc[4][4];
            const int k16a = (kk >> 3) + (lane >> 4);
            const uint32_t abase = sb_s + aRowOff + ((uint32_t)(k16a ^ srA) << 4);
            const int k16b = (kk >> 3) + ((lane >> 3) & 1);
            const uint32_t bbase = sb_s + bRowOff + ((uint32_t)(k16b ^ srB) << 4);

#pragma unroll
            for (int mt = 0; mt < 2; ++mt) ldm4(abase + mt*16*64, Xa[mt]);
#pragma unroll
            for (int ng = 0; ng < 4; ++ng) ldm4(bbase + ng*16*64, Xb[ng]);
#pragma unroll
            for (int mt = 0; mt < 2; ++mt)
#pragma unroll
                for (int nt = 0; nt < 8; ++nt)
                    mma16816(acc[mt][nt], Xa[mt], &Xb[nt >> 1][(nt & 1)*2]);

#pragma unroll
            for (int ng = 0; ng < 4; ++ng) ldm4(bbase + (BL_O - BH_O) + ng*16*64, Xc[ng]);
#pragma unroll
            for (int mt = 0; mt < 2; ++mt)
#pragma unroll
                for (int nt = 0; nt < 8; ++nt)
                    mma16816(acc[mt][nt], Xa[mt], &Xc[nt >> 1][(nt & 1)*2]);

#pragma unroll
            for (int mt = 0; mt < 2; ++mt) ldm4(abase + AL_O + mt*16*64, Xc[mt]);
#pragma unroll
            for (int mt = 0; mt < 2; ++mt)
#pragma unroll
                for (int nt = 0; nt < 8; ++nt)
                    mma16816(acc[mt][nt], Xc[mt], &Xb[nt >> 1][(nt & 1)*2]);
        }
        __syncthreads();
    }

    const int g = lane >> 2, tg = lane & 3;
#pragma unroll
    for (int mt = 0; mt < 2; ++mt)
#pragma unroll
        for (int nt = 0; nt < 8; ++nt) {
            const int col = bcol + n0w + nt*8 + tg*2;
            const float b0 = bias[col], b1 = bias[col+1];
#pragma unroll
            for (int half = 0; half < 2; ++half) {
                const int row = brow + m0w + mt*16 + g + half*8;
                if (row < Mstore) {
                    float o0 = acc[mt][nt][half*2+0] + b0;
                    float o1 = acc[mt][nt][half*2+1] + b1;
                    const size_t o = (size_t)row*N + col;
                    if (C) { float2 v; v.x = o0; v.y = o1; *(float2*)(C + o) = v; }
                    if (Chi) {
                        unsigned h0,l0,h1,l1;
                        cvt2(o0,h0,l0); cvt2(o1,h1,l1);
                        *(uint32_t*)(Chi + o) = h0 | (h1<<16);
                        *(uint32_t*)(Clo + o) = l0 | (l1<<16);
                    }
                }
            }
        }
}

// ======== plain fp16 GEMM (vocab projection): D = A @ B^T + bias ========
#define STG2  16384
#define BH2_O 8192
__global__ __launch_bounds__(256, 2)
void k_mgemm2(const __half* __restrict__ Ah, const __half* __restrict__ Bh,
              const float* __restrict__ bias, float* __restrict__ C,
              int N, int K, int Mstore)
{
    __shared__ __align__(16) unsigned char sm[2*STG2];
    const uint32_t sbase = smem_u32(sm);

    const int tid = threadIdx.x, lane = tid & 31, wid = tid >> 5;
    const int brow = blockIdx.x*128, bcol = blockIdx.y*128;

    const int lrow = tid >> 1, ak = (tid & 1)*2;
    const __half* gAh_t = Ah + (size_t)(brow + lrow)*K + ak*8;
    const __half* gBh_t = Bh + (size_t)(bcol + lrow)*K + ak*8;
    const uint32_t cs0 = sbase + swz64(lrow, ak);
    const uint32_t cs1 = sbase + swz64(lrow, ak+1);

    const int m0w = (wid & 3)*32, n0w = (wid >> 2)*64;
    const int arL = lane & 15;
    const int srA = (arL >> 1) & 3;
    const int brL = (lane & 7) + ((lane >> 4) << 3);
    const int srB = ((lane & 7) >> 1) & 3;
    const uint32_t aRowOff = (uint32_t)(m0w + arL)*64;
    const uint32_t bRowOff = (uint32_t)(n0w + brL)*64 + BH2_O;

    float acc[2][8][4];
#pragma unroll
    for (int i = 0; i < 2; ++i)
#pragma unroll
        for (int j = 0; j < 8; ++j)
#pragma unroll
            for (int q = 0; q < 4; ++q) acc[i][j][q] = 0.f;

    const int nch = K >> 5;

    {
        cpa16(cs0, gAh_t);             cpa16(cs1, gAh_t + 8);
        cpa16(cs0 + BH2_O, gBh_t);     cpa16(cs1 + BH2_O, gBh_t + 8);
        cpcommit();
    }

    for (int c = 0; c < nch; ++c) {
        if (c + 1 < nch) {
            const uint32_t so = (uint32_t)((c+1) & 1)*STG2;
            const int kc = (c+1)*32;
            cpa16(cs0 + so, gAh_t + kc);         cpa16(cs1 + so, gAh_t + kc + 8);
            cpa16(cs0 + BH2_O + so, gBh_t + kc); cpa16(cs1 + BH2_O + so, gBh_t + kc + 8);
            cpcommit();
            cpwait<1>();
        } else {
            cpwait<0>();
        }
        __syncthreads();

        const uint32_t sb_s = sbase + (uint32_t)(c & 1)*STG2;
#pragma unroll
        for (int kk = 0; kk < 32; kk += 16) {
            uint32_t Xa[2][4], Xb[4][4];
            const int k16a = (kk >> 3) + (lane >> 4);
            const uint32_t abase = sb_s + aRowOff + ((uint32_t)(k16a ^ srA) << 4);
            const int k16b = (kk >> 3) + ((lane >> 3) & 1);
            const uint32_t bbase = sb_s + bRowOff + ((uint32_t)(k16b ^ srB) << 4);

#pragma unroll
            for (int mt = 0; mt < 2; ++mt) ldm4(abase + mt*16*64, Xa[mt]);
#pragma unroll
            for (int ng = 0; ng < 4; ++ng) ldm4(bbase + ng*16*64, Xb[ng]);

#pragma unroll
            for (int mt = 0; mt < 2; ++mt)
#pragma unroll
                for (int nt = 0; nt < 8; ++nt)
                    mma16816h(acc[mt][nt], Xa[mt], &Xb[nt >> 1][(nt & 1)*2]);
        }
        __syncthreads();
    }

    const int g = lane >> 2, tg = lane & 3;
#pragma unroll
    for (int mt = 0; mt < 2; ++mt)
#pragma unroll
        for (int nt = 0; nt < 8; ++nt) {
            const int col = bcol + n0w + nt*8 + tg*2;
            const float b0 = bias[col], b1 = bias[col+1];
#pragma unroll
            for (int half = 0; half < 2; ++half) {
                const int row = brow + m0w + mt*16 + g + half*8;
                if (row < Mstore) {
                    float2 v;
                    v.x = acc[mt][nt][half*2+0] + b0;
                    v.y = acc[mt][nt][half*2+1] + b1;
                    *(float2*)(C + (size_t)row*N + col) = v;
                }
            }
        }
}

// ======== persistent HMMA recurrence: all 63 steps in one kernel ========
#define WH_O  0
#define WL_O  65536
#define HS_O  131072
#define GS_O  147456
#define REC_SMEM 151552
static __device__ __forceinline__ uint32_t soff(int row, int seg) {
    return (uint32_t)(row*128 + ((seg ^ (row & 7)) << 4));
}

__global__ __launch_bounds__(128)
void k_srec(const float* __restrict__ Gx,
            const __nv_bfloat16* __restrict__ Wh, const __nv_bfloat16* __restrict__ Wl,
            __nv_bfloat16* __restrict__ hsh, __nv_bfloat16* __restrict__ hsl,
            const float* __restrict__ sv,
            __half* __restrict__ Hh,
            unsigned* __restrict__ barc)
{
    extern __shared__ __align__(16) unsigned char sm[];
    float* gsm = (float*)(sm + GS_O);
    const uint32_t sbase = smem_u32(sm);
    const int tid = threadIdx.x, lane = tid & 31, w = tid >> 5;
    const int n0 = blockIdx.x * 8;

    const int lrow = tid >> 2, sp = (tid & 3)*2;
    const uint32_t lo0 = soff(lrow, sp);
    const uint32_t lo1 = soff(lrow, sp+1);
    const int grow = (lrow >> 3)*HID + n0 + (lrow & 7);
    const __nv_bfloat16* gw_h = Wh + (size_t)grow*HID + sp*8;
    const __nv_bfloat16* gw_l = Wl + (size_t)grow*HID + sp*8;

#pragma unroll
    for (int cc = 0; cc < 16; ++cc) {
        const uint32_t wb = (uint32_t)cc*4096;
        cpa16(sbase + WH_O + wb + lo0, gw_h + cc*64);
        cpa16(sbase + WH_O + wb + lo1, gw_h + cc*64 + 8);
        cpa16(sbase + WL_O + wb + lo0, gw_l + cc*64);
        cpa16(sbase + WL_O + wb + lo1, gw_l + cc*64 + 8);
    }
    cpcommit();

    const int cb = tid >> 3, cn = n0 + (tid & 7);
    float creg0 = sv[cb*HID + cn];
    float creg1 = sv[(cb+16)*HID + cn];

    cpwait<0>();
    __syncthreads();

    const int arow0 = (lane & 15), arow1 = 16 + (lane & 15);
    const int rw = w*8 + (lane & 7), si = lane >> 3;

    for (int ts = 0; ts < TSTEPS; ++ts) {
        const __nv_bfloat16* hih = hsh + (ts & 1)*NB*HID;
        const __nv_bfloat16* hil = hsl + (ts & 1)*NB*HID;
        __nv_bfloat16* hoh = hsh + (1 - (ts & 1))*NB*HID;
        __nv_bfloat16* hol = hsl + (1 - (ts & 1))*NB*HID;
        const __nv_bfloat16* gh_h = hih + lrow*HID + sp*8;
        const __nv_bfloat16* gh_l = hil + lrow*HID + sp*8;

        float acc[2][4];
#pragma unroll
        for (int i = 0; i < 2; ++i)
#pragma unroll
            for (int q = 0; q < 4; ++q) acc[i][q] = 0.f;

        cpa16(sbase + HS_O + lo0, gh_h);            cpa16(sbase + HS_O + lo1, gh_h + 8);
        cpa16(sbase + HS_O + 4096 + lo0, gh_l);     cpa16(sbase + HS_O + 4096 + lo1, gh_l + 8);
        cpcommit();

        for (int cc = 0; cc < 16; ++cc) {
            if (cc + 1 < 16) {
                const uint32_t so = HS_O + (uint32_t)((cc+1) & 1)*8192;
                const int kc = (cc+1)*64;
                cpa16(sbase + so + lo0, gh_h + kc);        cpa16(sbase + so + lo1, gh_h + kc + 8);
                cpa16(sbase + so + 4096 + lo0, gh_l + kc); cpa16(sbase + so + 4096 + lo1, gh_l + kc + 8);
                cpcommit();
                cpwait<1>();
            } else {
                cpwait<0>();
            }
            __syncthreads();

            const uint32_t hb = sbase + HS_O + (uint32_t)(cc & 1)*8192;
            const uint32_t wb = (uint32_t)cc*4096;
            uint32_t ah[4][2][4], al[4][2][4], bh[2][4], bl[2][4];
#pragma unroll
            for (int kb = 0; kb < 2; ++kb) {
                ldm4(sbase + WH_O + wb + soff(rw, kb*4 + si), bh[kb]);
                ldm4(sbase + WL_O + wb + soff(rw, kb*4 + si), bl[kb]);
            }
#pragma unroll
            for (int q = 0; q < 4; ++q) {
                const int seg = q*2 + (lane >> 4);
                ldm4(hb        + soff(arow0, seg), ah[q][0]);
                ldm4(hb        + soff(arow1, seg), ah[q][1]);
                ldm4(hb + 4096 + soff(arow0, seg), al[q][0]);
                ldm4(hb + 4096 + soff(arow1, seg), al[q][1]);
            }
#pragma unroll
            for (int q = 0; q < 4; ++q)
#pragma unroll
                for (int mt = 0; mt < 2; ++mt)
                    mma16816(acc[mt], ah[q][mt], &bh[q >> 1][(q & 1)*2]);
#pragma unroll
            for (int q = 0; q < 4; ++q)
#pragma unroll
                for (int mt = 0; mt < 2; ++mt)
                    mma16816(acc[mt], ah[q][mt], &bl[q >> 1][(q & 1)*2]);
#pragma unroll
            for (int q = 0; q < 4; ++q)
#pragma unroll
                for (int mt = 0; mt < 2; ++mt)
                    mma16816(acc[mt], al[q][mt], &bh[q >> 1][(q & 1)*2]);
            __syncthreads();
        }

        {
            const int r = lane >> 2, nl0 = (lane & 3)*2;
#pragma unroll
            for (int mt = 0; mt < 2; ++mt) {
                const int b0 = mt*16 + r, b1 = b0 + 8;
                gsm[(w*32 + b0)*8 + nl0]     = acc[mt][0];
                gsm[(w*32 + b0)*8 + nl0 + 1] = acc[mt][1];
                gsm[(w*32 + b1)*8 + nl0]     = acc[mt][2];
                gsm[(w*32 + b1)*8 + nl0 + 1] = acc[mt][3];
            }
        }
        __syncthreads();

#pragma unroll
        for (int rep = 0; rep < 2; ++rep) {
            const int b = cb + rep*16;
            const int nl = tid & 7;
            const int n = cn;
            const size_t gxrow = (size_t)(ts*NB + b)*(4*HID);
            float gi = gsm[(0*32 + b)*8 + nl] + Gx[gxrow + 0*HID + n];
            float gf = gsm[(1*32 + b)*8 + nl] + Gx[gxrow + 1*HID + n];
            float go = gsm[(2*32 + b)*8 + nl] + Gx[gxrow + 2*HID + n];
            float gc = gsm[(3*32 + b)*8 + nl] + Gx[gxrow + 3*HID + n];
            float cv = rep ? creg1 : creg0;
            float si_ = 1.f / (1.f + expf(-gi));
            float sf  = 1.f / (1.f + expf(-gf));
            float so_ = 1.f / (1.f + expf(-go));
            float c_new = sf * cv + si_ * tanhf(gc);
            float h_new = so_ * c_new;
            if (rep) creg1 = c_new; else creg0 = c_new;
            unsigned hh, ll;
            cvt2(h_new, hh, ll);
            ((unsigned short*)hoh)[b*HID + n] = (unsigned short)hh;
            ((unsigned short*)hol)[b*HID + n] = (unsigned short)ll;
            const size_t ho = (size_t)(b*TSTEPS + ts)*HID + n;
            ((unsigned short*)Hh)[ho] =
                (unsigned short)__half_as_ushort(__float2half_rn(h_new));
        }

        if (ts < TSTEPS - 1) {
            __threadfence();
            __syncthreads();
            if (tid == 0) {
                atomicAdd(&barc[ts], 1u);
                while (*(volatile unsigned*)&barc[ts] < 128u) { }
                __threadfence();
            }
            __syncthreads();
        }
    }
}

// ---------------- launch ----------------
extern "C" void kernel_launch(void* const* d_in, const int* in_sizes, int n_in,
                              void* d_out, int out_size)
{
    const int*   rnn   = (const int*)  d_in[0];
    const float* sv    = (const float*)d_in[1];
    const float* embed = (const float*)d_in[2];
    const float* U_w   = (const float*)d_in[3];
    const float* U_b   = (const float*)d_in[4];
    const float* S1_w  = (const float*)d_in[5];
    const float* S1_b  = (const float*)d_in[6];
    const float* V_w   = (const float*)d_in[7];
    const float* W_w   = (const float*)d_in[9];
    const float* P_w   = (const float*)d_in[11];
    const float* P_b   = (const float*)d_in[12];
    float* out = (float*)d_out;

    float *Gx,*b3;
    unsigned* barc;
    __nv_bfloat16 *Xh,*Xl,*Uh,*Ul,*Sh,*Sl,*Bh,*Bl,*Wh,*Wl,*hsh,*hsl;
    __half *Hh,*P16;
    cudaGetSymbolAddress((void**)&Gx, g_Gx);
    cudaGetSymbolAddress((void**)&b3, g_bias3);
    cudaGetSymbolAddress((void**)&barc, g_barc);
    cudaGetSymbolAddress((void**)&Xh, g_Xh); cudaGetSymbolAddress((void**)&Xl, g_Xl);
    cudaGetSymbolAddress((void**)&Uh, g_Uh); cudaGetSymbolAddress((void**)&Ul, g_Ul);
    cudaGetSymbolAddress((void**)&Sh, g_Sh); cudaGetSymbolAddress((void**)&Sl, g_Sl);
    cudaGetSymbolAddress((void**)&Hh, g_Hh);
    cudaGetSymbolAddress((void**)&Bh, g_Bh); cudaGetSymbolAddress((void**)&Bl, g_Bl);
    cudaGetSymbolAddress((void**)&P16, g_P16);
    cudaGetSymbolAddress((void**)&Wh, g_Wh); cudaGetSymbolAddress((void**)&Wl, g_Wl);
    cudaGetSymbolAddress((void**)&hsh, g_hsh); cudaGetSymbolAddress((void**)&hsl, g_hsl);

    cudaFuncSetAttribute(k_srec, cudaFuncAttributeMaxDynamicSharedMemorySize, REC_SMEM);

    cudaStream_t s2;
    cudaStreamCreateWithFlags(&s2, cudaStreamNonBlocking);
    cudaEvent_t evFork, evJoin;
    cudaEventCreateWithFlags(&evFork, cudaEventDisableTiming);
    cudaEventCreateWithFlags(&evJoin, cudaEventDisableTiming);

    k_gather<<<dim3(TSTEPS, NB), 128>>>(rnn, embed, Xh, Xl);
    k_init<<<(NB*HID + 255)/256, 256>>>(sv, (const float*)d_in[8],
                                        (const float*)d_in[10], hsh, hsl, b3, barc);

    // fork: P_w fp16 transpose runs concurrently (joined before GEMM4)
    cudaEventRecord(evFork, 0);
    cudaStreamWaitEvent(s2, evFork, 0);
    k_convT1<<<dim3(VOCAB/32, HID/32), 256, 0, s2>>>(P_w, P16, HID, VOCAB);
    cudaEventRecord(evJoin, s2);

    // W^T split for the recurrence
    k_convT<<<dim3((4*HID)/32, HID/32), 256>>>(W_w, Wh, Wl, HID, 4*HID);

    // GEMM1: U = X @ U_w + U_b -> bf16 hi/lo only
    k_convT<<<dim3((4*STY)/32, EMB/32), 256>>>(U_w, Bh, Bl, EMB, 4*STY);
    k_mgemm<<<dim3(MPAD/128, (4*STY)/128), 256>>>(Xh, Xl, Bh, Bl, U_b,
                                                  nullptr, Uh, Ul, 4*STY, EMB, MPAD);
    // GEMM2: S = U @ S1_w + S1_b -> bf16 hi/lo only
    k_convT<<<dim3(STY/32, (4*STY)/32), 256>>>(S1_w, Bh, Bl, 4*STY, STY);
    k_mgemm<<<dim3(MPAD/128, STY/128), 256>>>(Uh, Ul, Bh, Bl, S1_b,
                                              nullptr, Sh, Sl, STY, 4*STY, MPAD);
    // GEMM3: Gx = S @ V_w + (V_b+W_b) -> fp32 only
    k_convT<<<dim3((4*HID)/32, STY/32), 256>>>(V_w, Bh, Bl, STY, 4*HID);
    k_mgemm<<<dim3(MPAD/128, (4*HID)/128), 256>>>(Sh, Sl, Bh, Bl, b3,
                                                  Gx, nullptr, nullptr, 4*HID, STY, MPAD);

    // recurrence: single persistent kernel, all 63 steps
    k_srec<<<(4*HID)/32, 128, REC_SMEM>>>(Gx, Wh, Wl, hsh, hsl, sv, Hh, barc);

    // join, then GEMM4 (plain fp16): out = H @ P_w + P_b -> fp32 d_out
    cudaStreamWaitEvent(0, evJoin, 0);
    k_mgemm2<<<dim3(MPAD/128, VOCAB/128), 256>>>(Hh, P16, P_b,
                                                 out, VOCAB, HID, MROWS);
}

// round 16
// speedup vs baseline: 2.8297x; 1.1323x over previous
#include <cuda_runtime.h>
#include <cuda_bf16.h>
#include <cuda_fp16.h>
#include <stdint.h>
#include <math.h>

#define EMB   512
#define VOCAB 32000
#define HID   1024
#define STY   512
#define NB    32
#define SEQ   64
#define TSTEPS 63
#define MROWS (TSTEPS*NB)   /* 2016 */
#define MPAD  2048

// ---------------- device scratch (zero-initialized .bss) ----------------
__device__ float g_Gx[(size_t)MPAD*4*HID];
__device__ float g_bias3[4*HID];
__device__ unsigned g_barc[64];
__device__ __half g_Xh[MPAD*EMB],   g_Xl[MPAD*EMB];
__device__ __half g_Uh[MPAD*4*STY], g_Ul[MPAD*4*STY];
__device__ __half g_Sh[MPAD*STY],   g_Sl[MPAD*STY];
__device__ __half g_Hh[MPAD*HID];                      // fp16 H; rows>=2016 stay 0
__device__ __half g_B16[(size_t)VOCAB*1024];           // weight staging (fp16, reused)
__device__ __half g_P16[(size_t)VOCAB*1024];           // fp16 P_w^T
__device__ __half g_W16[(size_t)4*HID*HID];            // fp16 W^T
__device__ __half g_hs16[2*NB*HID];                    // h ping-pong (fp16)

// ---------------- helpers ----------------
static __device__ __forceinline__ uint32_t smem_u32(const void* p) {
    uint32_t a;
    asm("{ .reg .u64 t; cvta.to.shared.u64 t, %1; cvt.u32.u64 %0, t; }" : "=r"(a) : "l"(p));
    return a;
}
static __device__ __forceinline__ void cvt2h(float f, unsigned& h, unsigned& l) {
    __half hb = __float2half_rn(f);
    float rem = f - __half2float(hb);
    __half lb = __float2half_rn(rem);
    h = (unsigned)__half_as_ushort(hb);
    l = (unsigned)__half_as_ushort(lb);
}
static __device__ __forceinline__ void ldm4(uint32_t addr, uint32_t* r) {
    asm volatile("ldmatrix.sync.aligned.m8n8.x4.shared.b16 {%0,%1,%2,%3}, [%4];"
        : "=r"(r[0]), "=r"(r[1]), "=r"(r[2]), "=r"(r[3]) : "r"(addr));
}
static __device__ __forceinline__ void mma16816h(float* d, const uint32_t* a,
                                                 const uint32_t* b) {
    asm volatile("mma.sync.aligned.m16n8k16.row.col.f32.f16.f16.f32 "
        "{%0,%1,%2,%3},{%4,%5,%6,%7},{%8,%9},{%0,%1,%2,%3};"
        : "+f"(d[0]), "+f"(d[1]), "+f"(d[2]), "+f"(d[3])
        : "r"(a[0]), "r"(a[1]), "r"(a[2]), "r"(a[3]), "r"(b[0]), "r"(b[1]));
}
static __device__ __forceinline__ void cpa16(uint32_t s, const void* g) {
    asm volatile("cp.async.cg.shared.global [%0], [%1], 16;" :: "r"(s), "l"(g));
}
static __device__ __forceinline__ void cpcommit() {
    asm volatile("cp.async.commit_group;" ::: "memory");
}
template<int n> static __device__ __forceinline__ void cpwait() {
    asm volatile("cp.async.wait_group %0;" :: "n"(n) : "memory");
}

// ---------------- gather: X fp16 exact split ----------------
__global__ void k_gather(const int* __restrict__ idx, const float* __restrict__ embed,
                         __half* __restrict__ Xh, __half* __restrict__ Xl)
{
    int t = blockIdx.x, b = blockIdx.y;
    int tok = idx[b*SEQ + t];
    float4 v = ((const float4*)(embed + (size_t)tok*EMB))[threadIdx.x];
    unsigned h0,l0,h1,l1,h2,l2,h3,l3;
    cvt2h(v.x,h0,l0); cvt2h(v.y,h1,l1); cvt2h(v.z,h2,l2); cvt2h(v.w,h3,l3);
    uint2 hv; hv.x = h0|(h1<<16); hv.y = h2|(h3<<16);
    uint2 lv; lv.x = l0|(l1<<16); lv.y = l2|(l3<<16);
    size_t o = (size_t)(t*NB + b)*EMB + threadIdx.x*4;
    *(uint2*)(Xh + o) = hv;
    *(uint2*)(Xl + o) = lv;
}

// ---------------- init: h0 fp16, combined bias, barrier slots ----------------
__global__ void k_init(const float* __restrict__ sv, const float* __restrict__ Vb,
                       const float* __restrict__ Wb,
                       __half* __restrict__ hs16,
                       float* __restrict__ b3, unsigned* __restrict__ barc)
{
    int i = blockIdx.x*blockDim.x + threadIdx.x;
    if (i < NB*HID)
        ((unsigned short*)hs16)[i] =
            (unsigned short)__half_as_ushort(__float2half_rn(sv[i]));
    if (i < 4*HID)  b3[i] = Vb[i] + Wb[i];
    if (i < 64)     barc[i] = 0u;
}

// ---------------- convert + transpose: fp32 [K][N] -> fp16 [N][K] ----------------
__global__ void k_convT1(const float* __restrict__ in, __half* __restrict__ hiT,
                         int K, int N)
{
    __shared__ float s[32][33];
    const int k0 = blockIdx.y*32, n0 = blockIdx.x*32;
    const int tid = threadIdx.x;
    {
        int r = tid>>3, c4 = (tid&7)*4;
        float4 v = *(const float4*)(in + (size_t)(k0+r)*N + n0 + c4);
        s[r][c4+0]=v.x; s[r][c4+1]=v.y; s[r][c4+2]=v.z; s[r][c4+3]=v.w;
    }
    __syncthreads();
    {
        int n = tid>>3, kq = (tid&7)*4;
        unsigned hh[4];
#pragma unroll
        for (int i = 0; i < 4; ++i)
            hh[i] = (unsigned)__half_as_ushort(__float2half_rn(s[kq+i][n]));
        uint2 hv; hv.x = hh[0]|(hh[1]<<16); hv.y = hh[2]|(hh[3]<<16);
        *(uint2*)(hiT + ((size_t)(n0+n)*K + k0 + kq)) = hv;
    }
}

// ======== fp16 HMMA GEMM (TERMS=1: A@B; TERMS=2: (Ah+Al)@B) ========
// 128x128 block, 8 warps of 32x64, Kc=32, 2-stage cp.async.
static __device__ __forceinline__ uint32_t swz64(int row, int k16) {
    return (uint32_t)(row*64 + ((k16 ^ ((row>>1)&3))<<4));
}

template<int TERMS>
__global__ __launch_bounds__(256, 2)
void k_hgemm(const __half* __restrict__ Ah, const __half* __restrict__ Al,
             const __half* __restrict__ B16,
             const float* __restrict__ bias, float* __restrict__ C,
             __half* __restrict__ Chi, __half* __restrict__ Clo,
             int N, int K, int Mstore)
{
    constexpr uint32_t ALO  = 8192;
    constexpr uint32_t BO   = (uint32_t)TERMS * 8192;
    constexpr uint32_t BSTG = (uint32_t)(TERMS + 1) * 8192;
    __shared__ __align__(16) unsigned char sm[2*BSTG];
    const uint32_t sbase = smem_u32(sm);

    const int tid = threadIdx.x, lane = tid & 31, wid = tid >> 5;
    const int brow = blockIdx.x*128, bcol = blockIdx.y*128;

    const int lrow = tid >> 1, ak = (tid & 1)*2;
    const __half* gAh_t = Ah + (size_t)(brow + lrow)*K + ak*8;
    const __half* gAl_t = (TERMS == 2) ? (Al + (size_t)(brow + lrow)*K + ak*8) : nullptr;
    const __half* gB_t  = B16 + (size_t)(bcol + lrow)*K + ak*8;
    const uint32_t cs0 = sbase + swz64(lrow, ak);
    const uint32_t cs1 = sbase + swz64(lrow, ak+1);

    const int m0w = (wid & 3)*32, n0w = (wid >> 2)*64;
    const int arL = lane & 15;
    const int srA = (arL >> 1) & 3;
    const int brL = (lane & 7) + ((lane >> 4) << 3);
    const int srB = ((lane & 7) >> 1) & 3;
    const uint32_t aRowOff = (uint32_t)(m0w + arL)*64;
    const uint32_t bRowOff = (uint32_t)(n0w + brL)*64 + BO;

    float acc[2][8][4];
#pragma unroll
    for (int i = 0; i < 2; ++i)
#pragma unroll
        for (int j = 0; j < 8; ++j)
#pragma unroll
            for (int q = 0; q < 4; ++q) acc[i][j][q] = 0.f;

    const int nch = K >> 5;

    {
        cpa16(cs0, gAh_t);           cpa16(cs1, gAh_t + 8);
        if (TERMS == 2) { cpa16(cs0 + ALO, gAl_t); cpa16(cs1 + ALO, gAl_t + 8); }
        cpa16(cs0 + BO, gB_t);       cpa16(cs1 + BO, gB_t + 8);
        cpcommit();
    }

    for (int c = 0; c < nch; ++c) {
        if (c + 1 < nch) {
            const uint32_t so = (uint32_t)((c+1) & 1)*BSTG;
            const int kc = (c+1)*32;
            cpa16(cs0 + so, gAh_t + kc);       cpa16(cs1 + so, gAh_t + kc + 8);
            if (TERMS == 2) {
                cpa16(cs0 + ALO + so, gAl_t + kc);
                cpa16(cs1 + ALO + so, gAl_t + kc + 8);
            }
            cpa16(cs0 + BO + so, gB_t + kc);   cpa16(cs1 + BO + so, gB_t + kc + 8);
            cpcommit();
            cpwait<1>();
        } else {
            cpwait<0>();
        }
        __syncthreads();

        const uint32_t sb_s = sbase + (uint32_t)(c & 1)*BSTG;
#pragma unroll
        for (int kk = 0; kk < 32; kk += 16) {
            uint32_t Xa[2][4], Xd[2][4], Xb[4][4];
            const int k16a = (kk >> 3) + (lane >> 4);
            const uint32_t abase = sb_s + aRowOff + ((uint32_t)(k16a ^ srA) << 4);
            const int k16b = (kk >> 3) + ((lane >> 3) & 1);
            const uint32_t bbase = sb_s + bRowOff + ((uint32_t)(k16b ^ srB) << 4);

#pragma unroll
            for (int mt = 0; mt < 2; ++mt) ldm4(abase + mt*16*64, Xa[mt]);
            if (TERMS == 2)
#pragma unroll
                for (int mt = 0; mt < 2; ++mt) ldm4(abase + ALO + mt*16*64, Xd[mt]);
#pragma unroll
            for (int ng = 0; ng < 4; ++ng) ldm4(bbase + ng*16*64, Xb[ng]);

#pragma unroll
            for (int mt = 0; mt < 2; ++mt)
#pragma unroll
                for (int nt = 0; nt < 8; ++nt)
                    mma16816h(acc[mt][nt], Xa[mt], &Xb[nt >> 1][(nt & 1)*2]);
            if (TERMS == 2)
#pragma unroll
                for (int mt = 0; mt < 2; ++mt)
#pragma unroll
                    for (int nt = 0; nt < 8; ++nt)
                        mma16816h(acc[mt][nt], Xd[mt], &Xb[nt >> 1][(nt & 1)*2]);
        }
        __syncthreads();
    }

    const int g = lane >> 2, tg = lane & 3;
#pragma unroll
    for (int mt = 0; mt < 2; ++mt)
#pragma unroll
        for (int nt = 0; nt < 8; ++nt) {
            const int col = bcol + n0w + nt*8 + tg*2;
            const float b0 = bias[col], b1 = bias[col+1];
#pragma unroll
            for (int half = 0; half < 2; ++half) {
                const int row = brow + m0w + mt*16 + g + half*8;
                if (row < Mstore) {
                    float o0 = acc[mt][nt][half*2+0] + b0;
                    float o1 = acc[mt][nt][half*2+1] + b1;
                    const size_t o = (size_t)row*N + col;
                    if (C) { float2 v; v.x = o0; v.y = o1; *(float2*)(C + o) = v; }
                    if (Chi) {
                        unsigned h0,l0,h1,l1;
                        cvt2h(o0,h0,l0); cvt2h(o1,h1,l1);
                        *(uint32_t*)(Chi + o) = h0 | (h1<<16);
                        *(uint32_t*)(Clo + o) = l0 | (l1<<16);
                    }
                }
            }
        }
}

// ======== persistent fp16 recurrence: all 63 steps, W resident in smem ========
// smem: W 64K (16 chunks x 4K) | h stages 2x4K | gate buf 4K = 76K dynamic.
#define WO    0
#define HSO   65536
#define GSO   73728
#define REC_SMEM 77824
static __device__ __forceinline__ uint32_t soff(int row, int seg) {
    return (uint32_t)(row*128 + ((seg ^ (row & 7)) << 4));
}

__global__ __launch_bounds__(128)
void k_srec(const float* __restrict__ Gx,
            const __half* __restrict__ W16,
            __half* __restrict__ hs16,
            const float* __restrict__ sv,
            __half* __restrict__ Hh,
            unsigned* __restrict__ barc)
{
    extern __shared__ __align__(16) unsigned char sm[];
    float* gsm = (float*)(sm + GSO);
    const uint32_t sbase = smem_u32(sm);
    const int tid = threadIdx.x, lane = tid & 31, w = tid >> 5;
    const int n0 = blockIdx.x * 8;

    // loader: thread -> row 0..31, seg pair
    const int lrow = tid >> 2, sp = (tid & 3)*2;
    const uint32_t lo0 = soff(lrow, sp);
    const uint32_t lo1 = soff(lrow, sp+1);
    const int grow = (lrow >> 3)*HID + n0 + (lrow & 7);
    const __half* gw = W16 + (size_t)grow*HID + sp*8;

    // preload W (single fp16, 16 chunks x 4 KB)
#pragma unroll
    for (int cc = 0; cc < 16; ++cc) {
        const uint32_t wb = (uint32_t)cc*4096;
        cpa16(sbase + WO + wb + lo0, gw + cc*64);
        cpa16(sbase + WO + wb + lo1, gw + cc*64 + 8);
    }
    cpcommit();

    // c in registers
    const int cb = tid >> 3, cn = n0 + (tid & 7);
    float creg0 = sv[cb*HID + cn];
    float creg1 = sv[(cb+16)*HID + cn];

    cpwait<0>();
    __syncthreads();

    const int arow0 = (lane & 15), arow1 = 16 + (lane & 15);
    const int rw = w*8 + (lane & 7), si = lane >> 3;

    for (int ts = 0; ts < TSTEPS; ++ts) {
        const __half* hin = hs16 + (ts & 1)*NB*HID;
        __half* hout = hs16 + (1 - (ts & 1))*NB*HID;
        const __half* gh = hin + lrow*HID + sp*8;

        float acc[2][4];
#pragma unroll
        for (int i = 0; i < 2; ++i)
#pragma unroll
            for (int q = 0; q < 4; ++q) acc[i][q] = 0.f;

        // prologue: h chunk 0 -> stage 0
        cpa16(sbase + HSO + lo0, gh);  cpa16(sbase + HSO + lo1, gh + 8);
        cpcommit();

        for (int cc = 0; cc < 16; ++cc) {
            if (cc + 1 < 16) {
                const uint32_t so = HSO + (uint32_t)((cc+1) & 1)*4096;
                const int kc = (cc+1)*64;
                cpa16(sbase + so + lo0, gh + kc);
                cpa16(sbase + so + lo1, gh + kc + 8);
                cpcommit();
                cpwait<1>();
            } else {
                cpwait<0>();
            }
            __syncthreads();

            const uint32_t hb = sbase + HSO + (uint32_t)(cc & 1)*4096;
            const uint32_t wb = (uint32_t)cc*4096;
            uint32_t ah[4][2][4], bh[2][4];
#pragma unroll
            for (int kb = 0; kb < 2; ++kb)
                ldm4(sbase + WO + wb + soff(rw, kb*4 + si), bh[kb]);
#pragma unroll
            for (int q = 0; q < 4; ++q) {
                const int seg = q*2 + (lane >> 4);
                ldm4(hb + soff(arow0, seg), ah[q][0]);
                ldm4(hb + soff(arow1, seg), ah[q][1]);
            }
#pragma unroll
            for (int q = 0; q < 4; ++q)
#pragma unroll
                for (int mt = 0; mt < 2; ++mt)
                    mma16816h(acc[mt], ah[q][mt], &bh[q >> 1][(q & 1)*2]);
            __syncthreads();
        }

        // gate results -> gsm[gate][b][nl]
        {
            const int r = lane >> 2, nl0 = (lane & 3)*2;
#pragma unroll
            for (int mt = 0; mt < 2; ++mt) {
                const int b0 = mt*16 + r, b1 = b0 + 8;
                gsm[(w*32 + b0)*8 + nl0]     = acc[mt][0];
                gsm[(w*32 + b0)*8 + nl0 + 1] = acc[mt][1];
                gsm[(w*32 + b1)*8 + nl0]     = acc[mt][2];
                gsm[(w*32 + b1)*8 + nl0 + 1] = acc[mt][3];
            }
        }
        __syncthreads();

#pragma unroll
        for (int rep = 0; rep < 2; ++rep) {
            const int b = cb + rep*16;
            const int nl = tid & 7;
            const int n = cn;
            const size_t gxrow = (size_t)(ts*NB + b)*(4*HID);
            float gi = gsm[(0*32 + b)*8 + nl] + Gx[gxrow + 0*HID + n];
            float gf = gsm[(1*32 + b)*8 + nl] + Gx[gxrow + 1*HID + n];
            float go = gsm[(2*32 + b)*8 + nl] + Gx[gxrow + 2*HID + n];
            float gc = gsm[(3*32 + b)*8 + nl] + Gx[gxrow + 3*HID + n];
            float cv = rep ? creg1 : creg0;
            float si_ = 1.f / (1.f + expf(-gi));
            float sf  = 1.f / (1.f + expf(-gf));
            float so_ = 1.f / (1.f + expf(-go));
            float c_new = sf * cv + si_ * tanhf(gc);
            float h_new = so_ * c_new;
            if (rep) creg1 = c_new; else creg0 = c_new;
            unsigned short hb16 =
                (unsigned short)__half_as_ushort(__float2half_rn(h_new));
            ((unsigned short*)hout)[b*HID + n] = hb16;
            ((unsigned short*)Hh)[(size_t)(b*TSTEPS + ts)*HID + n] = hb16;
        }

        if (ts < TSTEPS - 1) {
            __threadfence();
            __syncthreads();
            if (tid == 0) {
                atomicAdd(&barc[ts], 1u);
                while (*(volatile unsigned*)&barc[ts] < 128u) { }
                __threadfence();
            }
            __syncthreads();
        }
    }
}

// ---------------- launch ----------------
extern "C" void kernel_launch(void* const* d_in, const int* in_sizes, int n_in,
                              void* d_out, int out_size)
{
    const int*   rnn   = (const int*)  d_in[0];
    const float* sv    = (const float*)d_in[1];
    const float* embed = (const float*)d_in[2];
    const float* U_w   = (const float*)d_in[3];
    const float* U_b   = (const float*)d_in[4];
    const float* S1_w  = (const float*)d_in[5];
    const float* S1_b  = (const float*)d_in[6];
    const float* V_w   = (const float*)d_in[7];
    const float* W_w   = (const float*)d_in[9];
    const float* P_w   = (const float*)d_in[11];
    const float* P_b   = (const float*)d_in[12];
    float* out = (float*)d_out;

    float *Gx,*b3;
    unsigned* barc;
    __half *Xh,*Xl,*Uh,*Ul,*Sh,*Sl,*Hh,*B16,*P16,*W16,*hs16;
    cudaGetSymbolAddress((void**)&Gx, g_Gx);
    cudaGetSymbolAddress((void**)&b3, g_bias3);
    cudaGetSymbolAddress((void**)&barc, g_barc);
    cudaGetSymbolAddress((void**)&Xh, g_Xh); cudaGetSymbolAddress((void**)&Xl, g_Xl);
    cudaGetSymbolAddress((void**)&Uh, g_Uh); cudaGetSymbolAddress((void**)&Ul, g_Ul);
    cudaGetSymbolAddress((void**)&Sh, g_Sh); cudaGetSymbolAddress((void**)&Sl, g_Sl);
    cudaGetSymbolAddress((void**)&Hh, g_Hh);
    cudaGetSymbolAddress((void**)&B16, g_B16);
    cudaGetSymbolAddress((void**)&P16, g_P16);
    cudaGetSymbolAddress((void**)&W16, g_W16);
    cudaGetSymbolAddress((void**)&hs16, g_hs16);

    cudaFuncSetAttribute(k_srec, cudaFuncAttributeMaxDynamicSharedMemorySize, REC_SMEM);

    cudaStream_t s2;
    cudaStreamCreateWithFlags(&s2, cudaStreamNonBlocking);
    cudaEvent_t evFork, evJoin;
    cudaEventCreateWithFlags(&evFork, cudaEventDisableTiming);
    cudaEventCreateWithFlags(&evJoin, cudaEventDisableTiming);

    k_gather<<<dim3(TSTEPS, NB), 128>>>(rnn, embed, Xh, Xl);
    k_init<<<(NB*HID + 255)/256, 256>>>(sv, (const float*)d_in[8],
                                        (const float*)d_in[10], hs16, b3, barc);

    // fork: P_w fp16 transpose runs concurrently (joined before GEMM4)
    cudaEventRecord(evFork, 0);
    cudaStreamWaitEvent(s2, evFork, 0);
    k_convT1<<<dim3(VOCAB/32, HID/32), 256, 0, s2>>>(P_w, P16, HID, VOCAB);
    cudaEventRecord(evJoin, s2);

    // W^T fp16 for the recurrence
    k_convT1<<<dim3((4*HID)/32, HID/32), 256>>>(W_w, W16, HID, 4*HID);

    // GEMM1: U = X @ U_w + U_b -> fp16 hi/lo
    k_convT1<<<dim3((4*STY)/32, EMB/32), 256>>>(U_w, B16, EMB, 4*STY);
    k_hgemm<2><<<dim3(MPAD/128, (4*STY)/128), 256>>>(Xh, Xl, B16, U_b,
                                                     nullptr, Uh, Ul, 4*STY, EMB, MPAD);
    // GEMM2: S = U @ S1_w + S1_b -> fp16 hi/lo
    k_convT1<<<dim3(STY/32, (4*STY)/32), 256>>>(S1_w, B16, 4*STY, STY);
    k_hgemm<2><<<dim3(MPAD/128, STY/128), 256>>>(Uh, Ul, B16, S1_b,
                                                 nullptr, Sh, Sl, STY, 4*STY, MPAD);
    // GEMM3: Gx = S @ V_w + (V_b+W_b) -> fp32
    k_convT1<<<dim3((4*HID)/32, STY/32), 256>>>(V_w, B16, STY, 4*HID);
    k_hgemm<2><<<dim3(MPAD/128, (4*HID)/128), 256>>>(Sh, Sl, B16, b3,
                                                     Gx, nullptr, nullptr, 4*HID, STY, MPAD);

    // recurrence: single persistent fp16 kernel, all 63 steps
    k_srec<<<(4*HID)/32, 128, REC_SMEM>>>(Gx, W16, hs16, sv, Hh, barc);

    // join, then GEMM4 (plain fp16): out = H @ P_w + P_b -> fp32 d_out
    cudaStreamWaitEvent(0, evJoin, 0);
    k_hgemm<1><<<dim3(MPAD/128, VOCAB/128), 256>>>(Hh, nullptr, P16, P_b,
                                                   out, nullptr, nullptr,
                                                   VOCAB, HID, MROWS);
}